// round 1
// baseline (speedup 1.0000x reference)
#include <cuda_runtime.h>
#include <math.h>

#define EPSF 1e-6f
#define NTOK 4096
#define DDIM 1024
#define HNUM 16
#define HDIM 64
#define MDIM 2736
#define SEQ  1024

// ---------------- scratch (device globals: allocation-free) ----------------
__device__ float g_attn_in[NTOK * DDIM];
__device__ float g_q[NTOK * DDIM];
__device__ float g_k[NTOK * DDIM];
__device__ float g_v[NTOK * DDIM];
__device__ float g_ao[NTOK * DDIM];
__device__ float g_x1[NTOK * DDIM];
__device__ float g_mlp[NTOK * DDIM];
__device__ float g_gate[NTOK * MDIM];
__device__ float g_hbuf[NTOK * MDIM];

// power iteration state
__device__ float g_u[7][MDIM];     // current u vector (raw)
__device__ float g_w[7][MDIM];     // w = K @ u (scaled)
__device__ float g_n2[7][16];      // norm^2 slots: [t]=||w_t||^2 (t=0..5), [8+t]=||u_{t+1}||^2 (t=0..4)
__device__ float g_sigma[7];

__constant__ int c_rows[7] = {1024, 1024, 1024, 1024, 1024, 1024, 2736};
__constant__ int c_cols[7] = {1024, 1024, 1024, 1024, 2736, 2736, 1024};
__constant__ int c_nct[7]  = {4, 4, 4, 4, 11, 11, 4};   // col tiles of 256
__constant__ int c_nrc[7]  = {2, 2, 2, 2, 2, 2, 6};     // row chunks of 512

struct WP { const float* p[7]; };

// ---------------- power iteration kernels ----------------

__global__ void pi_init() {
    int idx = blockIdx.x * 256 + threadIdx.x;
    if (idx < 7 * MDIM) {
        int wi = idx / MDIM, j = idx % MDIM;
        int cols = c_cols[wi];
        float val = (j < cols) ? 1.0f / (sqrtf((float)cols) + EPSF) : 0.0f;
        (&g_u[0][0])[idx] = val;
    }
    if (idx < 7 * 16) (&g_n2[0][0])[idx] = 0.0f;
}

__global__ void pi_zero_u() {
    int idx = blockIdx.x * 256 + threadIdx.x;
    if (idx < 7 * MDIM) (&g_u[0][0])[idx] = 0.0f;
}

// w = K @ (u / (||u||+eps)); accumulate ||w||^2 into slot t
__global__ void pi_fwd(WP wp, int t) {
    int gw = (blockIdx.x * blockDim.x + threadIdx.x) >> 5;
    int lane = threadIdx.x & 31;
    if (gw >= 6 * 1024 + 2736) return;
    int wi, r;
    if (gw < 6144) { wi = gw >> 10; r = gw & 1023; } else { wi = 6; r = gw - 6144; }
    int cols = c_cols[wi];
    float su = 1.0f;
    if (t > 0) su = 1.0f / (sqrtf(g_n2[wi][8 + t - 1]) + EPSF);
    const float* row = wp.p[wi] + (size_t)r * cols;
    const float* u = g_u[wi];
    float acc = 0.0f;
    for (int c = lane * 4; c < cols; c += 128) {
        float4 kv = *(const float4*)(row + c);
        float4 uv = *(const float4*)(u + c);
        acc += kv.x * uv.x + kv.y * uv.y + kv.z * uv.z + kv.w * uv.w;
    }
    #pragma unroll
    for (int o = 16; o; o >>= 1) acc += __shfl_xor_sync(0xffffffffu, acc, o);
    if (lane == 0) {
        float y = acc * su;
        g_w[wi][r] = y;
        atomicAdd(&g_n2[wi][t], y * y);
    }
}

// u += K^T @ (w / (||w||+eps))   (g_u pre-zeroed)
__global__ void pi_bwd(WP wp, int t) {
    __shared__ float ws[512];
    int bid = blockIdx.x, wi = 0;
    for (;;) { int nb = c_nct[wi] * c_nrc[wi]; if (bid < nb) break; bid -= nb; wi++; }
    int ct = bid % c_nct[wi], rc = bid / c_nct[wi];
    int rows = c_rows[wi], cols = c_cols[wi];
    float sv = 1.0f / (sqrtf(g_n2[wi][t]) + EPSF);
    int i0 = rc * 512;
    int ilen = min(512, rows - i0);
    for (int i = threadIdx.x; i < ilen; i += 256) ws[i] = g_w[wi][i0 + i] * sv;
    __syncthreads();
    int j = ct * 256 + threadIdx.x;
    if (j < cols) {
        const float* base = wp.p[wi] + (size_t)i0 * cols + j;
        float acc = 0.0f;
        int i = 0;
        for (; i + 4 <= ilen; i += 4) {
            acc += base[(size_t)i * cols] * ws[i]
                 + base[(size_t)(i + 1) * cols] * ws[i + 1]
                 + base[(size_t)(i + 2) * cols] * ws[i + 2]
                 + base[(size_t)(i + 3) * cols] * ws[i + 3];
        }
        for (; i < ilen; i++) acc += base[(size_t)i * cols] * ws[i];
        atomicAdd(&g_u[wi][j], acc);
    }
}

__global__ void pi_norm_u(int t) {
    int wi = blockIdx.x;
    int cols = c_cols[wi];
    float s = 0.0f;
    for (int j = threadIdx.x; j < cols; j += 256) { float v = g_u[wi][j]; s += v * v; }
    #pragma unroll
    for (int o = 16; o; o >>= 1) s += __shfl_xor_sync(0xffffffffu, s, o);
    __shared__ float red[8];
    if ((threadIdx.x & 31) == 0) red[threadIdx.x >> 5] = s;
    __syncthreads();
    if (threadIdx.x == 0) {
        float tot = 0.0f;
        #pragma unroll
        for (int i = 0; i < 8; i++) tot += red[i];
        g_n2[wi][8 + t] = tot;
    }
}

__global__ void pi_sigma() {
    int wi = threadIdx.x;
    if (wi < 7) {
        float n2 = g_n2[wi][5];
        float s = sqrtf(n2);
        g_sigma[wi] = fmaxf(n2 / (s + EPSF), EPSF);
    }
}

// ---------------- elementwise kernels ----------------

__global__ void rmsnorm_kernel(const float* __restrict__ x, const float* __restrict__ sc,
                               float* __restrict__ y) {
    int row = blockIdx.x;
    const float* xr = x + (size_t)row * DDIM;
    float4 v = *(const float4*)(xr + threadIdx.x * 4);
    float s = v.x * v.x + v.y * v.y + v.z * v.z + v.w * v.w;
    #pragma unroll
    for (int o = 16; o; o >>= 1) s += __shfl_xor_sync(0xffffffffu, s, o);
    __shared__ float red[8];
    if ((threadIdx.x & 31) == 0) red[threadIdx.x >> 5] = s;
    __syncthreads();
    float tot = 0.0f;
    #pragma unroll
    for (int i = 0; i < 8; i++) tot += red[i];
    float r = rsqrtf(tot * (1.0f / (float)DDIM) + EPSF);
    float4 s4 = *(const float4*)(sc + threadIdx.x * 4);
    float4 o;
    o.x = v.x * r * s4.x; o.y = v.y * r * s4.y; o.z = v.z * r * s4.z; o.w = v.w * r * s4.w;
    *(float4*)(y + (size_t)row * DDIM + threadIdx.x * 4) = o;
}

__global__ void qknorm_kernel(const float* __restrict__ qsc, const float* __restrict__ ksc) {
    int warp = threadIdx.x >> 5, lane = threadIdx.x & 31;
    int gw = blockIdx.x * 8 + warp;               // 0..65535 = (token, head)
    int n = gw >> 4, h = gw & 15;
    float* p = (blockIdx.y ? g_k : g_q) + (size_t)n * DDIM + h * HDIM;
    const float* sc = blockIdx.y ? ksc : qsc;
    float2 v = *(float2*)(p + lane * 2);
    float s = v.x * v.x + v.y * v.y;
    #pragma unroll
    for (int o = 16; o; o >>= 1) s += __shfl_xor_sync(0xffffffffu, s, o);
    float r = rsqrtf(s * (1.0f / (float)HDIM) + EPSF);
    float2 scv = *(const float2*)(sc + lane * 2);
    v.x *= r * scv.x; v.y *= r * scv.y;
    *(float2*)(p + lane * 2) = v;
}

// ---------------- SGEMM: C[4096,N] = alpha * A[4096,K] @ B[K,N] + epilogue ----------------
// EPI 0: + bias ; EPI 1: + bias + res ; EPI 2: silu(gate) * (alpha*acc + bias)

template <int EPI>
__global__ __launch_bounds__(256) void sgemm(const float* __restrict__ A,
                                             const float* __restrict__ Bw,
                                             float* __restrict__ C,
                                             int K, int N,
                                             const float* __restrict__ sp, int sidx,
                                             const float* __restrict__ bias,
                                             const float* __restrict__ extra) {
    __shared__ float As[16][128];
    __shared__ float Bs[16][132];
    int tid = threadIdx.x;
    int tx = tid & 15, ty = tid >> 4;
    int m0 = blockIdx.y * 128;
    int n0 = blockIdx.x * 128;

    int arow = tid >> 2;              // 0..63
    int acol = (tid & 3) * 4;         // 0..12
    int brow = tid >> 5;              // 0..7
    int bcol = (tid & 31) * 4;        // 0..124

    float acc[8][8];
    #pragma unroll
    for (int i = 0; i < 8; i++)
        #pragma unroll
        for (int j = 0; j < 8; j++) acc[i][j] = 0.0f;

    const float* Aptr = A + (size_t)m0 * K;

    for (int k0 = 0; k0 < K; k0 += 16) {
        #pragma unroll
        for (int s = 0; s < 2; s++) {
            int r = arow + s * 64;
            float4 av = *(const float4*)(Aptr + (size_t)r * K + k0 + acol);
            As[acol + 0][r] = av.x; As[acol + 1][r] = av.y;
            As[acol + 2][r] = av.z; As[acol + 3][r] = av.w;
        }
        #pragma unroll
        for (int s = 0; s < 2; s++) {
            int kr = brow + s * 8;
            int gcol = n0 + bcol;
            float4 bv = make_float4(0.f, 0.f, 0.f, 0.f);
            if (gcol < N) bv = *(const float4*)(Bw + (size_t)(k0 + kr) * N + gcol);
            *(float4*)&Bs[kr][bcol] = bv;
        }
        __syncthreads();
        #pragma unroll
        for (int kk = 0; kk < 16; kk++) {
            float a[8], b[8];
            *(float4*)&a[0] = *(const float4*)&As[kk][ty * 8];
            *(float4*)&a[4] = *(const float4*)&As[kk][ty * 8 + 4];
            *(float4*)&b[0] = *(const float4*)&Bs[kk][tx * 8];
            *(float4*)&b[4] = *(const float4*)&Bs[kk][tx * 8 + 4];
            #pragma unroll
            for (int i = 0; i < 8; i++)
                #pragma unroll
                for (int j = 0; j < 8; j++)
                    acc[i][j] = fmaf(a[i], b[j], acc[i][j]);
        }
        __syncthreads();
    }

    float alpha = sp[0] / g_sigma[sidx];
    #pragma unroll
    for (int i = 0; i < 8; i++) {
        int gm = m0 + ty * 8 + i;
        #pragma unroll
        for (int jj = 0; jj < 8; jj += 4) {
            int gn = n0 + tx * 8 + jj;
            if (gn < N) {
                float4 ov;
                float vals[4];
                #pragma unroll
                for (int c = 0; c < 4; c++) {
                    float val = alpha * acc[i][jj + c] + bias[gn + c];
                    if (EPI == 1) val += extra[(size_t)gm * N + gn + c];
                    if (EPI == 2) {
                        float g = extra[(size_t)gm * N + gn + c];
                        val = val * (g / (1.0f + __expf(-g)));
                    }
                    vals[c] = val;
                }
                ov.x = vals[0]; ov.y = vals[1]; ov.z = vals[2]; ov.w = vals[3];
                *(float4*)(C + (size_t)gm * N + gn) = ov;
            }
        }
    }
}

// ---------------- fused attention (flash-style, fp32) ----------------
// grid: (16 q-tiles, 64 b*h), 256 threads. Tiles 64x64, HD=64.

#define ATTN_STRIDE 68
#define ATTN_SMEM (3 * 64 * ATTN_STRIDE * 4)

__global__ __launch_bounds__(256) void attn_kernel(const float* __restrict__ q,
                                                   const float* __restrict__ k,
                                                   const float* __restrict__ v,
                                                   float* __restrict__ out) {
    extern __shared__ float sm[];
    float(*Qs)[ATTN_STRIDE] = (float(*)[ATTN_STRIDE])sm;
    float(*Ks)[ATTN_STRIDE] = (float(*)[ATTN_STRIDE])(sm + 64 * ATTN_STRIDE);       // reused as P
    float(*Vs)[ATTN_STRIDE] = (float(*)[ATTN_STRIDE])(sm + 2 * 64 * ATTN_STRIDE);

    int tid = threadIdx.x;
    int tx = tid & 15, ty = tid >> 4;
    int bh = blockIdx.y;
    int b = bh >> 4, h = bh & 15;
    int q0 = blockIdx.x * 64;
    size_t base = ((size_t)b * SEQ) * DDIM + (size_t)h * HDIM;

    // load Q transposed: Qs[d][i]
    {
        int d4 = (tid & 15) * 4;
        int i0 = tid >> 4;
        #pragma unroll
        for (int ss = 0; ss < 4; ss++) {
            int i = i0 + ss * 16;
            float4 t4 = *(const float4*)(q + base + (size_t)(q0 + i) * DDIM + d4);
            Qs[d4 + 0][i] = t4.x; Qs[d4 + 1][i] = t4.y;
            Qs[d4 + 2][i] = t4.z; Qs[d4 + 3][i] = t4.w;
        }
    }

    float m[4], lsum[4], o[4][4];
    #pragma unroll
    for (int r = 0; r < 4; r++) {
        m[r] = -1e30f; lsum[r] = 0.0f;
        #pragma unroll
        for (int c = 0; c < 4; c++) o[r][c] = 0.0f;
    }

    for (int kt = 0; kt < 16; kt++) {
        __syncthreads();
        // load K transposed Ks[d][j], V natural Vs[j][d]
        {
            int d4 = (tid & 15) * 4;
            int j0 = tid >> 4;
            #pragma unroll
            for (int ss = 0; ss < 4; ss++) {
                int j = j0 + ss * 16;
                const float* kp = k + base + (size_t)(kt * 64 + j) * DDIM + d4;
                float4 t4 = *(const float4*)kp;
                Ks[d4 + 0][j] = t4.x; Ks[d4 + 1][j] = t4.y;
                Ks[d4 + 2][j] = t4.z; Ks[d4 + 3][j] = t4.w;
                const float* vp = v + base + (size_t)(kt * 64 + j) * DDIM + d4;
                *(float4*)&Vs[j][d4] = *(const float4*)vp;
            }
        }
        __syncthreads();

        float s[4][4];
        #pragma unroll
        for (int r = 0; r < 4; r++)
            #pragma unroll
            for (int c = 0; c < 4; c++) s[r][c] = 0.0f;

        #pragma unroll 8
        for (int d = 0; d < 64; d++) {
            float a[4], bb[4];
            *(float4*)a = *(const float4*)&Qs[d][ty * 4];
            *(float4*)bb = *(const float4*)&Ks[d][tx * 4];
            #pragma unroll
            for (int r = 0; r < 4; r++)
                #pragma unroll
                for (int c = 0; c < 4; c++)
                    s[r][c] = fmaf(a[r], bb[c], s[r][c]);
        }

        // scale + softcap
        #pragma unroll
        for (int r = 0; r < 4; r++)
            #pragma unroll
            for (int c = 0; c < 4; c++) {
                float l = s[r][c] * 0.125f;
                s[r][c] = 50.0f * tanhf(l * 0.02f);
            }

        // online softmax
        float mt[4];
        #pragma unroll
        for (int r = 0; r < 4; r++) {
            mt[r] = fmaxf(fmaxf(s[r][0], s[r][1]), fmaxf(s[r][2], s[r][3]));
            #pragma unroll
            for (int off = 8; off; off >>= 1)
                mt[r] = fmaxf(mt[r], __shfl_xor_sync(0xffffffffu, mt[r], off, 16));
        }
        float ps[4];
        #pragma unroll
        for (int r = 0; r < 4; r++) {
            float mn = fmaxf(m[r], mt[r]);
            float corr = __expf(m[r] - mn);
            m[r] = mn;
            float acc = 0.0f;
            #pragma unroll
            for (int c = 0; c < 4; c++) {
                float p = __expf(s[r][c] - mn);
                s[r][c] = p;
                acc += p;
            }
            #pragma unroll
            for (int off = 8; off; off >>= 1)
                acc += __shfl_xor_sync(0xffffffffu, acc, off, 16);
            ps[r] = acc;
            lsum[r] = lsum[r] * corr + ps[r];
            #pragma unroll
            for (int c = 0; c < 4; c++) o[r][c] *= corr;
        }

        __syncthreads();
        // write P into Ks buffer: Ps[j][i]
        #pragma unroll
        for (int c = 0; c < 4; c++) {
            int j = tx * 4 + c;
            float4 pv = make_float4(s[0][c], s[1][c], s[2][c], s[3][c]);
            *(float4*)&Ks[j][ty * 4] = pv;
        }
        __syncthreads();

        // O += P @ V
        #pragma unroll 8
        for (int j = 0; j < 64; j++) {
            float pa[4], vb[4];
            *(float4*)pa = *(const float4*)&Ks[j][ty * 4];
            *(float4*)vb = *(const float4*)&Vs[j][tx * 4];
            #pragma unroll
            for (int r = 0; r < 4; r++)
                #pragma unroll
                for (int c = 0; c < 4; c++)
                    o[r][c] = fmaf(pa[r], vb[c], o[r][c]);
        }
    }

    #pragma unroll
    for (int r = 0; r < 4; r++) {
        float inv = 1.0f / lsum[r];
        int i = ty * 4 + r;
        float4 ov = make_float4(o[r][0] * inv, o[r][1] * inv, o[r][2] * inv, o[r][3] * inv);
        *(float4*)(out + base + (size_t)(q0 + i) * DDIM + tx * 4) = ov;
    }
}

// ---------------- host launch ----------------

extern "C" void kernel_launch(void* const* d_in, const int* in_sizes, int n_in,
                              void* d_out, int out_size) {
    const float* x   = (const float*)d_in[0];
    const float* ln1 = (const float*)d_in[1];
    const float* wq  = (const float*)d_in[2];
    const float* sq  = (const float*)d_in[3];
    const float* bq  = (const float*)d_in[4];
    const float* wk  = (const float*)d_in[5];
    const float* sk  = (const float*)d_in[6];
    const float* bk  = (const float*)d_in[7];
    const float* wv  = (const float*)d_in[8];
    const float* sv  = (const float*)d_in[9];
    const float* bv  = (const float*)d_in[10];
    const float* qn  = (const float*)d_in[11];
    const float* kn  = (const float*)d_in[12];
    const float* wo  = (const float*)d_in[13];
    const float* so  = (const float*)d_in[14];
    const float* bo  = (const float*)d_in[15];
    const float* ln2 = (const float*)d_in[16];
    const float* wg  = (const float*)d_in[17];
    const float* sg  = (const float*)d_in[18];
    const float* bg  = (const float*)d_in[19];
    const float* wu  = (const float*)d_in[20];
    const float* su  = (const float*)d_in[21];
    const float* bu  = (const float*)d_in[22];
    const float* wd  = (const float*)d_in[23];
    const float* sd  = (const float*)d_in[24];
    const float* bd  = (const float*)d_in[25];
    float* out = (float*)d_out;

    float *p_attn_in, *p_q, *p_k, *p_v, *p_ao, *p_x1, *p_mlp, *p_gate, *p_hbuf;
    cudaGetSymbolAddress((void**)&p_attn_in, g_attn_in);
    cudaGetSymbolAddress((void**)&p_q, g_q);
    cudaGetSymbolAddress((void**)&p_k, g_k);
    cudaGetSymbolAddress((void**)&p_v, g_v);
    cudaGetSymbolAddress((void**)&p_ao, g_ao);
    cudaGetSymbolAddress((void**)&p_x1, g_x1);
    cudaGetSymbolAddress((void**)&p_mlp, g_mlp);
    cudaGetSymbolAddress((void**)&p_gate, g_gate);
    cudaGetSymbolAddress((void**)&p_hbuf, g_hbuf);

    WP wp;
    wp.p[0] = wq; wp.p[1] = wk; wp.p[2] = wv; wp.p[3] = wo;
    wp.p[4] = wg; wp.p[5] = wu; wp.p[6] = wd;

    // RMSNorm 1
    rmsnorm_kernel<<<NTOK, 256>>>(x, ln1, p_attn_in);

    // spectral sigmas (power iteration, all 7 weights fused per step)
    pi_init<<<75, 256>>>();
    for (int t = 0; t < 5; t++) {
        pi_fwd<<<1110, 256>>>(wp, t);
        pi_zero_u<<<75, 256>>>();
        pi_bwd<<<100, 256>>>(wp, t);
        pi_norm_u<<<7, 256>>>(t);
    }
    pi_fwd<<<1110, 256>>>(wp, 5);
    pi_sigma<<<1, 32>>>();

    // q, k, v projections
    dim3 g1(8, 32);
    sgemm<0><<<g1, 256>>>(p_attn_in, wq, p_q, 1024, 1024, sq, 0, bq, nullptr);
    sgemm<0><<<g1, 256>>>(p_attn_in, wk, p_k, 1024, 1024, sk, 1, bk, nullptr);
    sgemm<0><<<g1, 256>>>(p_attn_in, wv, p_v, 1024, 1024, sv, 2, bv, nullptr);

    // q/k head RMS norms
    qknorm_kernel<<<dim3(8192, 2), 256>>>(qn, kn);

    // fused attention
    cudaFuncSetAttribute(attn_kernel, cudaFuncAttributeMaxDynamicSharedMemorySize, ATTN_SMEM);
    attn_kernel<<<dim3(16, 64), 256, ATTN_SMEM>>>(p_q, p_k, p_v, p_ao);

    // output projection + residual
    sgemm<1><<<g1, 256>>>(p_ao, wo, p_x1, 1024, 1024, so, 3, bo, x);

    // RMSNorm 2
    rmsnorm_kernel<<<NTOK, 256>>>(p_x1, ln2, p_mlp);

    // gated MLP
    dim3 g2(22, 32);
    sgemm<0><<<g2, 256>>>(p_mlp, wg, p_gate, 1024, 2736, sg, 4, bg, nullptr);
    sgemm<2><<<g2, 256>>>(p_mlp, wu, p_hbuf, 1024, 2736, su, 5, bu, p_gate);
    sgemm<1><<<g1, 256>>>(p_hbuf, wd, out, 2736, 1024, sd, 6, bd, p_x1);
}

// round 2
// speedup vs baseline: 1.0060x; 1.0060x over previous
#include <cuda_runtime.h>
#include <math.h>

#define EPSF 1e-6f
#define NTOK 4096
#define DDIM 1024
#define HNUM 16
#define HDIM 64
#define MDIM 2736
#define SEQ  1024

// ---------------- scratch (device globals: allocation-free) ----------------
__device__ float g_attn_in[NTOK * DDIM];
__device__ float g_q[NTOK * DDIM];
__device__ float g_k[NTOK * DDIM];
__device__ float g_v[NTOK * DDIM];
__device__ float g_ao[NTOK * DDIM];
__device__ float g_x1[NTOK * DDIM];
__device__ float g_mlp[NTOK * DDIM];
__device__ float g_gate[NTOK * MDIM];
__device__ float g_hbuf[NTOK * MDIM];

// power iteration state
__device__ float g_u[7][MDIM];     // current u vector (raw)
__device__ float g_w[7][MDIM];     // w = K @ u (scaled)
__device__ float g_n2[7][16];      // norm^2 slots: [t]=||w_t||^2 (t=0..5), [8+t]=||u_{t+1}||^2 (t=0..4)
__device__ float g_sigma[7];

__constant__ int c_rows[7] = {1024, 1024, 1024, 1024, 1024, 1024, 2736};
__constant__ int c_cols[7] = {1024, 1024, 1024, 1024, 2736, 2736, 1024};
__constant__ int c_nct[7]  = {4, 4, 4, 4, 11, 11, 4};   // col tiles of 256
__constant__ int c_nrc[7]  = {2, 2, 2, 2, 2, 2, 6};     // row chunks of 512

struct WP { const float* p[7]; };

// ---------------- power iteration kernels ----------------

__global__ void pi_init() {
    int idx = blockIdx.x * 256 + threadIdx.x;
    if (idx < 7 * MDIM) {
        int wi = idx / MDIM, j = idx % MDIM;
        int cols = c_cols[wi];
        float val = (j < cols) ? 1.0f / (sqrtf((float)cols) + EPSF) : 0.0f;
        (&g_u[0][0])[idx] = val;
    }
    if (idx < 7 * 16) (&g_n2[0][0])[idx] = 0.0f;
}

__global__ void pi_zero_u() {
    int idx = blockIdx.x * 256 + threadIdx.x;
    if (idx < 7 * MDIM) (&g_u[0][0])[idx] = 0.0f;
}

// w = K @ (u / (||u||+eps)); accumulate ||w||^2 into slot t
__global__ void pi_fwd(WP wp, int t) {
    int gw = (blockIdx.x * blockDim.x + threadIdx.x) >> 5;
    int lane = threadIdx.x & 31;
    if (gw >= 6 * 1024 + 2736) return;
    int wi, r;
    if (gw < 6144) { wi = gw >> 10; r = gw & 1023; } else { wi = 6; r = gw - 6144; }
    int cols = c_cols[wi];
    float su = 1.0f;
    if (t > 0) su = 1.0f / (sqrtf(g_n2[wi][8 + t - 1]) + EPSF);
    const float* row = wp.p[wi] + (size_t)r * cols;
    const float* u = g_u[wi];
    float acc = 0.0f;
    for (int c = lane * 4; c < cols; c += 128) {
        float4 kv = *(const float4*)(row + c);
        float4 uv = *(const float4*)(u + c);
        acc += kv.x * uv.x + kv.y * uv.y + kv.z * uv.z + kv.w * uv.w;
    }
    #pragma unroll
    for (int o = 16; o; o >>= 1) acc += __shfl_xor_sync(0xffffffffu, acc, o);
    if (lane == 0) {
        float y = acc * su;
        g_w[wi][r] = y;
        atomicAdd(&g_n2[wi][t], y * y);
    }
}

// u += K^T @ (w / (||w||+eps))   (g_u pre-zeroed)
__global__ void pi_bwd(WP wp, int t) {
    __shared__ float ws[512];
    int bid = blockIdx.x, wi = 0;
    for (;;) { int nb = c_nct[wi] * c_nrc[wi]; if (bid < nb) break; bid -= nb; wi++; }
    int ct = bid % c_nct[wi], rc = bid / c_nct[wi];
    int rows = c_rows[wi], cols = c_cols[wi];
    float sv = 1.0f / (sqrtf(g_n2[wi][t]) + EPSF);
    int i0 = rc * 512;
    int ilen = min(512, rows - i0);
    for (int i = threadIdx.x; i < ilen; i += 256) ws[i] = g_w[wi][i0 + i] * sv;
    __syncthreads();
    int j = ct * 256 + threadIdx.x;
    if (j < cols) {
        const float* base = wp.p[wi] + (size_t)i0 * cols + j;
        float acc = 0.0f;
        int i = 0;
        for (; i + 4 <= ilen; i += 4) {
            acc += base[(size_t)i * cols] * ws[i]
                 + base[(size_t)(i + 1) * cols] * ws[i + 1]
                 + base[(size_t)(i + 2) * cols] * ws[i + 2]
                 + base[(size_t)(i + 3) * cols] * ws[i + 3];
        }
        for (; i < ilen; i++) acc += base[(size_t)i * cols] * ws[i];
        atomicAdd(&g_u[wi][j], acc);
    }
}

__global__ void pi_norm_u(int t) {
    int wi = blockIdx.x;
    int cols = c_cols[wi];
    float s = 0.0f;
    for (int j = threadIdx.x; j < cols; j += 256) { float v = g_u[wi][j]; s += v * v; }
    #pragma unroll
    for (int o = 16; o; o >>= 1) s += __shfl_xor_sync(0xffffffffu, s, o);
    __shared__ float red[8];
    if ((threadIdx.x & 31) == 0) red[threadIdx.x >> 5] = s;
    __syncthreads();
    if (threadIdx.x == 0) {
        float tot = 0.0f;
        #pragma unroll
        for (int i = 0; i < 8; i++) tot += red[i];
        g_n2[wi][8 + t] = tot;
    }
}

__global__ void pi_sigma() {
    int wi = threadIdx.x;
    if (wi < 7) {
        float n2 = g_n2[wi][5];
        float s = sqrtf(n2);
        g_sigma[wi] = fmaxf(n2 / (s + EPSF), EPSF);
    }
}

// ---------------- elementwise kernels ----------------

__global__ void rmsnorm_kernel(const float* __restrict__ x, const float* __restrict__ sc,
                               float* __restrict__ y) {
    int row = blockIdx.x;
    const float* xr = x + (size_t)row * DDIM;
    float4 v = *(const float4*)(xr + threadIdx.x * 4);
    float s = v.x * v.x + v.y * v.y + v.z * v.z + v.w * v.w;
    #pragma unroll
    for (int o = 16; o; o >>= 1) s += __shfl_xor_sync(0xffffffffu, s, o);
    __shared__ float red[8];
    if ((threadIdx.x & 31) == 0) red[threadIdx.x >> 5] = s;
    __syncthreads();
    float tot = 0.0f;
    #pragma unroll
    for (int i = 0; i < 8; i++) tot += red[i];
    float r = rsqrtf(tot * (1.0f / (float)DDIM) + EPSF);
    float4 s4 = *(const float4*)(sc + threadIdx.x * 4);
    float4 o;
    o.x = v.x * r * s4.x; o.y = v.y * r * s4.y; o.z = v.z * r * s4.z; o.w = v.w * r * s4.w;
    *(float4*)(y + (size_t)row * DDIM + threadIdx.x * 4) = o;
}

__global__ void qknorm_kernel(const float* __restrict__ qsc, const float* __restrict__ ksc) {
    int warp = threadIdx.x >> 5, lane = threadIdx.x & 31;
    int gw = blockIdx.x * 8 + warp;               // 0..65535 = (token, head)
    int n = gw >> 4, h = gw & 15;
    float* p = (blockIdx.y ? g_k : g_q) + (size_t)n * DDIM + h * HDIM;
    const float* sc = blockIdx.y ? ksc : qsc;
    float2 v = *(float2*)(p + lane * 2);
    float s = v.x * v.x + v.y * v.y;
    #pragma unroll
    for (int o = 16; o; o >>= 1) s += __shfl_xor_sync(0xffffffffu, s, o);
    float r = rsqrtf(s * (1.0f / (float)HDIM) + EPSF);
    float2 scv = *(const float2*)(sc + lane * 2);
    v.x *= r * scv.x; v.y *= r * scv.y;
    *(float2*)(p + lane * 2) = v;
}

// ---------------- SGEMM: C[4096,N] = alpha * A[4096,K] @ B[K,N] + epilogue ----------------
// EPI 0: + bias ; EPI 1: + bias + res ; EPI 2: silu(gate) * (alpha*acc + bias)

template <int EPI>
__global__ __launch_bounds__(256) void sgemm(const float* __restrict__ A,
                                             const float* __restrict__ Bw,
                                             float* __restrict__ C,
                                             int K, int N,
                                             const float* __restrict__ sp, int sidx,
                                             const float* __restrict__ bias,
                                             const float* __restrict__ extra) {
    __shared__ float As[16][128];
    __shared__ float Bs[16][132];
    int tid = threadIdx.x;
    int tx = tid & 15, ty = tid >> 4;
    int m0 = blockIdx.y * 128;
    int n0 = blockIdx.x * 128;

    int arow = tid >> 2;              // 0..63
    int acol = (tid & 3) * 4;         // 0..12
    int brow = tid >> 5;              // 0..7
    int bcol = (tid & 31) * 4;        // 0..124

    float acc[8][8];
    #pragma unroll
    for (int i = 0; i < 8; i++)
        #pragma unroll
        for (int j = 0; j < 8; j++) acc[i][j] = 0.0f;

    const float* Aptr = A + (size_t)m0 * K;

    for (int k0 = 0; k0 < K; k0 += 16) {
        #pragma unroll
        for (int s = 0; s < 2; s++) {
            int r = arow + s * 64;
            float4 av = *(const float4*)(Aptr + (size_t)r * K + k0 + acol);
            As[acol + 0][r] = av.x; As[acol + 1][r] = av.y;
            As[acol + 2][r] = av.z; As[acol + 3][r] = av.w;
        }
        #pragma unroll
        for (int s = 0; s < 2; s++) {
            int kr = brow + s * 8;
            int gcol = n0 + bcol;
            float4 bv = make_float4(0.f, 0.f, 0.f, 0.f);
            if (gcol < N) bv = *(const float4*)(Bw + (size_t)(k0 + kr) * N + gcol);
            *(float4*)&Bs[kr][bcol] = bv;
        }
        __syncthreads();
        #pragma unroll
        for (int kk = 0; kk < 16; kk++) {
            float a[8], b[8];
            *(float4*)&a[0] = *(const float4*)&As[kk][ty * 8];
            *(float4*)&a[4] = *(const float4*)&As[kk][ty * 8 + 4];
            *(float4*)&b[0] = *(const float4*)&Bs[kk][tx * 8];
            *(float4*)&b[4] = *(const float4*)&Bs[kk][tx * 8 + 4];
            #pragma unroll
            for (int i = 0; i < 8; i++)
                #pragma unroll
                for (int j = 0; j < 8; j++)
                    acc[i][j] = fmaf(a[i], b[j], acc[i][j]);
        }
        __syncthreads();
    }

    float alpha = sp[0] / g_sigma[sidx];
    #pragma unroll
    for (int i = 0; i < 8; i++) {
        int gm = m0 + ty * 8 + i;
        #pragma unroll
        for (int jj = 0; jj < 8; jj += 4) {
            int gn = n0 + tx * 8 + jj;
            if (gn < N) {
                float4 ov;
                float vals[4];
                #pragma unroll
                for (int c = 0; c < 4; c++) {
                    float val = alpha * acc[i][jj + c] + bias[gn + c];
                    if (EPI == 1) val += extra[(size_t)gm * N + gn + c];
                    if (EPI == 2) {
                        float g = extra[(size_t)gm * N + gn + c];
                        val = val * (g / (1.0f + __expf(-g)));
                    }
                    vals[c] = val;
                }
                ov.x = vals[0]; ov.y = vals[1]; ov.z = vals[2]; ov.w = vals[3];
                *(float4*)(C + (size_t)gm * N + gn) = ov;
            }
        }
    }
}

// ---------------- fused attention (flash-style, fp32) ----------------
// grid: (16 q-tiles, 64 b*h), 256 threads. Tiles 64x64, HD=64.

#define ATTN_STRIDE 68
#define ATTN_SMEM (3 * 64 * ATTN_STRIDE * 4)

__global__ __launch_bounds__(256) void attn_kernel(const float* __restrict__ q,
                                                   const float* __restrict__ k,
                                                   const float* __restrict__ v,
                                                   float* __restrict__ out) {
    extern __shared__ float sm[];
    float(*Qs)[ATTN_STRIDE] = (float(*)[ATTN_STRIDE])sm;
    float(*Ks)[ATTN_STRIDE] = (float(*)[ATTN_STRIDE])(sm + 64 * ATTN_STRIDE);       // reused as P
    float(*Vs)[ATTN_STRIDE] = (float(*)[ATTN_STRIDE])(sm + 2 * 64 * ATTN_STRIDE);

    int tid = threadIdx.x;
    int tx = tid & 15, ty = tid >> 4;
    int bh = blockIdx.y;
    int b = bh >> 4, h = bh & 15;
    int q0 = blockIdx.x * 64;
    size_t base = ((size_t)b * SEQ) * DDIM + (size_t)h * HDIM;

    // load Q transposed: Qs[d][i]
    {
        int d4 = (tid & 15) * 4;
        int i0 = tid >> 4;
        #pragma unroll
        for (int ss = 0; ss < 4; ss++) {
            int i = i0 + ss * 16;
            float4 t4 = *(const float4*)(q + base + (size_t)(q0 + i) * DDIM + d4);
            Qs[d4 + 0][i] = t4.x; Qs[d4 + 1][i] = t4.y;
            Qs[d4 + 2][i] = t4.z; Qs[d4 + 3][i] = t4.w;
        }
    }

    float m[4], lsum[4], o[4][4];
    #pragma unroll
    for (int r = 0; r < 4; r++) {
        m[r] = -1e30f; lsum[r] = 0.0f;
        #pragma unroll
        for (int c = 0; c < 4; c++) o[r][c] = 0.0f;
    }

    for (int kt = 0; kt < 16; kt++) {
        __syncthreads();
        // load K transposed Ks[d][j], V natural Vs[j][d]
        {
            int d4 = (tid & 15) * 4;
            int j0 = tid >> 4;
            #pragma unroll
            for (int ss = 0; ss < 4; ss++) {
                int j = j0 + ss * 16;
                const float* kp = k + base + (size_t)(kt * 64 + j) * DDIM + d4;
                float4 t4 = *(const float4*)kp;
                Ks[d4 + 0][j] = t4.x; Ks[d4 + 1][j] = t4.y;
                Ks[d4 + 2][j] = t4.z; Ks[d4 + 3][j] = t4.w;
                const float* vp = v + base + (size_t)(kt * 64 + j) * DDIM + d4;
                *(float4*)&Vs[j][d4] = *(const float4*)vp;
            }
        }
        __syncthreads();

        float s[4][4];
        #pragma unroll
        for (int r = 0; r < 4; r++)
            #pragma unroll
            for (int c = 0; c < 4; c++) s[r][c] = 0.0f;

        #pragma unroll 8
        for (int d = 0; d < 64; d++) {
            float a[4], bb[4];
            *(float4*)a = *(const float4*)&Qs[d][ty * 4];
            *(float4*)bb = *(const float4*)&Ks[d][tx * 4];
            #pragma unroll
            for (int r = 0; r < 4; r++)
                #pragma unroll
                for (int c = 0; c < 4; c++)
                    s[r][c] = fmaf(a[r], bb[c], s[r][c]);
        }

        // scale + softcap
        #pragma unroll
        for (int r = 0; r < 4; r++)
            #pragma unroll
            for (int c = 0; c < 4; c++) {
                float l = s[r][c] * 0.125f;
                s[r][c] = 50.0f * tanhf(l * 0.02f);
            }

        // online softmax
        float mt[4];
        #pragma unroll
        for (int r = 0; r < 4; r++) {
            mt[r] = fmaxf(fmaxf(s[r][0], s[r][1]), fmaxf(s[r][2], s[r][3]));
            #pragma unroll
            for (int off = 8; off; off >>= 1)
                mt[r] = fmaxf(mt[r], __shfl_xor_sync(0xffffffffu, mt[r], off, 16));
        }
        float ps[4];
        #pragma unroll
        for (int r = 0; r < 4; r++) {
            float mn = fmaxf(m[r], mt[r]);
            float corr = __expf(m[r] - mn);
            m[r] = mn;
            float acc = 0.0f;
            #pragma unroll
            for (int c = 0; c < 4; c++) {
                float p = __expf(s[r][c] - mn);
                s[r][c] = p;
                acc += p;
            }
            #pragma unroll
            for (int off = 8; off; off >>= 1)
                acc += __shfl_xor_sync(0xffffffffu, acc, off, 16);
            ps[r] = acc;
            lsum[r] = lsum[r] * corr + ps[r];
            #pragma unroll
            for (int c = 0; c < 4; c++) o[r][c] *= corr;
        }

        __syncthreads();
        // write P into Ks buffer: Ps[j][i]
        #pragma unroll
        for (int c = 0; c < 4; c++) {
            int j = tx * 4 + c;
            float4 pv = make_float4(s[0][c], s[1][c], s[2][c], s[3][c]);
            *(float4*)&Ks[j][ty * 4] = pv;
        }
        __syncthreads();

        // O += P @ V
        #pragma unroll 8
        for (int j = 0; j < 64; j++) {
            float pa[4], vb[4];
            *(float4*)pa = *(const float4*)&Ks[j][ty * 4];
            *(float4*)vb = *(const float4*)&Vs[j][tx * 4];
            #pragma unroll
            for (int r = 0; r < 4; r++)
                #pragma unroll
                for (int c = 0; c < 4; c++)
                    o[r][c] = fmaf(pa[r], vb[c], o[r][c]);
        }
    }

    #pragma unroll
    for (int r = 0; r < 4; r++) {
        float inv = 1.0f / lsum[r];
        int i = ty * 4 + r;
        float4 ov = make_float4(o[r][0] * inv, o[r][1] * inv, o[r][2] * inv, o[r][3] * inv);
        *(float4*)(out + base + (size_t)(q0 + i) * DDIM + tx * 4) = ov;
    }
}

// ---------------- host launch ----------------

extern "C" void kernel_launch(void* const* d_in, const int* in_sizes, int n_in,
                              void* d_out, int out_size) {
    const float* x   = (const float*)d_in[0];
    const float* ln1 = (const float*)d_in[1];
    const float* wq  = (const float*)d_in[2];
    const float* sq  = (const float*)d_in[3];
    const float* bq  = (const float*)d_in[4];
    const float* wk  = (const float*)d_in[5];
    const float* sk  = (const float*)d_in[6];
    const float* bk  = (const float*)d_in[7];
    const float* wv  = (const float*)d_in[8];
    const float* sv  = (const float*)d_in[9];
    const float* bv  = (const float*)d_in[10];
    const float* qn  = (const float*)d_in[11];
    const float* kn  = (const float*)d_in[12];
    const float* wo  = (const float*)d_in[13];
    const float* so  = (const float*)d_in[14];
    const float* bo  = (const float*)d_in[15];
    const float* ln2 = (const float*)d_in[16];
    const float* wg  = (const float*)d_in[17];
    const float* sg  = (const float*)d_in[18];
    const float* bg  = (const float*)d_in[19];
    const float* wu  = (const float*)d_in[20];
    const float* su  = (const float*)d_in[21];
    const float* bu  = (const float*)d_in[22];
    const float* wd  = (const float*)d_in[23];
    const float* sd  = (const float*)d_in[24];
    const float* bd  = (const float*)d_in[25];
    float* out = (float*)d_out;

    float *p_attn_in, *p_q, *p_k, *p_v, *p_ao, *p_x1, *p_mlp, *p_gate, *p_hbuf;
    cudaGetSymbolAddress((void**)&p_attn_in, g_attn_in);
    cudaGetSymbolAddress((void**)&p_q, g_q);
    cudaGetSymbolAddress((void**)&p_k, g_k);
    cudaGetSymbolAddress((void**)&p_v, g_v);
    cudaGetSymbolAddress((void**)&p_ao, g_ao);
    cudaGetSymbolAddress((void**)&p_x1, g_x1);
    cudaGetSymbolAddress((void**)&p_mlp, g_mlp);
    cudaGetSymbolAddress((void**)&p_gate, g_gate);
    cudaGetSymbolAddress((void**)&p_hbuf, g_hbuf);

    WP wp;
    wp.p[0] = wq; wp.p[1] = wk; wp.p[2] = wv; wp.p[3] = wo;
    wp.p[4] = wg; wp.p[5] = wu; wp.p[6] = wd;

    // RMSNorm 1
    rmsnorm_kernel<<<NTOK, 256>>>(x, ln1, p_attn_in);

    // spectral sigmas (power iteration, all 7 weights fused per step)
    pi_init<<<75, 256>>>();
    for (int t = 0; t < 5; t++) {
        pi_fwd<<<1110, 256>>>(wp, t);
        pi_zero_u<<<75, 256>>>();
        pi_bwd<<<100, 256>>>(wp, t);
        pi_norm_u<<<7, 256>>>(t);
    }
    pi_fwd<<<1110, 256>>>(wp, 5);
    pi_sigma<<<1, 32>>>();

    // q, k, v projections
    dim3 g1(8, 32);
    sgemm<0><<<g1, 256>>>(p_attn_in, wq, p_q, 1024, 1024, sq, 0, bq, nullptr);
    sgemm<0><<<g1, 256>>>(p_attn_in, wk, p_k, 1024, 1024, sk, 1, bk, nullptr);
    sgemm<0><<<g1, 256>>>(p_attn_in, wv, p_v, 1024, 1024, sv, 2, bv, nullptr);

    // q/k head RMS norms
    qknorm_kernel<<<dim3(8192, 2), 256>>>(qn, kn);

    // fused attention
    cudaFuncSetAttribute(attn_kernel, cudaFuncAttributeMaxDynamicSharedMemorySize, ATTN_SMEM);
    attn_kernel<<<dim3(16, 64), 256, ATTN_SMEM>>>(p_q, p_k, p_v, p_ao);

    // output projection + residual
    sgemm<1><<<g1, 256>>>(p_ao, wo, p_x1, 1024, 1024, so, 3, bo, x);

    // RMSNorm 2
    rmsnorm_kernel<<<NTOK, 256>>>(p_x1, ln2, p_mlp);

    // gated MLP
    dim3 g2(22, 32);
    sgemm<0><<<g2, 256>>>(p_mlp, wg, p_gate, 1024, 2736, sg, 4, bg, nullptr);
    sgemm<2><<<g2, 256>>>(p_mlp, wu, p_hbuf, 1024, 2736, su, 5, bu, p_gate);
    sgemm<1><<<g1, 256>>>(p_hbuf, wd, out, 2736, 1024, sd, 6, bd, p_x1);
}

// round 4
// speedup vs baseline: 1.6613x; 1.6513x over previous
#include <cuda_runtime.h>
#include <cuda_bf16.h>
#include <math.h>
#include <stdint.h>

#define EPSF 1e-6f
#define NTOK 4096
#define DDIM 1024
#define HDIM 64
#define MDIM 2736
#define SEQ  1024
#define KPADM 2752
#define NPADM 2816

typedef __nv_bfloat16 bf16;

// ---------------- scratch ----------------
__device__ float g_q[NTOK * DDIM];
__device__ float g_k[NTOK * DDIM];
__device__ float g_v[NTOK * DDIM];
__device__ float g_ao[NTOK * DDIM];
__device__ float g_x1[NTOK * DDIM];
__device__ float g_gate[NTOK * MDIM];

__device__ bf16 g_ai_h[NTOK * DDIM], g_ai_l[NTOK * DDIM];
__device__ bf16 g_aop_h[NTOK * DDIM], g_aop_l[NTOK * DDIM];
__device__ bf16 g_mi_h[NTOK * DDIM], g_mi_l[NTOK * DDIM];
__device__ bf16 g_hb_h[NTOK * KPADM], g_hb_l[NTOK * KPADM];

__device__ bf16 g_wqT_h[DDIM * DDIM], g_wqT_l[DDIM * DDIM];
__device__ bf16 g_wkT_h[DDIM * DDIM], g_wkT_l[DDIM * DDIM];
__device__ bf16 g_wvT_h[DDIM * DDIM], g_wvT_l[DDIM * DDIM];
__device__ bf16 g_woT_h[DDIM * DDIM], g_woT_l[DDIM * DDIM];
__device__ bf16 g_wgT_h[NPADM * DDIM], g_wgT_l[NPADM * DDIM];
__device__ bf16 g_wuT_h[NPADM * DDIM], g_wuT_l[NPADM * DDIM];
__device__ bf16 g_wdT_h[DDIM * KPADM], g_wdT_l[DDIM * KPADM];

__device__ float g_u[7][MDIM];
__device__ float g_w[7][MDIM];
__device__ float g_n2[7][16];
__device__ float g_sigma[7];

__constant__ int c_rows[7] = {1024, 1024, 1024, 1024, 1024, 1024, 2736};
__constant__ int c_cols[7] = {1024, 1024, 1024, 1024, 2736, 2736, 1024};
__constant__ int c_nct[7]  = {4, 4, 4, 4, 11, 11, 4};
__constant__ int c_nrc[7]  = {2, 2, 2, 2, 2, 2, 6};

struct WP { const float* p[7]; };

// ---------------- PTX helpers ----------------
__device__ __forceinline__ uint32_t s2u(const void* p) {
    uint32_t a;
    asm("{ .reg .u64 t; cvta.to.shared.u64 t, %1; cvt.u32.u64 %0, t; }" : "=r"(a) : "l"(p));
    return a;
}
__device__ __forceinline__ void cpa16(uint32_t d, const void* g) {
    asm volatile("cp.async.cg.shared.global [%0], [%1], 16;" :: "r"(d), "l"(g) : "memory");
}
__device__ __forceinline__ void cpa_commit() { asm volatile("cp.async.commit_group;" ::: "memory"); }
template <int N> __device__ __forceinline__ void cpa_wait() {
    asm volatile("cp.async.wait_group %0;" :: "n"(N) : "memory");
}
__device__ __forceinline__ void ldmx4(uint32_t* r, uint32_t a) {
    asm volatile("ldmatrix.sync.aligned.m8n8.x4.shared.b16 {%0,%1,%2,%3}, [%4];"
                 : "=r"(r[0]), "=r"(r[1]), "=r"(r[2]), "=r"(r[3]) : "r"(a));
}
__device__ __forceinline__ void ldmx2(uint32_t* r, uint32_t a) {
    asm volatile("ldmatrix.sync.aligned.m8n8.x2.shared.b16 {%0,%1}, [%2];"
                 : "=r"(r[0]), "=r"(r[1]) : "r"(a));
}
__device__ __forceinline__ void mma16816(float* c, const uint32_t* a, const uint32_t* b) {
    asm volatile(
        "mma.sync.aligned.m16n8k16.row.col.f32.bf16.bf16.f32 "
        "{%0,%1,%2,%3}, {%4,%5,%6,%7}, {%8,%9}, {%0,%1,%2,%3};"
        : "+f"(c[0]), "+f"(c[1]), "+f"(c[2]), "+f"(c[3])
        : "r"(a[0]), "r"(a[1]), "r"(a[2]), "r"(a[3]), "r"(b[0]), "r"(b[1]));
}

// ---------------- HMMA split-bf16 GEMM ----------------
// C[4096,N] = alpha*(A@B) + epi, A = Ah+Al [4096][Kp], B = (Bh+Bl)^T stored [Nrows][Kp].
// CTA tile 128x128, 8 warps of 64x32, K chunk 32, 2-stage cp.async.
// smem per stage: 4 tiles x 128 rows x 80B = 40960B. Total 81920B.
// EPI 0:+bias 1:+bias+extra 2:(v+bias)*silu(extra). OUTPAIR: bf16 hi/lo out stride Cp.

#define TILEB 10240
#define STAGE_B 40960
#define GEMM_SMEM (2 * STAGE_B)

template <int EPI, int OUTPAIR>
__global__ __launch_bounds__(256)
void gemm_hmma(const bf16* __restrict__ Ah, const bf16* __restrict__ Al,
               const bf16* __restrict__ Bh, const bf16* __restrict__ Bl,
               int Kp, int N,
               float* __restrict__ Cf, bf16* __restrict__ Ch, bf16* __restrict__ Cl, int Cp,
               const float* __restrict__ sp, int sidx,
               const float* __restrict__ bias, const float* __restrict__ extra) {
    extern __shared__ char smem[];
    uint32_t sb = s2u(smem);
    int tid = threadIdx.x;
    int wid = tid >> 5, lane = tid & 31;
    int m0 = blockIdx.y * 128, n0 = blockIdx.x * 128;
    int wm = (wid & 1) * 64, wn = (wid >> 1) * 32;

    const bf16* bases[4] = {Ah, Al, Bh, Bl};
    int row0s[4] = {m0, m0, n0, n0};

    auto load_chunk = [&](int ck) {
        uint32_t st = sb + (uint32_t)(ck & 1) * STAGE_B;
        #pragma unroll
        for (int op = 0; op < 4; op++) {
            #pragma unroll
            for (int p = 0; p < 2; p++) {
                int idx = tid + p * 256;
                int r = idx >> 2, cg = idx & 3;
                const bf16* g = bases[op] + (size_t)(row0s[op] + r) * Kp + ck * 32 + cg * 8;
                cpa16(st + (uint32_t)op * TILEB + (uint32_t)(r * 80 + cg * 16), g);
            }
        }
        cpa_commit();
    };

    float acc[4][4][4];
    #pragma unroll
    for (int i = 0; i < 4; i++)
        #pragma unroll
        for (int j = 0; j < 4; j++)
            #pragma unroll
            for (int r = 0; r < 4; r++) acc[i][j][r] = 0.0f;

    const int T = Kp >> 5;
    load_chunk(0);
    load_chunk(1);

    // ldmatrix address offsets (within a tile)
    uint32_t a_off = (uint32_t)((lane & 15) * 80 + (lane >> 4) * 16);
    uint32_t b_off = (uint32_t)((lane & 7) * 80 + ((lane >> 3) & 1) * 16);

    for (int ck = 0; ck < T; ck++) {
        if (ck + 1 < T) cpa_wait<1>(); else cpa_wait<0>();
        __syncthreads();
        uint32_t st = sb + (uint32_t)(ck & 1) * STAGE_B;
        #pragma unroll
        for (int ks = 0; ks < 2; ks++) {
            uint32_t kb = (uint32_t)(ks * 32);
            uint32_t ah[4][4], al[4][4], bh[4][2], bl[4][2];
            #pragma unroll
            for (int mp = 0; mp < 4; mp++) {
                uint32_t ra = st + (uint32_t)((wm + mp * 16) * 80) + a_off + kb;
                ldmx4(ah[mp], ra);
                ldmx4(al[mp], ra + TILEB);
            }
            #pragma unroll
            for (int np = 0; np < 4; np++) {
                uint32_t rb = st + 2 * TILEB + (uint32_t)((wn + np * 8) * 80) + b_off + kb;
                ldmx2(bh[np], rb);
                ldmx2(bl[np], rb + TILEB);
            }
            #pragma unroll
            for (int mp = 0; mp < 4; mp++)
                #pragma unroll
                for (int np = 0; np < 4; np++) {
                    mma16816(acc[mp][np], ah[mp], bh[np]);
                    mma16816(acc[mp][np], ah[mp], bl[np]);
                    mma16816(acc[mp][np], al[mp], bh[np]);
                }
        }
        __syncthreads();
        if (ck + 2 < T) load_chunk(ck + 2);
    }

    float alpha = sp[0] / g_sigma[sidx];
    int rl = lane >> 2, cl2 = (lane & 3) * 2;

    #pragma unroll
    for (int mp = 0; mp < 4; mp++) {
        #pragma unroll
        for (int np = 0; np < 4; np++) {
            #pragma unroll
            for (int half = 0; half < 2; half++) {
                int gm = m0 + wm + mp * 16 + rl + half * 8;
                int gn = n0 + wn + np * 8 + cl2;
                float v0 = acc[mp][np][half * 2 + 0];
                float v1 = acc[mp][np][half * 2 + 1];
                #pragma unroll
                for (int e = 0; e < 2; e++) {
                    int n = gn + e;
                    if (n >= N) continue;
                    float v = fmaf(alpha, e ? v1 : v0, bias[n]);
                    if (EPI == 1) v += extra[(size_t)gm * N + n];
                    if (EPI == 2) {
                        float g = extra[(size_t)gm * N + n];
                        v = v * (g / (1.0f + __expf(-g)));
                    }
                    if (OUTPAIR) {
                        bf16 h = __float2bfloat16(v);
                        Ch[(size_t)gm * Cp + n] = h;
                        Cl[(size_t)gm * Cp + n] = __float2bfloat16(v - __bfloat162float(h));
                    } else {
                        Cf[(size_t)gm * N + n] = v;
                    }
                }
            }
        }
    }
}

// ---------------- weight transpose + split ----------------
__global__ void wconv(const float* __restrict__ W, int K, int N,
                      bf16* __restrict__ Oh, bf16* __restrict__ Ol, int Kp) {
    __shared__ float t[32][33];
    int bx = blockIdx.x * 32, by = blockIdx.y * 32;
    int x = threadIdx.x, y = threadIdx.y;
    for (int yy = y; yy < 32; yy += 8) {
        int k = by + yy, n = bx + x;
        t[yy][x] = (k < K && n < N) ? W[(size_t)k * N + n] : 0.0f;
    }
    __syncthreads();
    for (int yy = y; yy < 32; yy += 8) {
        int n = bx + yy, k = by + x;
        if (n < N && k < K) {
            float v = t[x][yy];
            bf16 h = __float2bfloat16(v);
            Oh[(size_t)n * Kp + k] = h;
            Ol[(size_t)n * Kp + k] = __float2bfloat16(v - __bfloat162float(h));
        }
    }
}

// ---------------- power iteration ----------------
__global__ void pi_init() {
    int idx = blockIdx.x * 256 + threadIdx.x;
    if (idx < 7 * MDIM) {
        int wi = idx / MDIM, j = idx % MDIM;
        int cols = c_cols[wi];
        float val = (j < cols) ? 1.0f / (sqrtf((float)cols) + EPSF) : 0.0f;
        (&g_u[0][0])[idx] = val;
    }
    if (idx < 7 * 16) (&g_n2[0][0])[idx] = 0.0f;
}
__global__ void pi_zero_u() {
    int idx = blockIdx.x * 256 + threadIdx.x;
    if (idx < 7 * MDIM) (&g_u[0][0])[idx] = 0.0f;
}
__global__ void pi_fwd(WP wp, int t) {
    int gw = (blockIdx.x * blockDim.x + threadIdx.x) >> 5;
    int lane = threadIdx.x & 31;
    if (gw >= 6 * 1024 + 2736) return;
    int wi, r;
    if (gw < 6144) { wi = gw >> 10; r = gw & 1023; } else { wi = 6; r = gw - 6144; }
    int cols = c_cols[wi];
    float su = 1.0f;
    if (t > 0) su = 1.0f / (sqrtf(g_n2[wi][8 + t - 1]) + EPSF);
    const float* row = wp.p[wi] + (size_t)r * cols;
    const float* u = g_u[wi];
    float acc = 0.0f;
    for (int c = lane * 4; c < cols; c += 128) {
        float4 kv = *(const float4*)(row + c);
        float4 uv = *(const float4*)(u + c);
        acc += kv.x * uv.x + kv.y * uv.y + kv.z * uv.z + kv.w * uv.w;
    }
    #pragma unroll
    for (int o = 16; o; o >>= 1) acc += __shfl_xor_sync(0xffffffffu, acc, o);
    if (lane == 0) {
        float y = acc * su;
        g_w[wi][r] = y;
        atomicAdd(&g_n2[wi][t], y * y);
    }
}
__global__ void pi_bwd(WP wp, int t) {
    __shared__ float ws[512];
    int bid = blockIdx.x, wi = 0;
    for (;;) { int nb = c_nct[wi] * c_nrc[wi]; if (bid < nb) break; bid -= nb; wi++; }
    int ct = bid % c_nct[wi], rc = bid / c_nct[wi];
    int rows = c_rows[wi], cols = c_cols[wi];
    float sv = 1.0f / (sqrtf(g_n2[wi][t]) + EPSF);
    int i0 = rc * 512;
    int ilen = min(512, rows - i0);
    for (int i = threadIdx.x; i < ilen; i += 256) ws[i] = g_w[wi][i0 + i] * sv;
    __syncthreads();
    int j = ct * 256 + threadIdx.x;
    if (j < cols) {
        const float* base = wp.p[wi] + (size_t)i0 * cols + j;
        float acc = 0.0f;
        int i = 0;
        for (; i + 4 <= ilen; i += 4) {
            acc += base[(size_t)i * cols] * ws[i]
                 + base[(size_t)(i + 1) * cols] * ws[i + 1]
                 + base[(size_t)(i + 2) * cols] * ws[i + 2]
                 + base[(size_t)(i + 3) * cols] * ws[i + 3];
        }
        for (; i < ilen; i++) acc += base[(size_t)i * cols] * ws[i];
        atomicAdd(&g_u[wi][j], acc);
    }
}
__global__ void pi_norm_u(int t) {
    int wi = blockIdx.x;
    int cols = c_cols[wi];
    float s = 0.0f;
    for (int j = threadIdx.x; j < cols; j += 256) { float v = g_u[wi][j]; s += v * v; }
    #pragma unroll
    for (int o = 16; o; o >>= 1) s += __shfl_xor_sync(0xffffffffu, s, o);
    __shared__ float red[8];
    if ((threadIdx.x & 31) == 0) red[threadIdx.x >> 5] = s;
    __syncthreads();
    if (threadIdx.x == 0) {
        float tot = 0.0f;
        #pragma unroll
        for (int i = 0; i < 8; i++) tot += red[i];
        g_n2[wi][8 + t] = tot;
    }
}
__global__ void pi_sigma() {
    int wi = threadIdx.x;
    if (wi < 7) {
        float n2 = g_n2[wi][5];
        float s = sqrtf(n2);
        g_sigma[wi] = fmaxf(n2 / (s + EPSF), EPSF);
    }
}

// ---------------- elementwise ----------------
__global__ void rmsnorm_pair(const float* __restrict__ x, const float* __restrict__ sc,
                             bf16* __restrict__ oh, bf16* __restrict__ ol) {
    int row = blockIdx.x;
    const float* xr = x + (size_t)row * DDIM;
    float4 v = *(const float4*)(xr + threadIdx.x * 4);
    float s = v.x * v.x + v.y * v.y + v.z * v.z + v.w * v.w;
    #pragma unroll
    for (int o = 16; o; o >>= 1) s += __shfl_xor_sync(0xffffffffu, s, o);
    __shared__ float red[8];
    if ((threadIdx.x & 31) == 0) red[threadIdx.x >> 5] = s;
    __syncthreads();
    float tot = 0.0f;
    #pragma unroll
    for (int i = 0; i < 8; i++) tot += red[i];
    float r = rsqrtf(tot * (1.0f / (float)DDIM) + EPSF);
    float4 s4 = *(const float4*)(sc + threadIdx.x * 4);
    float y[4] = {v.x * r * s4.x, v.y * r * s4.y, v.z * r * s4.z, v.w * r * s4.w};
    size_t base = (size_t)row * DDIM + threadIdx.x * 4;
    #pragma unroll
    for (int c = 0; c < 4; c++) {
        bf16 h = __float2bfloat16(y[c]);
        oh[base + c] = h;
        ol[base + c] = __float2bfloat16(y[c] - __bfloat162float(h));
    }
}

__global__ void f2pair(const float* __restrict__ in, bf16* __restrict__ oh,
                       bf16* __restrict__ ol, int n4) {
    int i = blockIdx.x * 256 + threadIdx.x;
    if (i < n4) {
        float4 v = ((const float4*)in)[i];
        float y[4] = {v.x, v.y, v.z, v.w};
        #pragma unroll
        for (int c = 0; c < 4; c++) {
            bf16 h = __float2bfloat16(y[c]);
            oh[i * 4 + c] = h;
            ol[i * 4 + c] = __float2bfloat16(y[c] - __bfloat162float(h));
        }
    }
}

__global__ void qknorm_kernel(const float* __restrict__ qsc, const float* __restrict__ ksc) {
    int warp = threadIdx.x >> 5, lane = threadIdx.x & 31;
    int gw = blockIdx.x * 8 + warp;
    int n = gw >> 4, h = gw & 15;
    float* p = (blockIdx.y ? g_k : g_q) + (size_t)n * DDIM + h * HDIM;
    const float* sc = blockIdx.y ? ksc : qsc;
    float2 v = *(float2*)(p + lane * 2);
    float s = v.x * v.x + v.y * v.y;
    #pragma unroll
    for (int o = 16; o; o >>= 1) s += __shfl_xor_sync(0xffffffffu, s, o);
    float r = rsqrtf(s * (1.0f / (float)HDIM) + EPSF);
    float2 scv = *(const float2*)(sc + lane * 2);
    v.x *= r * scv.x; v.y *= r * scv.y;
    *(float2*)(p + lane * 2) = v;
}

// ---------------- fused attention (fp32 flash) ----------------
#define ATTN_STRIDE 68
#define ATTN_SMEM (3 * 64 * ATTN_STRIDE * 4)

__global__ __launch_bounds__(256) void attn_kernel(const float* __restrict__ q,
                                                   const float* __restrict__ k,
                                                   const float* __restrict__ v,
                                                   float* __restrict__ out) {
    extern __shared__ float sm[];
    float(*Qs)[ATTN_STRIDE] = (float(*)[ATTN_STRIDE])sm;
    float(*Ks)[ATTN_STRIDE] = (float(*)[ATTN_STRIDE])(sm + 64 * ATTN_STRIDE);
    float(*Vs)[ATTN_STRIDE] = (float(*)[ATTN_STRIDE])(sm + 2 * 64 * ATTN_STRIDE);

    int tid = threadIdx.x;
    int tx = tid & 15, ty = tid >> 4;
    int bh = blockIdx.y;
    int b = bh >> 4, h = bh & 15;
    int q0 = blockIdx.x * 64;
    size_t base = ((size_t)b * SEQ) * DDIM + (size_t)h * HDIM;

    {
        int d4 = (tid & 15) * 4;
        int i0 = tid >> 4;
        #pragma unroll
        for (int ss = 0; ss < 4; ss++) {
            int i = i0 + ss * 16;
            float4 t4 = *(const float4*)(q + base + (size_t)(q0 + i) * DDIM + d4);
            Qs[d4 + 0][i] = t4.x; Qs[d4 + 1][i] = t4.y;
            Qs[d4 + 2][i] = t4.z; Qs[d4 + 3][i] = t4.w;
        }
    }

    float m[4], lsum[4], o[4][4];
    #pragma unroll
    for (int r = 0; r < 4; r++) {
        m[r] = -1e30f; lsum[r] = 0.0f;
        #pragma unroll
        for (int c = 0; c < 4; c++) o[r][c] = 0.0f;
    }

    for (int kt = 0; kt < 16; kt++) {
        __syncthreads();
        {
            int d4 = (tid & 15) * 4;
            int j0 = tid >> 4;
            #pragma unroll
            for (int ss = 0; ss < 4; ss++) {
                int j = j0 + ss * 16;
                const float* kp = k + base + (size_t)(kt * 64 + j) * DDIM + d4;
                float4 t4 = *(const float4*)kp;
                Ks[d4 + 0][j] = t4.x; Ks[d4 + 1][j] = t4.y;
                Ks[d4 + 2][j] = t4.z; Ks[d4 + 3][j] = t4.w;
                const float* vp = v + base + (size_t)(kt * 64 + j) * DDIM + d4;
                *(float4*)&Vs[j][d4] = *(const float4*)vp;
            }
        }
        __syncthreads();

        float s[4][4];
        #pragma unroll
        for (int r = 0; r < 4; r++)
            #pragma unroll
            for (int c = 0; c < 4; c++) s[r][c] = 0.0f;

        #pragma unroll 8
        for (int d = 0; d < 64; d++) {
            float a[4], bb[4];
            *(float4*)a = *(const float4*)&Qs[d][ty * 4];
            *(float4*)bb = *(const float4*)&Ks[d][tx * 4];
            #pragma unroll
            for (int r = 0; r < 4; r++)
                #pragma unroll
                for (int c = 0; c < 4; c++)
                    s[r][c] = fmaf(a[r], bb[c], s[r][c]);
        }

        #pragma unroll
        for (int r = 0; r < 4; r++)
            #pragma unroll
            for (int c = 0; c < 4; c++) {
                float l = s[r][c] * 0.125f;
                s[r][c] = 50.0f * tanhf(l * 0.02f);
            }

        float mt[4];
        #pragma unroll
        for (int r = 0; r < 4; r++) {
            mt[r] = fmaxf(fmaxf(s[r][0], s[r][1]), fmaxf(s[r][2], s[r][3]));
            #pragma unroll
            for (int off = 8; off; off >>= 1)
                mt[r] = fmaxf(mt[r], __shfl_xor_sync(0xffffffffu, mt[r], off, 16));
        }
        #pragma unroll
        for (int r = 0; r < 4; r++) {
            float mn = fmaxf(m[r], mt[r]);
            float corr = __expf(m[r] - mn);
            m[r] = mn;
            float acc = 0.0f;
            #pragma unroll
            for (int c = 0; c < 4; c++) {
                float p = __expf(s[r][c] - mn);
                s[r][c] = p;
                acc += p;
            }
            #pragma unroll
            for (int off = 8; off; off >>= 1)
                acc += __shfl_xor_sync(0xffffffffu, acc, off, 16);
            lsum[r] = lsum[r] * corr + acc;
            #pragma unroll
            for (int c = 0; c < 4; c++) o[r][c] *= corr;
        }

        __syncthreads();
        #pragma unroll
        for (int c = 0; c < 4; c++) {
            int j = tx * 4 + c;
            float4 pv = make_float4(s[0][c], s[1][c], s[2][c], s[3][c]);
            *(float4*)&Ks[j][ty * 4] = pv;
        }
        __syncthreads();

        #pragma unroll 8
        for (int j = 0; j < 64; j++) {
            float pa[4], vb[4];
            *(float4*)pa = *(const float4*)&Ks[j][ty * 4];
            *(float4*)vb = *(const float4*)&Vs[j][tx * 4];
            #pragma unroll
            for (int r = 0; r < 4; r++)
                #pragma unroll
                for (int c = 0; c < 4; c++)
                    o[r][c] = fmaf(pa[r], vb[c], o[r][c]);
        }
    }

    #pragma unroll
    for (int r = 0; r < 4; r++) {
        float inv = 1.0f / lsum[r];
        int i = ty * 4 + r;
        float4 ov = make_float4(o[r][0] * inv, o[r][1] * inv, o[r][2] * inv, o[r][3] * inv);
        *(float4*)(out + base + (size_t)(q0 + i) * DDIM + tx * 4) = ov;
    }
}

// ---------------- host ----------------
extern "C" void kernel_launch(void* const* d_in, const int* in_sizes, int n_in,
                              void* d_out, int out_size) {
    const float* x   = (const float*)d_in[0];
    const float* ln1 = (const float*)d_in[1];
    const float* wq  = (const float*)d_in[2];
    const float* sq  = (const float*)d_in[3];
    const float* bq  = (const float*)d_in[4];
    const float* wk  = (const float*)d_in[5];
    const float* sk  = (const float*)d_in[6];
    const float* bk  = (const float*)d_in[7];
    const float* wv  = (const float*)d_in[8];
    const float* sv  = (const float*)d_in[9];
    const float* bv  = (const float*)d_in[10];
    const float* qn  = (const float*)d_in[11];
    const float* kn  = (const float*)d_in[12];
    const float* wo  = (const float*)d_in[13];
    const float* so  = (const float*)d_in[14];
    const float* bo  = (const float*)d_in[15];
    const float* ln2 = (const float*)d_in[16];
    const float* wg  = (const float*)d_in[17];
    const float* sg  = (const float*)d_in[18];
    const float* bg  = (const float*)d_in[19];
    const float* wu  = (const float*)d_in[20];
    const float* su  = (const float*)d_in[21];
    const float* bu  = (const float*)d_in[22];
    const float* wd  = (const float*)d_in[23];
    const float* sd  = (const float*)d_in[24];
    const float* bd  = (const float*)d_in[25];
    float* out = (float*)d_out;

    float *p_q, *p_k, *p_v, *p_ao, *p_x1, *p_gate;
    cudaGetSymbolAddress((void**)&p_q, g_q);
    cudaGetSymbolAddress((void**)&p_k, g_k);
    cudaGetSymbolAddress((void**)&p_v, g_v);
    cudaGetSymbolAddress((void**)&p_ao, g_ao);
    cudaGetSymbolAddress((void**)&p_x1, g_x1);
    cudaGetSymbolAddress((void**)&p_gate, g_gate);

    bf16 *ai_h, *ai_l, *aop_h, *aop_l, *mi_h, *mi_l, *hb_h, *hb_l;
    cudaGetSymbolAddress((void**)&ai_h, g_ai_h);   cudaGetSymbolAddress((void**)&ai_l, g_ai_l);
    cudaGetSymbolAddress((void**)&aop_h, g_aop_h); cudaGetSymbolAddress((void**)&aop_l, g_aop_l);
    cudaGetSymbolAddress((void**)&mi_h, g_mi_h);   cudaGetSymbolAddress((void**)&mi_l, g_mi_l);
    cudaGetSymbolAddress((void**)&hb_h, g_hb_h);   cudaGetSymbolAddress((void**)&hb_l, g_hb_l);

    bf16 *wqTh, *wqTl, *wkTh, *wkTl, *wvTh, *wvTl, *woTh, *woTl;
    bf16 *wgTh, *wgTl, *wuTh, *wuTl, *wdTh, *wdTl;
    cudaGetSymbolAddress((void**)&wqTh, g_wqT_h); cudaGetSymbolAddress((void**)&wqTl, g_wqT_l);
    cudaGetSymbolAddress((void**)&wkTh, g_wkT_h); cudaGetSymbolAddress((void**)&wkTl, g_wkT_l);
    cudaGetSymbolAddress((void**)&wvTh, g_wvT_h); cudaGetSymbolAddress((void**)&wvTl, g_wvT_l);
    cudaGetSymbolAddress((void**)&woTh, g_woT_h); cudaGetSymbolAddress((void**)&woTl, g_woT_l);
    cudaGetSymbolAddress((void**)&wgTh, g_wgT_h); cudaGetSymbolAddress((void**)&wgTl, g_wgT_l);
    cudaGetSymbolAddress((void**)&wuTh, g_wuT_h); cudaGetSymbolAddress((void**)&wuTl, g_wuT_l);
    cudaGetSymbolAddress((void**)&wdTh, g_wdT_h); cudaGetSymbolAddress((void**)&wdTl, g_wdT_l);

    cudaFuncSetAttribute(gemm_hmma<0, 0>, cudaFuncAttributeMaxDynamicSharedMemorySize, GEMM_SMEM);
    cudaFuncSetAttribute(gemm_hmma<1, 0>, cudaFuncAttributeMaxDynamicSharedMemorySize, GEMM_SMEM);
    cudaFuncSetAttribute(gemm_hmma<2, 1>, cudaFuncAttributeMaxDynamicSharedMemorySize, GEMM_SMEM);
    cudaFuncSetAttribute(attn_kernel, cudaFuncAttributeMaxDynamicSharedMemorySize, ATTN_SMEM);

    WP wp;
    wp.p[0] = wq; wp.p[1] = wk; wp.p[2] = wv; wp.p[3] = wo;
    wp.p[4] = wg; wp.p[5] = wu; wp.p[6] = wd;

    // weight conversions
    dim3 wb(32, 8);
    wconv<<<dim3(32, 32), wb>>>(wq, 1024, 1024, wqTh, wqTl, 1024);
    wconv<<<dim3(32, 32), wb>>>(wk, 1024, 1024, wkTh, wkTl, 1024);
    wconv<<<dim3(32, 32), wb>>>(wv, 1024, 1024, wvTh, wvTl, 1024);
    wconv<<<dim3(32, 32), wb>>>(wo, 1024, 1024, woTh, woTl, 1024);
    wconv<<<dim3(86, 32), wb>>>(wg, 1024, 2736, wgTh, wgTl, 1024);
    wconv<<<dim3(86, 32), wb>>>(wu, 1024, 2736, wuTh, wuTl, 1024);
    wconv<<<dim3(32, 86), wb>>>(wd, 2736, 1024, wdTh, wdTl, KPADM);

    rmsnorm_pair<<<NTOK, 256>>>(x, ln1, ai_h, ai_l);

    // power iteration
    pi_init<<<75, 256>>>();
    for (int t = 0; t < 5; t++) {
        pi_fwd<<<1110, 256>>>(wp, t);
        pi_zero_u<<<75, 256>>>();
        pi_bwd<<<100, 256>>>(wp, t);
        pi_norm_u<<<7, 256>>>(t);
    }
    pi_fwd<<<1110, 256>>>(wp, 5);
    pi_sigma<<<1, 32>>>();

    // QKV projections
    dim3 g1(8, 32);
    gemm_hmma<0, 0><<<g1, 256, GEMM_SMEM>>>(ai_h, ai_l, wqTh, wqTl, 1024, 1024,
                                            p_q, nullptr, nullptr, 0, sq, 0, bq, nullptr);
    gemm_hmma<0, 0><<<g1, 256, GEMM_SMEM>>>(ai_h, ai_l, wkTh, wkTl, 1024, 1024,
                                            p_k, nullptr, nullptr, 0, sk, 1, bk, nullptr);
    gemm_hmma<0, 0><<<g1, 256, GEMM_SMEM>>>(ai_h, ai_l, wvTh, wvTl, 1024, 1024,
                                            p_v, nullptr, nullptr, 0, sv, 2, bv, nullptr);

    qknorm_kernel<<<dim3(8192, 2), 256>>>(qn, kn);
    attn_kernel<<<dim3(16, 64), 256, ATTN_SMEM>>>(p_q, p_k, p_v, p_ao);
    f2pair<<<4096, 256>>>(p_ao, aop_h, aop_l, NTOK * DDIM / 4);

    // output projection + residual -> x1
    gemm_hmma<1, 0><<<g1, 256, GEMM_SMEM>>>(aop_h, aop_l, woTh, woTl, 1024, 1024,
                                            p_x1, nullptr, nullptr, 0, so, 3, bo, x);

    rmsnorm_pair<<<NTOK, 256>>>(p_x1, ln2, mi_h, mi_l);

    // MLP
    dim3 g2(22, 32);
    gemm_hmma<0, 0><<<g2, 256, GEMM_SMEM>>>(mi_h, mi_l, wgTh, wgTl, 1024, 2736,
                                            p_gate, nullptr, nullptr, 0, sg, 4, bg, nullptr);
    gemm_hmma<2, 1><<<g2, 256, GEMM_SMEM>>>(mi_h, mi_l, wuTh, wuTl, 1024, 2736,
                                            nullptr, hb_h, hb_l, KPADM, su, 5, bu, p_gate);
    gemm_hmma<1, 0><<<g1, 256, GEMM_SMEM>>>(hb_h, hb_l, wdTh, wdTl, KPADM, 1024,
                                            out, nullptr, nullptr, 0, sd, 6, bd, p_x1);
}

// round 5
// speedup vs baseline: 1.7931x; 1.0793x over previous
#include <cuda_runtime.h>
#include <cuda_bf16.h>
#include <math.h>
#include <stdint.h>

#define EPSF 1e-6f
#define NTOK 4096
#define DDIM 1024
#define HDIM 64
#define MDIM 2736
#define SEQ  1024
#define KPADM 2752
#define NPADM 2816

typedef __nv_bfloat16 bf16;

// ---------------- scratch ----------------
__device__ float g_x1[NTOK * DDIM];
__device__ float g_gate[NTOK * MDIM];

__device__ bf16 g_ai_h[NTOK * DDIM], g_ai_l[NTOK * DDIM];
__device__ bf16 g_qh[NTOK * DDIM], g_ql[NTOK * DDIM];
__device__ bf16 g_kh[NTOK * DDIM], g_kl[NTOK * DDIM];
__device__ bf16 g_vh[NTOK * DDIM], g_vl[NTOK * DDIM];
__device__ bf16 g_aop_h[NTOK * DDIM], g_aop_l[NTOK * DDIM];
__device__ bf16 g_mi_h[NTOK * DDIM], g_mi_l[NTOK * DDIM];
__device__ bf16 g_hb_h[NTOK * KPADM], g_hb_l[NTOK * KPADM];

__device__ bf16 g_wqT_h[DDIM * DDIM], g_wqT_l[DDIM * DDIM];
__device__ bf16 g_wkT_h[DDIM * DDIM], g_wkT_l[DDIM * DDIM];
__device__ bf16 g_wvT_h[DDIM * DDIM], g_wvT_l[DDIM * DDIM];
__device__ bf16 g_woT_h[DDIM * DDIM], g_woT_l[DDIM * DDIM];
__device__ bf16 g_wgT_h[NPADM * DDIM], g_wgT_l[NPADM * DDIM];
__device__ bf16 g_wuT_h[NPADM * DDIM], g_wuT_l[NPADM * DDIM];
__device__ bf16 g_wdT_h[DDIM * KPADM], g_wdT_l[DDIM * KPADM];

__device__ float g_u[7][MDIM];
__device__ float g_w[7][MDIM];
__device__ float g_n2[7][16];
__device__ float g_sigma[7];

__constant__ int c_rows[7] = {1024, 1024, 1024, 1024, 1024, 1024, 2736};
__constant__ int c_cols[7] = {1024, 1024, 1024, 1024, 2736, 2736, 1024};
__constant__ int c_nct[7]  = {4, 4, 4, 4, 11, 11, 4};
__constant__ int c_nrc[7]  = {2, 2, 2, 2, 2, 2, 6};

struct WP { const float* p[7]; };

// ---------------- PTX helpers ----------------
__device__ __forceinline__ uint32_t s2u(const void* p) {
    uint32_t a;
    asm("{ .reg .u64 t; cvta.to.shared.u64 t, %1; cvt.u32.u64 %0, t; }" : "=r"(a) : "l"(p));
    return a;
}
__device__ __forceinline__ void cpa16(uint32_t d, const void* g) {
    asm volatile("cp.async.cg.shared.global [%0], [%1], 16;" :: "r"(d), "l"(g) : "memory");
}
__device__ __forceinline__ void cpa_commit() { asm volatile("cp.async.commit_group;" ::: "memory"); }
template <int N> __device__ __forceinline__ void cpa_wait() {
    asm volatile("cp.async.wait_group %0;" :: "n"(N) : "memory");
}
__device__ __forceinline__ void ldmx4(uint32_t* r, uint32_t a) {
    asm volatile("ldmatrix.sync.aligned.m8n8.x4.shared.b16 {%0,%1,%2,%3}, [%4];"
                 : "=r"(r[0]), "=r"(r[1]), "=r"(r[2]), "=r"(r[3]) : "r"(a));
}
__device__ __forceinline__ void ldmx2(uint32_t* r, uint32_t a) {
    asm volatile("ldmatrix.sync.aligned.m8n8.x2.shared.b16 {%0,%1}, [%2];"
                 : "=r"(r[0]), "=r"(r[1]) : "r"(a));
}
__device__ __forceinline__ void ldmx2t(uint32_t* r, uint32_t a) {
    asm volatile("ldmatrix.sync.aligned.m8n8.x2.trans.shared.b16 {%0,%1}, [%2];"
                 : "=r"(r[0]), "=r"(r[1]) : "r"(a));
}
__device__ __forceinline__ void mma16816(float* c, const uint32_t* a, const uint32_t* b) {
    asm volatile(
        "mma.sync.aligned.m16n8k16.row.col.f32.bf16.bf16.f32 "
        "{%0,%1,%2,%3}, {%4,%5,%6,%7}, {%8,%9}, {%0,%1,%2,%3};"
        : "+f"(c[0]), "+f"(c[1]), "+f"(c[2]), "+f"(c[3])
        : "r"(a[0]), "r"(a[1]), "r"(a[2]), "r"(a[3]), "r"(b[0]), "r"(b[1]));
}
__device__ __forceinline__ void packsplit(float v0, float v1, uint32_t& hi, uint32_t& lo) {
    bf16 h0 = __float2bfloat16(v0), h1 = __float2bfloat16(v1);
    __nv_bfloat162 hh; hh.x = h0; hh.y = h1;
    hi = *(uint32_t*)&hh;
    __nv_bfloat162 ll;
    ll.x = __float2bfloat16(v0 - __bfloat162float(h0));
    ll.y = __float2bfloat16(v1 - __bfloat162float(h1));
    lo = *(uint32_t*)&ll;
}

// ---------------- HMMA split-bf16 GEMM (3-stage) ----------------
#define TILEB 10240
#define STAGE_B 40960
#define GEMM_SMEM (3 * STAGE_B)

template <int EPI, int OUTPAIR>
__global__ __launch_bounds__(256)
void gemm_hmma(const bf16* __restrict__ Ah, const bf16* __restrict__ Al,
               const bf16* __restrict__ Bh, const bf16* __restrict__ Bl,
               int Kp, int N,
               float* __restrict__ Cf, bf16* __restrict__ Ch, bf16* __restrict__ Cl, int Cp,
               const float* __restrict__ sp, int sidx,
               const float* __restrict__ bias, const float* __restrict__ extra) {
    extern __shared__ char smem[];
    uint32_t sb = s2u(smem);
    int tid = threadIdx.x;
    int wid = tid >> 5, lane = tid & 31;
    int m0 = blockIdx.y * 128, n0 = blockIdx.x * 128;
    int wm = (wid & 1) * 64, wn = (wid >> 1) * 32;

    const bf16* bases[4] = {Ah, Al, Bh, Bl};
    int row0s[4] = {m0, m0, n0, n0};

    auto load_chunk = [&](int ck) {
        uint32_t st = sb + (uint32_t)(ck % 3) * STAGE_B;
        #pragma unroll
        for (int op = 0; op < 4; op++) {
            #pragma unroll
            for (int p = 0; p < 2; p++) {
                int idx = tid + p * 256;
                int r = idx >> 2, cg = idx & 3;
                const bf16* g = bases[op] + (size_t)(row0s[op] + r) * Kp + ck * 32 + cg * 8;
                cpa16(st + (uint32_t)op * TILEB + (uint32_t)(r * 80 + cg * 16), g);
            }
        }
        cpa_commit();
    };

    float acc[4][4][4];
    #pragma unroll
    for (int i = 0; i < 4; i++)
        #pragma unroll
        for (int j = 0; j < 4; j++)
            #pragma unroll
            for (int r = 0; r < 4; r++) acc[i][j][r] = 0.0f;

    const int T = Kp >> 5;
    load_chunk(0);
    load_chunk(1);
    load_chunk(2);

    uint32_t a_off = (uint32_t)((lane & 15) * 80 + (lane >> 4) * 16);
    uint32_t b_off = (uint32_t)((lane & 7) * 80 + ((lane >> 3) & 1) * 16);

    for (int ck = 0; ck < T; ck++) {
        if (ck + 2 < T) cpa_wait<2>();
        else if (ck + 1 < T) cpa_wait<1>();
        else cpa_wait<0>();
        __syncthreads();
        uint32_t st = sb + (uint32_t)(ck % 3) * STAGE_B;
        #pragma unroll
        for (int ks = 0; ks < 2; ks++) {
            uint32_t kb = (uint32_t)(ks * 32);
            uint32_t ah[4][4], al[4][4], bh[4][2], bl[4][2];
            #pragma unroll
            for (int mp = 0; mp < 4; mp++) {
                uint32_t ra = st + (uint32_t)((wm + mp * 16) * 80) + a_off + kb;
                ldmx4(ah[mp], ra);
                ldmx4(al[mp], ra + TILEB);
            }
            #pragma unroll
            for (int np = 0; np < 4; np++) {
                uint32_t rb = st + 2 * TILEB + (uint32_t)((wn + np * 8) * 80) + b_off + kb;
                ldmx2(bh[np], rb);
                ldmx2(bl[np], rb + TILEB);
            }
            #pragma unroll
            for (int mp = 0; mp < 4; mp++)
                #pragma unroll
                for (int np = 0; np < 4; np++) {
                    mma16816(acc[mp][np], ah[mp], bh[np]);
                    mma16816(acc[mp][np], ah[mp], bl[np]);
                    mma16816(acc[mp][np], al[mp], bh[np]);
                }
        }
        __syncthreads();
        if (ck + 3 < T) load_chunk(ck + 3);
    }

    float alpha = sp[0] / g_sigma[sidx];
    int rl = lane >> 2, cl2 = (lane & 3) * 2;

    #pragma unroll
    for (int mp = 0; mp < 4; mp++) {
        #pragma unroll
        for (int np = 0; np < 4; np++) {
            #pragma unroll
            for (int half = 0; half < 2; half++) {
                int gm = m0 + wm + mp * 16 + rl + half * 8;
                int gn = n0 + wn + np * 8 + cl2;
                float v0 = acc[mp][np][half * 2 + 0];
                float v1 = acc[mp][np][half * 2 + 1];
                #pragma unroll
                for (int e = 0; e < 2; e++) {
                    int n = gn + e;
                    if (n >= N) continue;
                    float v = fmaf(alpha, e ? v1 : v0, bias[n]);
                    if (EPI == 1) v += extra[(size_t)gm * N + n];
                    if (EPI == 2) {
                        float g = extra[(size_t)gm * N + n];
                        v = v * (g / (1.0f + __expf(-g)));
                    }
                    if (OUTPAIR) {
                        bf16 h = __float2bfloat16(v);
                        Ch[(size_t)gm * Cp + n] = h;
                        Cl[(size_t)gm * Cp + n] = __float2bfloat16(v - __bfloat162float(h));
                    } else {
                        Cf[(size_t)gm * N + n] = v;
                    }
                }
            }
        }
    }
}

// ---------------- weight transpose + split ----------------
__global__ void wconv(const float* __restrict__ W, int K, int N,
                      bf16* __restrict__ Oh, bf16* __restrict__ Ol, int Kp) {
    __shared__ float t[32][33];
    int bx = blockIdx.x * 32, by = blockIdx.y * 32;
    int x = threadIdx.x, y = threadIdx.y;
    for (int yy = y; yy < 32; yy += 8) {
        int k = by + yy, n = bx + x;
        t[yy][x] = (k < K && n < N) ? W[(size_t)k * N + n] : 0.0f;
    }
    __syncthreads();
    for (int yy = y; yy < 32; yy += 8) {
        int n = bx + yy, k = by + x;
        if (n < N && k < K) {
            float v = t[x][yy];
            bf16 h = __float2bfloat16(v);
            Oh[(size_t)n * Kp + k] = h;
            Ol[(size_t)n * Kp + k] = __float2bfloat16(v - __bfloat162float(h));
        }
    }
}

// ---------------- power iteration ----------------
__global__ void pi_init() {
    int idx = blockIdx.x * 256 + threadIdx.x;
    if (idx < 7 * MDIM) {
        int wi = idx / MDIM, j = idx % MDIM;
        int cols = c_cols[wi];
        float val = (j < cols) ? 1.0f / (sqrtf((float)cols) + EPSF) : 0.0f;
        (&g_u[0][0])[idx] = val;
    }
    if (idx < 7 * 16) (&g_n2[0][0])[idx] = 0.0f;
}
__global__ void pi_zero_u() {
    int idx = blockIdx.x * 256 + threadIdx.x;
    if (idx < 7 * MDIM) (&g_u[0][0])[idx] = 0.0f;
}
__global__ void pi_fwd(WP wp, int t) {
    int gw = (blockIdx.x * blockDim.x + threadIdx.x) >> 5;
    int lane = threadIdx.x & 31;
    if (gw >= 6 * 1024 + 2736) return;
    int wi, r;
    if (gw < 6144) { wi = gw >> 10; r = gw & 1023; } else { wi = 6; r = gw - 6144; }
    int cols = c_cols[wi];
    float su = 1.0f;
    if (t > 0) su = 1.0f / (sqrtf(g_n2[wi][8 + t - 1]) + EPSF);
    const float* row = wp.p[wi] + (size_t)r * cols;
    const float* u = g_u[wi];
    float acc = 0.0f;
    for (int c = lane * 4; c < cols; c += 128) {
        float4 kv = *(const float4*)(row + c);
        float4 uv = *(const float4*)(u + c);
        acc += kv.x * uv.x + kv.y * uv.y + kv.z * uv.z + kv.w * uv.w;
    }
    #pragma unroll
    for (int o = 16; o; o >>= 1) acc += __shfl_xor_sync(0xffffffffu, acc, o);
    if (lane == 0) {
        float y = acc * su;
        g_w[wi][r] = y;
        atomicAdd(&g_n2[wi][t], y * y);
    }
}
__global__ void pi_bwd(WP wp, int t) {
    __shared__ float ws[512];
    int bid = blockIdx.x, wi = 0;
    for (;;) { int nb = c_nct[wi] * c_nrc[wi]; if (bid < nb) break; bid -= nb; wi++; }
    int ct = bid % c_nct[wi], rc = bid / c_nct[wi];
    int rows = c_rows[wi], cols = c_cols[wi];
    float sv = 1.0f / (sqrtf(g_n2[wi][t]) + EPSF);
    int i0 = rc * 512;
    int ilen = min(512, rows - i0);
    for (int i = threadIdx.x; i < ilen; i += 256) ws[i] = g_w[wi][i0 + i] * sv;
    __syncthreads();
    int j = ct * 256 + threadIdx.x;
    if (j < cols) {
        const float* base = wp.p[wi] + (size_t)i0 * cols + j;
        float acc = 0.0f;
        int i = 0;
        for (; i + 4 <= ilen; i += 4) {
            acc += base[(size_t)i * cols] * ws[i]
                 + base[(size_t)(i + 1) * cols] * ws[i + 1]
                 + base[(size_t)(i + 2) * cols] * ws[i + 2]
                 + base[(size_t)(i + 3) * cols] * ws[i + 3];
        }
        for (; i < ilen; i++) acc += base[(size_t)i * cols] * ws[i];
        atomicAdd(&g_u[wi][j], acc);
    }
}
__global__ void pi_norm_u(int t) {
    int wi = blockIdx.x;
    int cols = c_cols[wi];
    float s = 0.0f;
    for (int j = threadIdx.x; j < cols; j += 256) { float v = g_u[wi][j]; s += v * v; }
    #pragma unroll
    for (int o = 16; o; o >>= 1) s += __shfl_xor_sync(0xffffffffu, s, o);
    __shared__ float red[8];
    if ((threadIdx.x & 31) == 0) red[threadIdx.x >> 5] = s;
    __syncthreads();
    if (threadIdx.x == 0) {
        float tot = 0.0f;
        #pragma unroll
        for (int i = 0; i < 8; i++) tot += red[i];
        g_n2[wi][8 + t] = tot;
    }
}
__global__ void pi_sigma() {
    int wi = threadIdx.x;
    if (wi < 7) {
        float n2 = g_n2[wi][5];
        float s = sqrtf(n2);
        g_sigma[wi] = fmaxf(n2 / (s + EPSF), EPSF);
    }
}

// ---------------- elementwise ----------------
__global__ void rmsnorm_pair(const float* __restrict__ x, const float* __restrict__ sc,
                             bf16* __restrict__ oh, bf16* __restrict__ ol) {
    int row = blockIdx.x;
    const float* xr = x + (size_t)row * DDIM;
    float4 v = *(const float4*)(xr + threadIdx.x * 4);
    float s = v.x * v.x + v.y * v.y + v.z * v.z + v.w * v.w;
    #pragma unroll
    for (int o = 16; o; o >>= 1) s += __shfl_xor_sync(0xffffffffu, s, o);
    __shared__ float red[8];
    if ((threadIdx.x & 31) == 0) red[threadIdx.x >> 5] = s;
    __syncthreads();
    float tot = 0.0f;
    #pragma unroll
    for (int i = 0; i < 8; i++) tot += red[i];
    float r = rsqrtf(tot * (1.0f / (float)DDIM) + EPSF);
    float4 s4 = *(const float4*)(sc + threadIdx.x * 4);
    float y[4] = {v.x * r * s4.x, v.y * r * s4.y, v.z * r * s4.z, v.w * r * s4.w};
    size_t base = (size_t)row * DDIM + threadIdx.x * 4;
    #pragma unroll
    for (int c = 0; c < 4; c++) {
        bf16 h = __float2bfloat16(y[c]);
        oh[base + c] = h;
        ol[base + c] = __float2bfloat16(y[c] - __bfloat162float(h));
    }
}

__global__ void qknorm_pair(bf16* __restrict__ qh, bf16* __restrict__ ql,
                            bf16* __restrict__ kh, bf16* __restrict__ kl,
                            const float* __restrict__ qsc, const float* __restrict__ ksc) {
    int warp = threadIdx.x >> 5, lane = threadIdx.x & 31;
    int gw = blockIdx.x * 8 + warp;
    int n = gw >> 4, h = gw & 15;
    bf16* ph = blockIdx.y ? kh : qh;
    bf16* pl = blockIdx.y ? kl : ql;
    const float* sc = blockIdx.y ? ksc : qsc;
    size_t off = (size_t)n * DDIM + h * HDIM + lane * 2;
    __nv_bfloat162 hv = *(__nv_bfloat162*)(ph + off);
    __nv_bfloat162 lv = *(__nv_bfloat162*)(pl + off);
    float v0 = __bfloat162float(hv.x) + __bfloat162float(lv.x);
    float v1 = __bfloat162float(hv.y) + __bfloat162float(lv.y);
    float s = v0 * v0 + v1 * v1;
    #pragma unroll
    for (int o = 16; o; o >>= 1) s += __shfl_xor_sync(0xffffffffu, s, o);
    float r = rsqrtf(s * (1.0f / (float)HDIM) + EPSF);
    float y0 = v0 * r * sc[lane * 2];
    float y1 = v1 * r * sc[lane * 2 + 1];
    uint32_t hi, lo;
    packsplit(y0, y1, hi, lo);
    *(uint32_t*)(ph + off) = hi;
    *(uint32_t*)(pl + off) = lo;
}

// ---------------- HMMA flash attention ----------------
// q-tile 128, 8 warps x 16 rows; K/V tiles 64x64 bf16 hi/lo, 2-stage cp.async.
#define ATSB 144
#define QTILE_B (128 * ATSB)
#define KVTILE_B (64 * ATSB)
#define ATT_STAGE (4 * KVTILE_B)
#define ATT_SMEM (2 * QTILE_B + 2 * ATT_STAGE)

__global__ __launch_bounds__(256)
void attn_hmma(const bf16* __restrict__ qh, const bf16* __restrict__ ql,
               const bf16* __restrict__ kh, const bf16* __restrict__ kl,
               const bf16* __restrict__ vh, const bf16* __restrict__ vl,
               bf16* __restrict__ oh, bf16* __restrict__ ol) {
    extern __shared__ char smem[];
    uint32_t sb = s2u(smem);
    int tid = threadIdx.x, wid = tid >> 5, lane = tid & 31;
    int bh = blockIdx.y, b = bh >> 4, h = bh & 15;
    int q0 = blockIdx.x * 128;
    size_t base = ((size_t)b * SEQ) * DDIM + (size_t)h * HDIM;
    int wm = wid * 16;

    // Q load (hi+lo)
    #pragma unroll
    for (int p = 0; p < 4; p++) {
        int idx = tid + p * 256;
        int r = idx >> 3, c = idx & 7;
        size_t g = base + (size_t)(q0 + r) * DDIM + c * 8;
        uint32_t o = (uint32_t)(r * ATSB + c * 16);
        cpa16(sb + o, qh + g);
        cpa16(sb + QTILE_B + o, ql + g);
    }
    cpa_commit();

    auto load_kv = [&](int kt) {
        uint32_t st = sb + 2 * QTILE_B + (uint32_t)(kt & 1) * ATT_STAGE;
        int t0 = kt * 64;
        #pragma unroll
        for (int p = 0; p < 2; p++) {
            int idx = tid + p * 256;
            int r = idx >> 3, c = idx & 7;
            size_t g = base + (size_t)(t0 + r) * DDIM + c * 8;
            uint32_t o = (uint32_t)(r * ATSB + c * 16);
            cpa16(st + o, kh + g);
            cpa16(st + KVTILE_B + o, kl + g);
            cpa16(st + 2 * KVTILE_B + o, vh + g);
            cpa16(st + 3 * KVTILE_B + o, vl + g);
        }
        cpa_commit();
    };
    load_kv(0);
    load_kv(1);

    float O[8][4];
    #pragma unroll
    for (int i = 0; i < 8; i++)
        #pragma unroll
        for (int j = 0; j < 4; j++) O[i][j] = 0.0f;
    float m0v = -1e30f, m1v = -1e30f, l0 = 0.0f, l1 = 0.0f;

    for (int kt = 0; kt < 16; kt++) {
        if (kt < 15) cpa_wait<1>(); else cpa_wait<0>();
        __syncthreads();
        uint32_t sK = sb + 2 * QTILE_B + (uint32_t)(kt & 1) * ATT_STAGE;
        uint32_t sV = sK + 2 * KVTILE_B;

        float S[8][4];
        #pragma unroll
        for (int i = 0; i < 8; i++)
            #pragma unroll
            for (int j = 0; j < 4; j++) S[i][j] = 0.0f;

        #pragma unroll
        for (int ks = 0; ks < 4; ks++) {
            uint32_t qfh[4], qfl[4];
            uint32_t qa = sb + (uint32_t)((wm + (lane & 15)) * ATSB + ks * 32 + (lane >> 4) * 16);
            ldmx4(qfh, qa);
            ldmx4(qfl, qa + QTILE_B);
            #pragma unroll
            for (int nt = 0; nt < 8; nt++) {
                uint32_t kfh[2], kfl[2];
                uint32_t ka = sK + (uint32_t)((nt * 8 + (lane & 7)) * ATSB + ks * 32 + ((lane >> 3) & 1) * 16);
                ldmx2(kfh, ka);
                ldmx2(kfl, ka + KVTILE_B);
                mma16816(S[nt], qfh, kfh);
                mma16816(S[nt], qfh, kfl);
                mma16816(S[nt], qfl, kfh);
            }
        }

        // softcap: 50*tanh(S/(8*50))
        #pragma unroll
        for (int nt = 0; nt < 8; nt++)
            #pragma unroll
            for (int j = 0; j < 4; j++) {
                float e = __expf(S[nt][j] * 0.005f);
                S[nt][j] = 50.0f * __fdividef(e - 1.0f, e + 1.0f);
            }

        // online softmax (rows r=lane>>2 and r+8)
        float mx0 = -1e30f, mx1 = -1e30f;
        #pragma unroll
        for (int nt = 0; nt < 8; nt++) {
            mx0 = fmaxf(mx0, fmaxf(S[nt][0], S[nt][1]));
            mx1 = fmaxf(mx1, fmaxf(S[nt][2], S[nt][3]));
        }
        mx0 = fmaxf(mx0, __shfl_xor_sync(0xffffffffu, mx0, 1));
        mx0 = fmaxf(mx0, __shfl_xor_sync(0xffffffffu, mx0, 2));
        mx1 = fmaxf(mx1, __shfl_xor_sync(0xffffffffu, mx1, 1));
        mx1 = fmaxf(mx1, __shfl_xor_sync(0xffffffffu, mx1, 2));
        float mn0 = fmaxf(m0v, mx0), mn1 = fmaxf(m1v, mx1);
        float c0 = __expf(m0v - mn0), c1 = __expf(m1v - mn1);
        m0v = mn0; m1v = mn1;
        float s0 = 0.0f, s1 = 0.0f;
        #pragma unroll
        for (int nt = 0; nt < 8; nt++) {
            S[nt][0] = __expf(S[nt][0] - mn0);
            S[nt][1] = __expf(S[nt][1] - mn0);
            S[nt][2] = __expf(S[nt][2] - mn1);
            S[nt][3] = __expf(S[nt][3] - mn1);
            s0 += S[nt][0] + S[nt][1];
            s1 += S[nt][2] + S[nt][3];
        }
        s0 += __shfl_xor_sync(0xffffffffu, s0, 1);
        s0 += __shfl_xor_sync(0xffffffffu, s0, 2);
        s1 += __shfl_xor_sync(0xffffffffu, s1, 1);
        s1 += __shfl_xor_sync(0xffffffffu, s1, 2);
        l0 = l0 * c0 + s0;
        l1 = l1 * c1 + s1;
        #pragma unroll
        for (int dt = 0; dt < 8; dt++) {
            O[dt][0] *= c0; O[dt][1] *= c0;
            O[dt][2] *= c1; O[dt][3] *= c1;
        }

        // P@V
        #pragma unroll
        for (int ks2 = 0; ks2 < 4; ks2++) {
            uint32_t ph[4], pl[4];
            packsplit(S[2 * ks2][0], S[2 * ks2][1], ph[0], pl[0]);
            packsplit(S[2 * ks2][2], S[2 * ks2][3], ph[1], pl[1]);
            packsplit(S[2 * ks2 + 1][0], S[2 * ks2 + 1][1], ph[2], pl[2]);
            packsplit(S[2 * ks2 + 1][2], S[2 * ks2 + 1][3], ph[3], pl[3]);
            #pragma unroll
            for (int dt = 0; dt < 8; dt++) {
                uint32_t vfh[2], vfl[2];
                uint32_t va = sV + (uint32_t)((ks2 * 16 + (lane & 15)) * ATSB + dt * 16);
                ldmx2t(vfh, va);
                ldmx2t(vfl, va + KVTILE_B);
                mma16816(O[dt], ph, vfh);
                mma16816(O[dt], ph, vfl);
                mma16816(O[dt], pl, vfh);
            }
        }
        __syncthreads();
        if (kt + 2 < 16) load_kv(kt + 2);
    }

    float i0 = 1.0f / l0, i1 = 1.0f / l1;
    int r = lane >> 2, c2 = (lane & 3) * 2;
    #pragma unroll
    for (int dt = 0; dt < 8; dt++) {
        #pragma unroll
        for (int half = 0; half < 2; half++) {
            int tok = q0 + wm + r + half * 8;
            float inv = half ? i1 : i0;
            float v0 = O[dt][half * 2 + 0] * inv;
            float v1 = O[dt][half * 2 + 1] * inv;
            uint32_t hi, lo;
            packsplit(v0, v1, hi, lo);
            size_t g = base + (size_t)tok * DDIM + dt * 8 + c2;
            *(uint32_t*)(oh + g) = hi;
            *(uint32_t*)(ol + g) = lo;
        }
    }
}

// ---------------- host ----------------
extern "C" void kernel_launch(void* const* d_in, const int* in_sizes, int n_in,
                              void* d_out, int out_size) {
    const float* x   = (const float*)d_in[0];
    const float* ln1 = (const float*)d_in[1];
    const float* wq  = (const float*)d_in[2];
    const float* sq  = (const float*)d_in[3];
    const float* bq  = (const float*)d_in[4];
    const float* wk  = (const float*)d_in[5];
    const float* sk  = (const float*)d_in[6];
    const float* bk  = (const float*)d_in[7];
    const float* wv  = (const float*)d_in[8];
    const float* sv  = (const float*)d_in[9];
    const float* bv  = (const float*)d_in[10];
    const float* qn  = (const float*)d_in[11];
    const float* kn  = (const float*)d_in[12];
    const float* wo  = (const float*)d_in[13];
    const float* so  = (const float*)d_in[14];
    const float* bo  = (const float*)d_in[15];
    const float* ln2 = (const float*)d_in[16];
    const float* wg  = (const float*)d_in[17];
    const float* sg  = (const float*)d_in[18];
    const float* bg  = (const float*)d_in[19];
    const float* wu  = (const float*)d_in[20];
    const float* su  = (const float*)d_in[21];
    const float* bu  = (const float*)d_in[22];
    const float* wd  = (const float*)d_in[23];
    const float* sd  = (const float*)d_in[24];
    const float* bd  = (const float*)d_in[25];
    float* out = (float*)d_out;

    float *p_x1, *p_gate;
    cudaGetSymbolAddress((void**)&p_x1, g_x1);
    cudaGetSymbolAddress((void**)&p_gate, g_gate);

    bf16 *ai_h, *ai_l, *aop_h, *aop_l, *mi_h, *mi_l, *hb_h, *hb_l;
    bf16 *qhp, *qlp, *khp, *klp, *vhp, *vlp;
    cudaGetSymbolAddress((void**)&ai_h, g_ai_h);   cudaGetSymbolAddress((void**)&ai_l, g_ai_l);
    cudaGetSymbolAddress((void**)&aop_h, g_aop_h); cudaGetSymbolAddress((void**)&aop_l, g_aop_l);
    cudaGetSymbolAddress((void**)&mi_h, g_mi_h);   cudaGetSymbolAddress((void**)&mi_l, g_mi_l);
    cudaGetSymbolAddress((void**)&hb_h, g_hb_h);   cudaGetSymbolAddress((void**)&hb_l, g_hb_l);
    cudaGetSymbolAddress((void**)&qhp, g_qh); cudaGetSymbolAddress((void**)&qlp, g_ql);
    cudaGetSymbolAddress((void**)&khp, g_kh); cudaGetSymbolAddress((void**)&klp, g_kl);
    cudaGetSymbolAddress((void**)&vhp, g_vh); cudaGetSymbolAddress((void**)&vlp, g_vl);

    bf16 *wqTh, *wqTl, *wkTh, *wkTl, *wvTh, *wvTl, *woTh, *woTl;
    bf16 *wgTh, *wgTl, *wuTh, *wuTl, *wdTh, *wdTl;
    cudaGetSymbolAddress((void**)&wqTh, g_wqT_h); cudaGetSymbolAddress((void**)&wqTl, g_wqT_l);
    cudaGetSymbolAddress((void**)&wkTh, g_wkT_h); cudaGetSymbolAddress((void**)&wkTl, g_wkT_l);
    cudaGetSymbolAddress((void**)&wvTh, g_wvT_h); cudaGetSymbolAddress((void**)&wvTl, g_wvT_l);
    cudaGetSymbolAddress((void**)&woTh, g_woT_h); cudaGetSymbolAddress((void**)&woTl, g_woT_l);
    cudaGetSymbolAddress((void**)&wgTh, g_wgT_h); cudaGetSymbolAddress((void**)&wgTl, g_wgT_l);
    cudaGetSymbolAddress((void**)&wuTh, g_wuT_h); cudaGetSymbolAddress((void**)&wuTl, g_wuT_l);
    cudaGetSymbolAddress((void**)&wdTh, g_wdT_h); cudaGetSymbolAddress((void**)&wdTl, g_wdT_l);

    cudaFuncSetAttribute(gemm_hmma<0, 0>, cudaFuncAttributeMaxDynamicSharedMemorySize, GEMM_SMEM);
    cudaFuncSetAttribute(gemm_hmma<0, 1>, cudaFuncAttributeMaxDynamicSharedMemorySize, GEMM_SMEM);
    cudaFuncSetAttribute(gemm_hmma<1, 0>, cudaFuncAttributeMaxDynamicSharedMemorySize, GEMM_SMEM);
    cudaFuncSetAttribute(gemm_hmma<2, 1>, cudaFuncAttributeMaxDynamicSharedMemorySize, GEMM_SMEM);
    cudaFuncSetAttribute(attn_hmma, cudaFuncAttributeMaxDynamicSharedMemorySize, ATT_SMEM);

    WP wp;
    wp.p[0] = wq; wp.p[1] = wk; wp.p[2] = wv; wp.p[3] = wo;
    wp.p[4] = wg; wp.p[5] = wu; wp.p[6] = wd;

    dim3 wb(32, 8);
    wconv<<<dim3(32, 32), wb>>>(wq, 1024, 1024, wqTh, wqTl, 1024);
    wconv<<<dim3(32, 32), wb>>>(wk, 1024, 1024, wkTh, wkTl, 1024);
    wconv<<<dim3(32, 32), wb>>>(wv, 1024, 1024, wvTh, wvTl, 1024);
    wconv<<<dim3(32, 32), wb>>>(wo, 1024, 1024, woTh, woTl, 1024);
    wconv<<<dim3(86, 32), wb>>>(wg, 1024, 2736, wgTh, wgTl, 1024);
    wconv<<<dim3(86, 32), wb>>>(wu, 1024, 2736, wuTh, wuTl, 1024);
    wconv<<<dim3(32, 86), wb>>>(wd, 2736, 1024, wdTh, wdTl, KPADM);

    rmsnorm_pair<<<NTOK, 256>>>(x, ln1, ai_h, ai_l);

    pi_init<<<75, 256>>>();
    for (int t = 0; t < 5; t++) {
        pi_fwd<<<1110, 256>>>(wp, t);
        pi_zero_u<<<75, 256>>>();
        pi_bwd<<<100, 256>>>(wp, t);
        pi_norm_u<<<7, 256>>>(t);
    }
    pi_fwd<<<1110, 256>>>(wp, 5);
    pi_sigma<<<1, 32>>>();

    // QKV projections -> bf16 pairs
    dim3 g1(8, 32);
    gemm_hmma<0, 1><<<g1, 256, GEMM_SMEM>>>(ai_h, ai_l, wqTh, wqTl, 1024, 1024,
                                            nullptr, qhp, qlp, DDIM, sq, 0, bq, nullptr);
    gemm_hmma<0, 1><<<g1, 256, GEMM_SMEM>>>(ai_h, ai_l, wkTh, wkTl, 1024, 1024,
                                            nullptr, khp, klp, DDIM, sk, 1, bk, nullptr);
    gemm_hmma<0, 1><<<g1, 256, GEMM_SMEM>>>(ai_h, ai_l, wvTh, wvTl, 1024, 1024,
                                            nullptr, vhp, vlp, DDIM, sv, 2, bv, nullptr);

    qknorm_pair<<<dim3(8192, 2), 256>>>(qhp, qlp, khp, klp, qn, kn);

    attn_hmma<<<dim3(8, 64), 256, ATT_SMEM>>>(qhp, qlp, khp, klp, vhp, vlp, aop_h, aop_l);

    gemm_hmma<1, 0><<<g1, 256, GEMM_SMEM>>>(aop_h, aop_l, woTh, woTl, 1024, 1024,
                                            p_x1, nullptr, nullptr, 0, so, 3, bo, x);

    rmsnorm_pair<<<NTOK, 256>>>(p_x1, ln2, mi_h, mi_l);

    dim3 g2(22, 32);
    gemm_hmma<0, 0><<<g2, 256, GEMM_SMEM>>>(mi_h, mi_l, wgTh, wgTl, 1024, 2736,
                                            p_gate, nullptr, nullptr, 0, sg, 4, bg, nullptr);
    gemm_hmma<2, 1><<<g2, 256, GEMM_SMEM>>>(mi_h, mi_l, wuTh, wuTl, 1024, 2736,
                                            nullptr, hb_h, hb_l, KPADM, su, 5, bu, p_gate);
    gemm_hmma<1, 0><<<g1, 256, GEMM_SMEM>>>(hb_h, hb_l, wdTh, wdTl, KPADM, 1024,
                                            out, nullptr, nullptr, 0, sd, 6, bd, p_x1);
}

// round 6
// speedup vs baseline: 2.0116x; 1.1219x over previous
#include <cuda_runtime.h>
#include <cuda_bf16.h>
#include <math.h>
#include <stdint.h>

#define EPSF 1e-6f
#define NTOK 4096
#define DDIM 1024
#define HDIM 64
#define MDIM 2736
#define SEQ  1024
#define KPADM 2752
#define NPADM 2816

typedef __nv_bfloat16 bf16;

// ---------------- scratch ----------------
__device__ float g_x1[NTOK * DDIM];
__device__ float g_gate[NTOK * MDIM];

__device__ bf16 g_ai_h[NTOK * DDIM], g_ai_l[NTOK * DDIM];
__device__ bf16 g_qh[NTOK * DDIM], g_ql[NTOK * DDIM];
__device__ bf16 g_kh[NTOK * DDIM], g_kl[NTOK * DDIM];
__device__ bf16 g_vh[NTOK * DDIM], g_vl[NTOK * DDIM];
__device__ bf16 g_aop_h[NTOK * DDIM], g_aop_l[NTOK * DDIM];
__device__ bf16 g_mi_h[NTOK * DDIM], g_mi_l[NTOK * DDIM];
__device__ bf16 g_hb_h[NTOK * KPADM], g_hb_l[NTOK * KPADM];

__device__ bf16 g_wqT_h[DDIM * DDIM], g_wqT_l[DDIM * DDIM];
__device__ bf16 g_wkT_h[DDIM * DDIM], g_wkT_l[DDIM * DDIM];
__device__ bf16 g_wvT_h[DDIM * DDIM], g_wvT_l[DDIM * DDIM];
__device__ bf16 g_woT_h[DDIM * DDIM], g_woT_l[DDIM * DDIM];
__device__ bf16 g_wgT_h[NPADM * DDIM], g_wgT_l[NPADM * DDIM];
__device__ bf16 g_wuT_h[NPADM * DDIM], g_wuT_l[NPADM * DDIM];
__device__ bf16 g_wdT_h[DDIM * KPADM], g_wdT_l[DDIM * KPADM];

__device__ float g_u[7][MDIM];
__device__ float g_w[7][MDIM];
__device__ float g_n2[7][16];
__device__ float g_sigma[7];

__constant__ int c_rows[7] = {1024, 1024, 1024, 1024, 1024, 1024, 2736};
__constant__ int c_cols[7] = {1024, 1024, 1024, 1024, 2736, 2736, 1024};
__constant__ int c_nct[7]  = {4, 4, 4, 4, 11, 11, 4};
__constant__ int c_nrc[7]  = {2, 2, 2, 2, 2, 2, 6};

struct WP { const float* p[7]; };

// ---------------- PTX helpers ----------------
__device__ __forceinline__ uint32_t s2u(const void* p) {
    uint32_t a;
    asm("{ .reg .u64 t; cvta.to.shared.u64 t, %1; cvt.u32.u64 %0, t; }" : "=r"(a) : "l"(p));
    return a;
}
__device__ __forceinline__ void cpa16(uint32_t d, const void* g) {
    asm volatile("cp.async.cg.shared.global [%0], [%1], 16;" :: "r"(d), "l"(g) : "memory");
}
__device__ __forceinline__ void cpa_commit() { asm volatile("cp.async.commit_group;" ::: "memory"); }
template <int N> __device__ __forceinline__ void cpa_wait() {
    asm volatile("cp.async.wait_group %0;" :: "n"(N) : "memory");
}
__device__ __forceinline__ void ldmx4(uint32_t* r, uint32_t a) {
    asm volatile("ldmatrix.sync.aligned.m8n8.x4.shared.b16 {%0,%1,%2,%3}, [%4];"
                 : "=r"(r[0]), "=r"(r[1]), "=r"(r[2]), "=r"(r[3]) : "r"(a));
}
__device__ __forceinline__ void ldmx2(uint32_t* r, uint32_t a) {
    asm volatile("ldmatrix.sync.aligned.m8n8.x2.shared.b16 {%0,%1}, [%2];"
                 : "=r"(r[0]), "=r"(r[1]) : "r"(a));
}
__device__ __forceinline__ void ldmx2t(uint32_t* r, uint32_t a) {
    asm volatile("ldmatrix.sync.aligned.m8n8.x2.trans.shared.b16 {%0,%1}, [%2];"
                 : "=r"(r[0]), "=r"(r[1]) : "r"(a));
}
__device__ __forceinline__ void mma16816(float* c, const uint32_t* a, const uint32_t* b) {
    asm volatile(
        "mma.sync.aligned.m16n8k16.row.col.f32.bf16.bf16.f32 "
        "{%0,%1,%2,%3}, {%4,%5,%6,%7}, {%8,%9}, {%0,%1,%2,%3};"
        : "+f"(c[0]), "+f"(c[1]), "+f"(c[2]), "+f"(c[3])
        : "r"(a[0]), "r"(a[1]), "r"(a[2]), "r"(a[3]), "r"(b[0]), "r"(b[1]));
}
__device__ __forceinline__ void packsplit(float v0, float v1, uint32_t& hi, uint32_t& lo) {
    bf16 h0 = __float2bfloat16(v0), h1 = __float2bfloat16(v1);
    __nv_bfloat162 hh; hh.x = h0; hh.y = h1;
    hi = *(uint32_t*)&hh;
    __nv_bfloat162 ll;
    ll.x = __float2bfloat16(v0 - __bfloat162float(h0));
    ll.y = __float2bfloat16(v1 - __bfloat162float(h1));
    lo = *(uint32_t*)&ll;
}

// ---------------- HMMA split-bf16 GEMM (2-stage, 2 CTAs/SM) ----------------
// EPI 0: raw pair out (no alpha/bias)  [QKV]
// EPI 1: fp32 out alpha*acc + bias + extra (residual)
// EPI 2: pair out (alpha*acc + bias) * silu(extra)
// EPI 3: fp32 out alpha*acc + bias
#define TILEB 10240
#define STAGE_B 40960
#define GEMM_SMEM (2 * STAGE_B)

template <int EPI>
__device__ __forceinline__ void gemm_body(
    const bf16* __restrict__ Ah, const bf16* __restrict__ Al,
    const bf16* __restrict__ Bh, const bf16* __restrict__ Bl,
    int Kp, int N,
    float* __restrict__ Cf, bf16* __restrict__ Ch, bf16* __restrict__ Cl, int Cp,
    const float* __restrict__ sp, int sidx,
    const float* __restrict__ bias, const float* __restrict__ extra) {
    extern __shared__ char smem[];
    uint32_t sb = s2u(smem);
    int tid = threadIdx.x;
    int wid = tid >> 5, lane = tid & 31;
    int m0 = blockIdx.y * 128, n0 = blockIdx.x * 128;
    int wm = (wid & 1) * 64, wn = (wid >> 1) * 32;

    const bf16* bases[4] = {Ah, Al, Bh, Bl};
    int row0s[4] = {m0, m0, n0, n0};

    auto load_chunk = [&](int ck) {
        uint32_t st = sb + (uint32_t)(ck & 1) * STAGE_B;
        #pragma unroll
        for (int op = 0; op < 4; op++) {
            #pragma unroll
            for (int p = 0; p < 2; p++) {
                int idx = tid + p * 256;
                int r = idx >> 2, cg = idx & 3;
                const bf16* g = bases[op] + (size_t)(row0s[op] + r) * Kp + ck * 32 + cg * 8;
                cpa16(st + (uint32_t)op * TILEB + (uint32_t)(r * 80 + cg * 16), g);
            }
        }
        cpa_commit();
    };

    float acc[4][4][4];
    #pragma unroll
    for (int i = 0; i < 4; i++)
        #pragma unroll
        for (int j = 0; j < 4; j++)
            #pragma unroll
            for (int r = 0; r < 4; r++) acc[i][j][r] = 0.0f;

    const int T = Kp >> 5;
    load_chunk(0);
    load_chunk(1);

    uint32_t a_off = (uint32_t)((lane & 15) * 80 + (lane >> 4) * 16);
    uint32_t b_off = (uint32_t)((lane & 7) * 80 + ((lane >> 3) & 1) * 16);

    for (int ck = 0; ck < T; ck++) {
        if (ck + 1 < T) cpa_wait<1>(); else cpa_wait<0>();
        __syncthreads();
        uint32_t st = sb + (uint32_t)(ck & 1) * STAGE_B;
        #pragma unroll
        for (int ks = 0; ks < 2; ks++) {
            uint32_t kb = (uint32_t)(ks * 32);
            uint32_t ah[4][4], al[4][4], bh[4][2], bl[4][2];
            #pragma unroll
            for (int mp = 0; mp < 4; mp++) {
                uint32_t ra = st + (uint32_t)((wm + mp * 16) * 80) + a_off + kb;
                ldmx4(ah[mp], ra);
                ldmx4(al[mp], ra + TILEB);
            }
            #pragma unroll
            for (int np = 0; np < 4; np++) {
                uint32_t rb = st + 2 * TILEB + (uint32_t)((wn + np * 8) * 80) + b_off + kb;
                ldmx2(bh[np], rb);
                ldmx2(bl[np], rb + TILEB);
            }
            #pragma unroll
            for (int mp = 0; mp < 4; mp++)
                #pragma unroll
                for (int np = 0; np < 4; np++) {
                    mma16816(acc[mp][np], ah[mp], bh[np]);
                    mma16816(acc[mp][np], ah[mp], bl[np]);
                    mma16816(acc[mp][np], al[mp], bh[np]);
                }
        }
        __syncthreads();
        if (ck + 2 < T) load_chunk(ck + 2);
    }

    float alpha = 1.0f;
    if (EPI != 0) alpha = sp[0] / g_sigma[sidx];
    int rl = lane >> 2, cl2 = (lane & 3) * 2;

    #pragma unroll
    for (int mp = 0; mp < 4; mp++) {
        #pragma unroll
        for (int np = 0; np < 4; np++) {
            #pragma unroll
            for (int half = 0; half < 2; half++) {
                int gm = m0 + wm + mp * 16 + rl + half * 8;
                int gn = n0 + wn + np * 8 + cl2;
                #pragma unroll
                for (int e = 0; e < 2; e++) {
                    int n = gn + e;
                    if (n >= N) continue;
                    float v = acc[mp][np][half * 2 + e];
                    if (EPI != 0) v = fmaf(alpha, v, bias[n]);
                    if (EPI == 1) v += extra[(size_t)gm * N + n];
                    if (EPI == 2) {
                        float g = extra[(size_t)gm * N + n];
                        v = v * (g / (1.0f + __expf(-g)));
                    }
                    if (EPI == 0 || EPI == 2) {
                        bf16 h = __float2bfloat16(v);
                        Ch[(size_t)gm * Cp + n] = h;
                        Cl[(size_t)gm * Cp + n] = __float2bfloat16(v - __bfloat162float(h));
                    } else {
                        Cf[(size_t)gm * N + n] = v;
                    }
                }
            }
        }
    }
}

template <int EPI>
__global__ __launch_bounds__(256, 2)
void gemm_hmma(const bf16* Ah, const bf16* Al, const bf16* Bh, const bf16* Bl,
               int Kp, int N, float* Cf, bf16* Ch, bf16* Cl, int Cp,
               const float* sp, int sidx, const float* bias, const float* extra) {
    gemm_body<EPI>(Ah, Al, Bh, Bl, Kp, N, Cf, Ch, Cl, Cp, sp, sidx, bias, extra);
}

struct QKVArgs {
    const bf16 *bh[3], *bl[3];
    bf16 *ch[3], *cl[3];
};
__global__ __launch_bounds__(256, 2)
void gemm_qkv(const bf16* Ah, const bf16* Al, QKVArgs a) {
    int z = blockIdx.z;
    gemm_body<0>(Ah, Al, a.bh[z], a.bl[z], DDIM, DDIM,
                 nullptr, a.ch[z], a.cl[z], DDIM, nullptr, 0, nullptr, nullptr);
}

// ---------------- fused weight transpose + split (all 7) ----------------
struct WCAll {
    const float* W[7];
    bf16 *Oh[7], *Ol[7];
};
__constant__ int wc_K[7]  = {1024, 1024, 1024, 1024, 1024, 1024, 2736};
__constant__ int wc_N[7]  = {1024, 1024, 1024, 1024, 2736, 2736, 1024};
__constant__ int wc_Kp[7] = {1024, 1024, 1024, 1024, 1024, 1024, KPADM};
__constant__ int wc_nb[7] = {1024, 1024, 1024, 1024, 2752, 2752, 2752};

__global__ void wconv_all(WCAll a) {
    __shared__ float t[32][33];
    int bid = blockIdx.x, wi = 0;
    while (bid >= wc_nb[wi]) { bid -= wc_nb[wi]; wi++; }
    int K = wc_K[wi], N = wc_N[wi], Kp = wc_Kp[wi];
    int tiles_x = (N + 31) >> 5;
    int bx = (bid % tiles_x) * 32, by = (bid / tiles_x) * 32;
    const float* W = a.W[wi];
    bf16* Oh = a.Oh[wi];
    bf16* Ol = a.Ol[wi];
    int x = threadIdx.x, y = threadIdx.y;
    for (int yy = y; yy < 32; yy += 8) {
        int k = by + yy, n = bx + x;
        t[yy][x] = (k < K && n < N) ? W[(size_t)k * N + n] : 0.0f;
    }
    __syncthreads();
    for (int yy = y; yy < 32; yy += 8) {
        int n = bx + yy, k = by + x;
        if (n < N && k < K) {
            float v = t[x][yy];
            bf16 h = __float2bfloat16(v);
            Oh[(size_t)n * Kp + k] = h;
            Ol[(size_t)n * Kp + k] = __float2bfloat16(v - __bfloat162float(h));
        }
    }
}

// ---------------- power iteration ----------------
__global__ void pi_init() {
    int idx = blockIdx.x * 256 + threadIdx.x;
    if (idx < 7 * MDIM) {
        int wi = idx / MDIM, j = idx % MDIM;
        int cols = c_cols[wi];
        float val = (j < cols) ? 1.0f / (sqrtf((float)cols) + EPSF) : 0.0f;
        (&g_u[0][0])[idx] = val;
    }
    if (idx < 7 * 16) (&g_n2[0][0])[idx] = 0.0f;
}
__global__ void pi_zero_u() {
    int idx = blockIdx.x * 256 + threadIdx.x;
    if (idx < 7 * MDIM) (&g_u[0][0])[idx] = 0.0f;
}
__global__ void pi_fwd(WP wp, int t) {
    int gw = (blockIdx.x * blockDim.x + threadIdx.x) >> 5;
    int lane = threadIdx.x & 31;
    if (gw >= 6 * 1024 + 2736) return;
    int wi, r;
    if (gw < 6144) { wi = gw >> 10; r = gw & 1023; } else { wi = 6; r = gw - 6144; }
    int cols = c_cols[wi];
    float su = 1.0f;
    if (t > 0) su = 1.0f / (sqrtf(g_n2[wi][8 + t - 1]) + EPSF);
    const float* row = wp.p[wi] + (size_t)r * cols;
    const float* u = g_u[wi];
    float acc = 0.0f;
    for (int c = lane * 4; c < cols; c += 128) {
        float4 kv = *(const float4*)(row + c);
        float4 uv = *(const float4*)(u + c);
        acc += kv.x * uv.x + kv.y * uv.y + kv.z * uv.z + kv.w * uv.w;
    }
    #pragma unroll
    for (int o = 16; o; o >>= 1) acc += __shfl_xor_sync(0xffffffffu, acc, o);
    if (lane == 0) {
        float y = acc * su;
        g_w[wi][r] = y;
        atomicAdd(&g_n2[wi][t], y * y);
    }
}
__global__ void pi_bwd(WP wp, int t) {
    __shared__ float ws[512];
    int bid = blockIdx.x, wi = 0;
    for (;;) { int nb = c_nct[wi] * c_nrc[wi]; if (bid < nb) break; bid -= nb; wi++; }
    int ct = bid % c_nct[wi], rc = bid / c_nct[wi];
    int rows = c_rows[wi], cols = c_cols[wi];
    float sv = 1.0f / (sqrtf(g_n2[wi][t]) + EPSF);
    int i0 = rc * 512;
    int ilen = min(512, rows - i0);
    for (int i = threadIdx.x; i < ilen; i += 256) ws[i] = g_w[wi][i0 + i] * sv;
    __syncthreads();
    int j = ct * 256 + threadIdx.x;
    if (j < cols) {
        const float* base = wp.p[wi] + (size_t)i0 * cols + j;
        float acc = 0.0f;
        int i = 0;
        for (; i + 4 <= ilen; i += 4) {
            acc += base[(size_t)i * cols] * ws[i]
                 + base[(size_t)(i + 1) * cols] * ws[i + 1]
                 + base[(size_t)(i + 2) * cols] * ws[i + 2]
                 + base[(size_t)(i + 3) * cols] * ws[i + 3];
        }
        for (; i < ilen; i++) acc += base[(size_t)i * cols] * ws[i];
        atomicAdd(&g_u[wi][j], acc);
    }
}
__global__ void pi_norm_u(int t) {
    int wi = blockIdx.x;
    int cols = c_cols[wi];
    float s = 0.0f;
    for (int j = threadIdx.x; j < cols; j += 256) { float v = g_u[wi][j]; s += v * v; }
    #pragma unroll
    for (int o = 16; o; o >>= 1) s += __shfl_xor_sync(0xffffffffu, s, o);
    __shared__ float red[8];
    if ((threadIdx.x & 31) == 0) red[threadIdx.x >> 5] = s;
    __syncthreads();
    if (threadIdx.x == 0) {
        float tot = 0.0f;
        #pragma unroll
        for (int i = 0; i < 8; i++) tot += red[i];
        g_n2[wi][8 + t] = tot;
    }
}
__global__ void pi_sigma() {
    int wi = threadIdx.x;
    if (wi < 7) {
        float n2 = g_n2[wi][5];
        float s = sqrtf(n2);
        g_sigma[wi] = fmaxf(n2 / (s + EPSF), EPSF);
    }
}

// ---------------- elementwise ----------------
__global__ void rmsnorm_pair(const float* __restrict__ x, const float* __restrict__ sc,
                             bf16* __restrict__ oh, bf16* __restrict__ ol) {
    int row = blockIdx.x;
    const float* xr = x + (size_t)row * DDIM;
    float4 v = *(const float4*)(xr + threadIdx.x * 4);
    float s = v.x * v.x + v.y * v.y + v.z * v.z + v.w * v.w;
    #pragma unroll
    for (int o = 16; o; o >>= 1) s += __shfl_xor_sync(0xffffffffu, s, o);
    __shared__ float red[8];
    if ((threadIdx.x & 31) == 0) red[threadIdx.x >> 5] = s;
    __syncthreads();
    float tot = 0.0f;
    #pragma unroll
    for (int i = 0; i < 8; i++) tot += red[i];
    float r = rsqrtf(tot * (1.0f / (float)DDIM) + EPSF);
    float4 s4 = *(const float4*)(sc + threadIdx.x * 4);
    float y[4] = {v.x * r * s4.x, v.y * r * s4.y, v.z * r * s4.z, v.w * r * s4.w};
    size_t base = (size_t)row * DDIM + threadIdx.x * 4;
    #pragma unroll
    for (int c = 0; c < 4; c++) {
        bf16 h = __float2bfloat16(y[c]);
        oh[base + c] = h;
        ol[base + c] = __float2bfloat16(y[c] - __bfloat162float(h));
    }
}

// q/k: v = alpha*z + b (exact), then rmsnorm*scale, repack pairs
__global__ void qknorm_pair(bf16* __restrict__ qh, bf16* __restrict__ ql,
                            bf16* __restrict__ kh, bf16* __restrict__ kl,
                            const float* __restrict__ qsc, const float* __restrict__ ksc,
                            const float* __restrict__ sq, const float* __restrict__ sk,
                            const float* __restrict__ bq, const float* __restrict__ bk) {
    int warp = threadIdx.x >> 5, lane = threadIdx.x & 31;
    int gw = blockIdx.x * 8 + warp;
    int n = gw >> 4, h = gw & 15;
    bf16* ph = blockIdx.y ? kh : qh;
    bf16* pl = blockIdx.y ? kl : ql;
    const float* sc = blockIdx.y ? ksc : qsc;
    const float* bb = blockIdx.y ? bk : bq;
    float alpha = (blockIdx.y ? sk[0] / g_sigma[1] : sq[0] / g_sigma[0]);
    size_t off = (size_t)n * DDIM + h * HDIM + lane * 2;
    __nv_bfloat162 hv = *(__nv_bfloat162*)(ph + off);
    __nv_bfloat162 lv = *(__nv_bfloat162*)(pl + off);
    float v0 = fmaf(alpha, __bfloat162float(hv.x) + __bfloat162float(lv.x), bb[h * HDIM + lane * 2]);
    float v1 = fmaf(alpha, __bfloat162float(hv.y) + __bfloat162float(lv.y), bb[h * HDIM + lane * 2 + 1]);
    float s = v0 * v0 + v1 * v1;
    #pragma unroll
    for (int o = 16; o; o >>= 1) s += __shfl_xor_sync(0xffffffffu, s, o);
    float r = rsqrtf(s * (1.0f / (float)HDIM) + EPSF);
    float y0 = v0 * r * sc[lane * 2];
    float y1 = v1 * r * sc[lane * 2 + 1];
    uint32_t hi, lo;
    packsplit(y0, y1, hi, lo);
    *(uint32_t*)(ph + off) = hi;
    *(uint32_t*)(pl + off) = lo;
}

// ---------------- HMMA flash attention (Q in regs, 2 CTAs/SM) ----------------
#define ATSB 144
#define KVT 9216
#define ATT_STAGE (4 * KVT)
#define ATT_SMEM (2 * ATT_STAGE)

__global__ __launch_bounds__(256, 2)
void attn_hmma(const bf16* __restrict__ qh, const bf16* __restrict__ ql,
               const bf16* __restrict__ kh, const bf16* __restrict__ kl,
               const bf16* __restrict__ vh, const bf16* __restrict__ vl,
               bf16* __restrict__ oh, bf16* __restrict__ ol,
               const float* __restrict__ svp, const float* __restrict__ bv) {
    extern __shared__ char smem[];
    uint32_t sb = s2u(smem);
    int tid = threadIdx.x, wid = tid >> 5, lane = tid & 31;
    int bh = blockIdx.y, b = bh >> 4, h = bh & 15;
    int q0 = blockIdx.x * 128;
    size_t base = ((size_t)b * SEQ) * DDIM + (size_t)h * HDIM;
    int wm = wid * 16;

    // stage Q into stage0, extract fragments to registers
    #pragma unroll
    for (int p = 0; p < 4; p++) {
        int idx = tid + p * 256;
        int r = idx >> 3, c = idx & 7;
        size_t g = base + (size_t)(q0 + r) * DDIM + c * 8;
        uint32_t o = (uint32_t)(r * ATSB + c * 16);
        cpa16(sb + o, qh + g);
        cpa16(sb + 2 * KVT + o, ql + g);
    }
    cpa_commit();
    cpa_wait<0>();
    __syncthreads();
    uint32_t qfh[4][4], qfl[4][4];
    #pragma unroll
    for (int ks = 0; ks < 4; ks++) {
        uint32_t qa = sb + (uint32_t)((wm + (lane & 15)) * ATSB + ks * 32 + (lane >> 4) * 16);
        ldmx4(qfh[ks], qa);
        ldmx4(qfl[ks], qa + 2 * KVT);
    }
    __syncthreads();

    auto load_kv = [&](int kt) {
        uint32_t st = sb + (uint32_t)(kt & 1) * ATT_STAGE;
        int t0 = kt * 64;
        #pragma unroll
        for (int p = 0; p < 2; p++) {
            int idx = tid + p * 256;
            int r = idx >> 3, c = idx & 7;
            size_t g = base + (size_t)(t0 + r) * DDIM + c * 8;
            uint32_t o = (uint32_t)(r * ATSB + c * 16);
            cpa16(st + o, kh + g);
            cpa16(st + KVT + o, kl + g);
            cpa16(st + 2 * KVT + o, vh + g);
            cpa16(st + 3 * KVT + o, vl + g);
        }
        cpa_commit();
    };
    load_kv(0);
    load_kv(1);

    float O[8][4];
    #pragma unroll
    for (int i = 0; i < 8; i++)
        #pragma unroll
        for (int j = 0; j < 4; j++) O[i][j] = 0.0f;
    float m0v = -1e30f, m1v = -1e30f, l0 = 0.0f, l1 = 0.0f;

    for (int kt = 0; kt < 16; kt++) {
        if (kt < 15) cpa_wait<1>(); else cpa_wait<0>();
        __syncthreads();
        uint32_t sK = sb + (uint32_t)(kt & 1) * ATT_STAGE;
        uint32_t sV = sK + 2 * KVT;

        float S[8][4];
        #pragma unroll
        for (int i = 0; i < 8; i++)
            #pragma unroll
            for (int j = 0; j < 4; j++) S[i][j] = 0.0f;

        #pragma unroll
        for (int ks = 0; ks < 4; ks++) {
            #pragma unroll
            for (int nt = 0; nt < 8; nt++) {
                uint32_t kfh[2], kfl[2];
                uint32_t ka = sK + (uint32_t)((nt * 8 + (lane & 7)) * ATSB + ks * 32 + ((lane >> 3) & 1) * 16);
                ldmx2(kfh, ka);
                ldmx2(kfl, ka + KVT);
                mma16816(S[nt], qfh[ks], kfh);
                mma16816(S[nt], qfh[ks], kfl);
                mma16816(S[nt], qfl[ks], kfh);
            }
        }

        #pragma unroll
        for (int nt = 0; nt < 8; nt++)
            #pragma unroll
            for (int j = 0; j < 4; j++) {
                float e = __expf(S[nt][j] * 0.005f);
                S[nt][j] = 50.0f * __fdividef(e - 1.0f, e + 1.0f);
            }

        float mx0 = -1e30f, mx1 = -1e30f;
        #pragma unroll
        for (int nt = 0; nt < 8; nt++) {
            mx0 = fmaxf(mx0, fmaxf(S[nt][0], S[nt][1]));
            mx1 = fmaxf(mx1, fmaxf(S[nt][2], S[nt][3]));
        }
        mx0 = fmaxf(mx0, __shfl_xor_sync(0xffffffffu, mx0, 1));
        mx0 = fmaxf(mx0, __shfl_xor_sync(0xffffffffu, mx0, 2));
        mx1 = fmaxf(mx1, __shfl_xor_sync(0xffffffffu, mx1, 1));
        mx1 = fmaxf(mx1, __shfl_xor_sync(0xffffffffu, mx1, 2));
        float mn0 = fmaxf(m0v, mx0), mn1 = fmaxf(m1v, mx1);
        float c0 = __expf(m0v - mn0), c1 = __expf(m1v - mn1);
        m0v = mn0; m1v = mn1;
        float s0 = 0.0f, s1 = 0.0f;
        #pragma unroll
        for (int nt = 0; nt < 8; nt++) {
            S[nt][0] = __expf(S[nt][0] - mn0);
            S[nt][1] = __expf(S[nt][1] - mn0);
            S[nt][2] = __expf(S[nt][2] - mn1);
            S[nt][3] = __expf(S[nt][3] - mn1);
            s0 += S[nt][0] + S[nt][1];
            s1 += S[nt][2] + S[nt][3];
        }
        s0 += __shfl_xor_sync(0xffffffffu, s0, 1);
        s0 += __shfl_xor_sync(0xffffffffu, s0, 2);
        s1 += __shfl_xor_sync(0xffffffffu, s1, 1);
        s1 += __shfl_xor_sync(0xffffffffu, s1, 2);
        l0 = l0 * c0 + s0;
        l1 = l1 * c1 + s1;
        #pragma unroll
        for (int dt = 0; dt < 8; dt++) {
            O[dt][0] *= c0; O[dt][1] *= c0;
            O[dt][2] *= c1; O[dt][3] *= c1;
        }

        #pragma unroll
        for (int ks2 = 0; ks2 < 4; ks2++) {
            uint32_t ph[4], pl[4];
            packsplit(S[2 * ks2][0], S[2 * ks2][1], ph[0], pl[0]);
            packsplit(S[2 * ks2][2], S[2 * ks2][3], ph[1], pl[1]);
            packsplit(S[2 * ks2 + 1][0], S[2 * ks2 + 1][1], ph[2], pl[2]);
            packsplit(S[2 * ks2 + 1][2], S[2 * ks2 + 1][3], ph[3], pl[3]);
            #pragma unroll
            for (int dt = 0; dt < 8; dt++) {
                uint32_t vfh[2], vfl[2];
                uint32_t va = sV + (uint32_t)((ks2 * 16 + (lane & 15)) * ATSB + dt * 16);
                ldmx2t(vfh, va);
                ldmx2t(vfl, va + KVT);
                mma16816(O[dt], ph, vfh);
                mma16816(O[dt], ph, vfl);
                mma16816(O[dt], pl, vfh);
            }
        }
        __syncthreads();
        if (kt + 2 < 16) load_kv(kt + 2);
    }

    float av = svp[0] / g_sigma[2];
    float i0 = av / l0, i1 = av / l1;
    int r = lane >> 2, c2 = (lane & 3) * 2;
    #pragma unroll
    for (int dt = 0; dt < 8; dt++) {
        #pragma unroll
        for (int half = 0; half < 2; half++) {
            int tok = q0 + wm + r + half * 8;
            float inv = half ? i1 : i0;
            int d = dt * 8 + c2;
            float v0 = fmaf(O[dt][half * 2 + 0], inv, bv[h * HDIM + d]);
            float v1 = fmaf(O[dt][half * 2 + 1], inv, bv[h * HDIM + d + 1]);
            uint32_t hi, lo;
            packsplit(v0, v1, hi, lo);
            size_t g = base + (size_t)tok * DDIM + d;
            *(uint32_t*)(oh + g) = hi;
            *(uint32_t*)(ol + g) = lo;
        }
    }
}

// ---------------- host ----------------
extern "C" void kernel_launch(void* const* d_in, const int* in_sizes, int n_in,
                              void* d_out, int out_size) {
    const float* x   = (const float*)d_in[0];
    const float* ln1 = (const float*)d_in[1];
    const float* wq  = (const float*)d_in[2];
    const float* sq  = (const float*)d_in[3];
    const float* bq  = (const float*)d_in[4];
    const float* wk  = (const float*)d_in[5];
    const float* sk  = (const float*)d_in[6];
    const float* bk  = (const float*)d_in[7];
    const float* wv  = (const float*)d_in[8];
    const float* sv  = (const float*)d_in[9];
    const float* bv  = (const float*)d_in[10];
    const float* qn  = (const float*)d_in[11];
    const float* kn  = (const float*)d_in[12];
    const float* wo  = (const float*)d_in[13];
    const float* so  = (const float*)d_in[14];
    const float* bo  = (const float*)d_in[15];
    const float* ln2 = (const float*)d_in[16];
    const float* wg  = (const float*)d_in[17];
    const float* sg  = (const float*)d_in[18];
    const float* bg  = (const float*)d_in[19];
    const float* wu  = (const float*)d_in[20];
    const float* su  = (const float*)d_in[21];
    const float* bu  = (const float*)d_in[22];
    const float* wd  = (const float*)d_in[23];
    const float* sd  = (const float*)d_in[24];
    const float* bd  = (const float*)d_in[25];
    float* out = (float*)d_out;

    float *p_x1, *p_gate;
    cudaGetSymbolAddress((void**)&p_x1, g_x1);
    cudaGetSymbolAddress((void**)&p_gate, g_gate);

    bf16 *ai_h, *ai_l, *aop_h, *aop_l, *mi_h, *mi_l, *hb_h, *hb_l;
    bf16 *qhp, *qlp, *khp, *klp, *vhp, *vlp;
    cudaGetSymbolAddress((void**)&ai_h, g_ai_h);   cudaGetSymbolAddress((void**)&ai_l, g_ai_l);
    cudaGetSymbolAddress((void**)&aop_h, g_aop_h); cudaGetSymbolAddress((void**)&aop_l, g_aop_l);
    cudaGetSymbolAddress((void**)&mi_h, g_mi_h);   cudaGetSymbolAddress((void**)&mi_l, g_mi_l);
    cudaGetSymbolAddress((void**)&hb_h, g_hb_h);   cudaGetSymbolAddress((void**)&hb_l, g_hb_l);
    cudaGetSymbolAddress((void**)&qhp, g_qh); cudaGetSymbolAddress((void**)&qlp, g_ql);
    cudaGetSymbolAddress((void**)&khp, g_kh); cudaGetSymbolAddress((void**)&klp, g_kl);
    cudaGetSymbolAddress((void**)&vhp, g_vh); cudaGetSymbolAddress((void**)&vlp, g_vl);

    bf16 *wqTh, *wqTl, *wkTh, *wkTl, *wvTh, *wvTl, *woTh, *woTl;
    bf16 *wgTh, *wgTl, *wuTh, *wuTl, *wdTh, *wdTl;
    cudaGetSymbolAddress((void**)&wqTh, g_wqT_h); cudaGetSymbolAddress((void**)&wqTl, g_wqT_l);
    cudaGetSymbolAddress((void**)&wkTh, g_wkT_h); cudaGetSymbolAddress((void**)&wkTl, g_wkT_l);
    cudaGetSymbolAddress((void**)&wvTh, g_wvT_h); cudaGetSymbolAddress((void**)&wvTl, g_wvT_l);
    cudaGetSymbolAddress((void**)&woTh, g_woT_h); cudaGetSymbolAddress((void**)&woTl, g_woT_l);
    cudaGetSymbolAddress((void**)&wgTh, g_wgT_h); cudaGetSymbolAddress((void**)&wgTl, g_wgT_l);
    cudaGetSymbolAddress((void**)&wuTh, g_wuT_h); cudaGetSymbolAddress((void**)&wuTl, g_wuT_l);
    cudaGetSymbolAddress((void**)&wdTh, g_wdT_h); cudaGetSymbolAddress((void**)&wdTl, g_wdT_l);

    cudaFuncSetAttribute(gemm_hmma<1>, cudaFuncAttributeMaxDynamicSharedMemorySize, GEMM_SMEM);
    cudaFuncSetAttribute(gemm_hmma<2>, cudaFuncAttributeMaxDynamicSharedMemorySize, GEMM_SMEM);
    cudaFuncSetAttribute(gemm_hmma<3>, cudaFuncAttributeMaxDynamicSharedMemorySize, GEMM_SMEM);
    cudaFuncSetAttribute(gemm_qkv, cudaFuncAttributeMaxDynamicSharedMemorySize, GEMM_SMEM);
    cudaFuncSetAttribute(attn_hmma, cudaFuncAttributeMaxDynamicSharedMemorySize, ATT_SMEM);

    static cudaStream_t s2 = nullptr;
    static cudaEvent_t evFork = nullptr, evPI = nullptr;
    if (!s2) {
        cudaStreamCreate(&s2);
        cudaEventCreateWithFlags(&evFork, cudaEventDisableTiming);
        cudaEventCreateWithFlags(&evPI, cudaEventDisableTiming);
    }

    WP wp;
    wp.p[0] = wq; wp.p[1] = wk; wp.p[2] = wv; wp.p[3] = wo;
    wp.p[4] = wg; wp.p[5] = wu; wp.p[6] = wd;

    // ---- fork: power iteration on s2, concurrent with wconv/rmsnorm/QKV ----
    cudaEventRecord(evFork, 0);
    cudaStreamWaitEvent(s2, evFork, 0);
    pi_init<<<75, 256, 0, s2>>>();
    for (int t = 0; t < 5; t++) {
        pi_fwd<<<1110, 256, 0, s2>>>(wp, t);
        pi_zero_u<<<75, 256, 0, s2>>>();
        pi_bwd<<<100, 256, 0, s2>>>(wp, t);
        pi_norm_u<<<7, 256, 0, s2>>>(t);
    }
    pi_fwd<<<1110, 256, 0, s2>>>(wp, 5);
    pi_sigma<<<1, 32, 0, s2>>>();
    cudaEventRecord(evPI, s2);

    // ---- main stream ----
    WCAll wc;
    wc.W[0] = wq; wc.Oh[0] = wqTh; wc.Ol[0] = wqTl;
    wc.W[1] = wk; wc.Oh[1] = wkTh; wc.Ol[1] = wkTl;
    wc.W[2] = wv; wc.Oh[2] = wvTh; wc.Ol[2] = wvTl;
    wc.W[3] = wo; wc.Oh[3] = woTh; wc.Ol[3] = woTl;
    wc.W[4] = wg; wc.Oh[4] = wgTh; wc.Ol[4] = wgTl;
    wc.W[5] = wu; wc.Oh[5] = wuTh; wc.Ol[5] = wuTl;
    wc.W[6] = wd; wc.Oh[6] = wdTh; wc.Ol[6] = wdTl;
    wconv_all<<<12352, dim3(32, 8)>>>(wc);

    rmsnorm_pair<<<NTOK, 256>>>(x, ln1, ai_h, ai_l);

    // QKV (raw, sigma-free) in one launch
    QKVArgs qa;
    qa.bh[0] = wqTh; qa.bl[0] = wqTl; qa.ch[0] = qhp; qa.cl[0] = qlp;
    qa.bh[1] = wkTh; qa.bl[1] = wkTl; qa.ch[1] = khp; qa.cl[1] = klp;
    qa.bh[2] = wvTh; qa.bl[2] = wvTl; qa.ch[2] = vhp; qa.cl[2] = vlp;
    gemm_qkv<<<dim3(8, 32, 3), 256, GEMM_SMEM>>>(ai_h, ai_l, qa);

    // ---- join: sigma needed from here on ----
    cudaStreamWaitEvent(0, evPI, 0);

    qknorm_pair<<<dim3(8192, 2), 256>>>(qhp, qlp, khp, klp, qn, kn, sq, sk, bq, bk);

    attn_hmma<<<dim3(8, 64), 256, ATT_SMEM>>>(qhp, qlp, khp, klp, vhp, vlp,
                                              aop_h, aop_l, sv, bv);

    dim3 g1(8, 32);
    gemm_hmma<1><<<g1, 256, GEMM_SMEM>>>(aop_h, aop_l, woTh, woTl, 1024, 1024,
                                         p_x1, nullptr, nullptr, 0, so, 3, bo, x);

    rmsnorm_pair<<<NTOK, 256>>>(p_x1, ln2, mi_h, mi_l);

    dim3 g2(22, 32);
    gemm_hmma<3><<<g2, 256, GEMM_SMEM>>>(mi_h, mi_l, wgTh, wgTl, 1024, 2736,
                                         p_gate, nullptr, nullptr, 0, sg, 4, bg, nullptr);
    gemm_hmma<2><<<g2, 256, GEMM_SMEM>>>(mi_h, mi_l, wuTh, wuTl, 1024, 2736,
                                         nullptr, hb_h, hb_l, KPADM, su, 5, bu, p_gate);
    gemm_hmma<1><<<g1, 256, GEMM_SMEM>>>(hb_h, hb_l, wdTh, wdTl, KPADM, 1024,
                                         out, nullptr, nullptr, 0, sd, 6, bd, p_x1);
}

// round 7
// speedup vs baseline: 2.4311x; 1.2085x over previous
#include <cuda_runtime.h>
#include <cuda_bf16.h>
#include <math.h>
#include <stdint.h>

#define EPSF 1e-6f
#define NTOK 4096
#define DDIM 1024
#define HDIM 64
#define MDIM 2736
#define SEQ  1024
#define KPADM 2752
#define NPADM 2816

typedef __nv_bfloat16 bf16;

// ---------------- scratch ----------------
__device__ float g_x1[NTOK * DDIM];
__device__ float g_gate[NTOK * MDIM];

__device__ bf16 g_ai_h[NTOK * DDIM], g_ai_l[NTOK * DDIM];
__device__ bf16 g_qh[NTOK * DDIM], g_ql[NTOK * DDIM];
__device__ bf16 g_kh[NTOK * DDIM], g_kl[NTOK * DDIM];
__device__ bf16 g_vh[NTOK * DDIM], g_vl[NTOK * DDIM];
__device__ bf16 g_aop_h[NTOK * DDIM], g_aop_l[NTOK * DDIM];
__device__ bf16 g_mi_h[NTOK * DDIM], g_mi_l[NTOK * DDIM];
__device__ bf16 g_hb_h[NTOK * KPADM], g_hb_l[NTOK * KPADM];

__device__ bf16 g_wqT_h[DDIM * DDIM], g_wqT_l[DDIM * DDIM];
__device__ bf16 g_wkT_h[DDIM * DDIM], g_wkT_l[DDIM * DDIM];
__device__ bf16 g_wvT_h[DDIM * DDIM], g_wvT_l[DDIM * DDIM];
__device__ bf16 g_woT_h[DDIM * DDIM], g_woT_l[DDIM * DDIM];
__device__ bf16 g_wgT_h[NPADM * DDIM], g_wgT_l[NPADM * DDIM];
__device__ bf16 g_wuT_h[NPADM * DDIM], g_wuT_l[NPADM * DDIM];
__device__ bf16 g_wdT_h[DDIM * KPADM], g_wdT_l[DDIM * KPADM];

__device__ float g_u[7][MDIM];
__device__ float g_w[7][MDIM];
__device__ float g_n2[7][16];
__device__ float g_sigma[7];

__constant__ int c_rows[7] = {1024, 1024, 1024, 1024, 1024, 1024, 2736};
__constant__ int c_cols[7] = {1024, 1024, 1024, 1024, 2736, 2736, 1024};
// pi_bwd tiling: 256-col tiles x 128-row chunks
__constant__ int c_nct[7]  = {4, 4, 4, 4, 11, 11, 4};
__constant__ int c_nrc[7]  = {8, 8, 8, 8, 8, 8, 22};
#define BWD_CH 128
#define BWD_BLOCKS 392

struct WP { const float* p[7]; };

// ---------------- PTX helpers ----------------
__device__ __forceinline__ uint32_t s2u(const void* p) {
    uint32_t a;
    asm("{ .reg .u64 t; cvta.to.shared.u64 t, %1; cvt.u32.u64 %0, t; }" : "=r"(a) : "l"(p));
    return a;
}
__device__ __forceinline__ void cpa16(uint32_t d, const void* g) {
    asm volatile("cp.async.cg.shared.global [%0], [%1], 16;" :: "r"(d), "l"(g) : "memory");
}
__device__ __forceinline__ void cpa_commit() { asm volatile("cp.async.commit_group;" ::: "memory"); }
template <int N> __device__ __forceinline__ void cpa_wait() {
    asm volatile("cp.async.wait_group %0;" :: "n"(N) : "memory");
}
__device__ __forceinline__ void ldmx4(uint32_t* r, uint32_t a) {
    asm volatile("ldmatrix.sync.aligned.m8n8.x4.shared.b16 {%0,%1,%2,%3}, [%4];"
                 : "=r"(r[0]), "=r"(r[1]), "=r"(r[2]), "=r"(r[3]) : "r"(a));
}
__device__ __forceinline__ void ldmx2(uint32_t* r, uint32_t a) {
    asm volatile("ldmatrix.sync.aligned.m8n8.x2.shared.b16 {%0,%1}, [%2];"
                 : "=r"(r[0]), "=r"(r[1]) : "r"(a));
}
__device__ __forceinline__ void ldmx2t(uint32_t* r, uint32_t a) {
    asm volatile("ldmatrix.sync.aligned.m8n8.x2.trans.shared.b16 {%0,%1}, [%2];"
                 : "=r"(r[0]), "=r"(r[1]) : "r"(a));
}
__device__ __forceinline__ void mma16816(float* c, const uint32_t* a, const uint32_t* b) {
    asm volatile(
        "mma.sync.aligned.m16n8k16.row.col.f32.bf16.bf16.f32 "
        "{%0,%1,%2,%3}, {%4,%5,%6,%7}, {%8,%9}, {%0,%1,%2,%3};"
        : "+f"(c[0]), "+f"(c[1]), "+f"(c[2]), "+f"(c[3])
        : "r"(a[0]), "r"(a[1]), "r"(a[2]), "r"(a[3]), "r"(b[0]), "r"(b[1]));
}
__device__ __forceinline__ void packsplit(float v0, float v1, uint32_t& hi, uint32_t& lo) {
    bf16 h0 = __float2bfloat16(v0), h1 = __float2bfloat16(v1);
    __nv_bfloat162 hh; hh.x = h0; hh.y = h1;
    hi = *(uint32_t*)&hh;
    __nv_bfloat162 ll;
    ll.x = __float2bfloat16(v0 - __bfloat162float(h0));
    ll.y = __float2bfloat16(v1 - __bfloat162float(h1));
    lo = *(uint32_t*)&ll;
}

// ---------------- HMMA split-bf16 GEMM (2-stage, 2 CTAs/SM) ----------------
#define TILEB 10240
#define STAGE_B 40960
#define GEMM_SMEM (2 * STAGE_B)

template <int EPI>
__device__ __forceinline__ void gemm_body(
    const bf16* __restrict__ Ah, const bf16* __restrict__ Al,
    const bf16* __restrict__ Bh, const bf16* __restrict__ Bl,
    int Kp, int N,
    float* __restrict__ Cf, bf16* __restrict__ Ch, bf16* __restrict__ Cl, int Cp,
    const float* __restrict__ sp, int sidx,
    const float* __restrict__ bias, const float* __restrict__ extra) {
    extern __shared__ char smem[];
    uint32_t sb = s2u(smem);
    int tid = threadIdx.x;
    int wid = tid >> 5, lane = tid & 31;
    int m0 = blockIdx.y * 128, n0 = blockIdx.x * 128;
    int wm = (wid & 1) * 64, wn = (wid >> 1) * 32;

    const bf16* bases[4] = {Ah, Al, Bh, Bl};
    int row0s[4] = {m0, m0, n0, n0};

    auto load_chunk = [&](int ck) {
        uint32_t st = sb + (uint32_t)(ck & 1) * STAGE_B;
        #pragma unroll
        for (int op = 0; op < 4; op++) {
            #pragma unroll
            for (int p = 0; p < 2; p++) {
                int idx = tid + p * 256;
                int r = idx >> 2, cg = idx & 3;
                const bf16* g = bases[op] + (size_t)(row0s[op] + r) * Kp + ck * 32 + cg * 8;
                cpa16(st + (uint32_t)op * TILEB + (uint32_t)(r * 80 + cg * 16), g);
            }
        }
        cpa_commit();
    };

    float acc[4][4][4];
    #pragma unroll
    for (int i = 0; i < 4; i++)
        #pragma unroll
        for (int j = 0; j < 4; j++)
            #pragma unroll
            for (int r = 0; r < 4; r++) acc[i][j][r] = 0.0f;

    const int T = Kp >> 5;
    load_chunk(0);
    load_chunk(1);

    uint32_t a_off = (uint32_t)((lane & 15) * 80 + (lane >> 4) * 16);
    uint32_t b_off = (uint32_t)((lane & 7) * 80 + ((lane >> 3) & 1) * 16);

    for (int ck = 0; ck < T; ck++) {
        if (ck + 1 < T) cpa_wait<1>(); else cpa_wait<0>();
        __syncthreads();
        uint32_t st = sb + (uint32_t)(ck & 1) * STAGE_B;
        #pragma unroll
        for (int ks = 0; ks < 2; ks++) {
            uint32_t kb = (uint32_t)(ks * 32);
            uint32_t ah[4][4], al[4][4], bh[4][2], bl[4][2];
            #pragma unroll
            for (int mp = 0; mp < 4; mp++) {
                uint32_t ra = st + (uint32_t)((wm + mp * 16) * 80) + a_off + kb;
                ldmx4(ah[mp], ra);
                ldmx4(al[mp], ra + TILEB);
            }
            #pragma unroll
            for (int np = 0; np < 4; np++) {
                uint32_t rb = st + 2 * TILEB + (uint32_t)((wn + np * 8) * 80) + b_off + kb;
                ldmx2(bh[np], rb);
                ldmx2(bl[np], rb + TILEB);
            }
            #pragma unroll
            for (int mp = 0; mp < 4; mp++)
                #pragma unroll
                for (int np = 0; np < 4; np++) {
                    mma16816(acc[mp][np], ah[mp], bh[np]);
                    mma16816(acc[mp][np], ah[mp], bl[np]);
                    mma16816(acc[mp][np], al[mp], bh[np]);
                }
        }
        __syncthreads();
        if (ck + 2 < T) load_chunk(ck + 2);
    }

    float alpha = 1.0f;
    if (EPI != 0) alpha = sp[0] / g_sigma[sidx];
    int rl = lane >> 2, cl2 = (lane & 3) * 2;

    #pragma unroll
    for (int mp = 0; mp < 4; mp++) {
        #pragma unroll
        for (int np = 0; np < 4; np++) {
            #pragma unroll
            for (int half = 0; half < 2; half++) {
                int gm = m0 + wm + mp * 16 + rl + half * 8;
                int gn = n0 + wn + np * 8 + cl2;
                #pragma unroll
                for (int e = 0; e < 2; e++) {
                    int n = gn + e;
                    if (n >= N) continue;
                    float v = acc[mp][np][half * 2 + e];
                    if (EPI != 0) v = fmaf(alpha, v, bias[n]);
                    if (EPI == 1) v += extra[(size_t)gm * N + n];
                    if (EPI == 2) {
                        float g = extra[(size_t)gm * N + n];
                        v = v * (g / (1.0f + __expf(-g)));
                    }
                    if (EPI == 0 || EPI == 2) {
                        bf16 h = __float2bfloat16(v);
                        Ch[(size_t)gm * Cp + n] = h;
                        Cl[(size_t)gm * Cp + n] = __float2bfloat16(v - __bfloat162float(h));
                    } else {
                        Cf[(size_t)gm * N + n] = v;
                    }
                }
            }
        }
    }
}

template <int EPI>
__global__ __launch_bounds__(256, 2)
void gemm_hmma(const bf16* Ah, const bf16* Al, const bf16* Bh, const bf16* Bl,
               int Kp, int N, float* Cf, bf16* Ch, bf16* Cl, int Cp,
               const float* sp, int sidx, const float* bias, const float* extra) {
    gemm_body<EPI>(Ah, Al, Bh, Bl, Kp, N, Cf, Ch, Cl, Cp, sp, sidx, bias, extra);
}

struct QKVArgs {
    const bf16 *bh[3], *bl[3];
    bf16 *ch[3], *cl[3];
};
__global__ __launch_bounds__(256, 2)
void gemm_qkv(const bf16* Ah, const bf16* Al, QKVArgs a) {
    int z = blockIdx.z;
    gemm_body<0>(Ah, Al, a.bh[z], a.bl[z], DDIM, DDIM,
                 nullptr, a.ch[z], a.cl[z], DDIM, nullptr, 0, nullptr, nullptr);
}

// ---------------- fused weight transpose + split (all 7) ----------------
struct WCAll {
    const float* W[7];
    bf16 *Oh[7], *Ol[7];
};
__constant__ int wc_K[7]  = {1024, 1024, 1024, 1024, 1024, 1024, 2736};
__constant__ int wc_N[7]  = {1024, 1024, 1024, 1024, 2736, 2736, 1024};
__constant__ int wc_Kp[7] = {1024, 1024, 1024, 1024, 1024, 1024, KPADM};
__constant__ int wc_nb[7] = {1024, 1024, 1024, 1024, 2752, 2752, 2752};

__global__ void wconv_all(WCAll a) {
    __shared__ float t[32][33];
    int bid = blockIdx.x, wi = 0;
    while (bid >= wc_nb[wi]) { bid -= wc_nb[wi]; wi++; }
    int K = wc_K[wi], N = wc_N[wi], Kp = wc_Kp[wi];
    int tiles_x = (N + 31) >> 5;
    int bx = (bid % tiles_x) * 32, by = (bid / tiles_x) * 32;
    const float* W = a.W[wi];
    bf16* Oh = a.Oh[wi];
    bf16* Ol = a.Ol[wi];
    int x = threadIdx.x, y = threadIdx.y;
    for (int yy = y; yy < 32; yy += 8) {
        int k = by + yy, n = bx + x;
        t[yy][x] = (k < K && n < N) ? W[(size_t)k * N + n] : 0.0f;
    }
    __syncthreads();
    for (int yy = y; yy < 32; yy += 8) {
        int n = bx + yy, k = by + x;
        if (n < N && k < K) {
            float v = t[x][yy];
            bf16 h = __float2bfloat16(v);
            Oh[(size_t)n * Kp + k] = h;
            Ol[(size_t)n * Kp + k] = __float2bfloat16(v - __bfloat162float(h));
        }
    }
}

// ---------------- power iteration ----------------
__global__ void pi_init() {
    int idx = blockIdx.x * 256 + threadIdx.x;
    if (idx < 7 * MDIM) {
        int wi = idx / MDIM, j = idx % MDIM;
        int cols = c_cols[wi];
        float val = (j < cols) ? 1.0f / (sqrtf((float)cols) + EPSF) : 0.0f;
        (&g_u[0][0])[idx] = val;
    }
    if (idx < 7 * 16) (&g_n2[0][0])[idx] = 0.0f;
}
__global__ void pi_zero_u() {
    int idx = blockIdx.x * 256 + threadIdx.x;
    if (idx < 7 * MDIM) (&g_u[0][0])[idx] = 0.0f;
}
__global__ void pi_fwd(WP wp, int t) {
    int gw = (blockIdx.x * blockDim.x + threadIdx.x) >> 5;
    int lane = threadIdx.x & 31;
    if (gw >= 6 * 1024 + 2736) return;
    int wi, r;
    if (gw < 6144) { wi = gw >> 10; r = gw & 1023; } else { wi = 6; r = gw - 6144; }
    int cols = c_cols[wi];
    float su = 1.0f;
    if (t > 0) su = 1.0f / (sqrtf(g_n2[wi][8 + t - 1]) + EPSF);
    const float* row = wp.p[wi] + (size_t)r * cols;
    const float* u = g_u[wi];
    float a0 = 0.0f, a1 = 0.0f;
    for (int c = lane * 4; c < cols; c += 256) {
        float4 kv = *(const float4*)(row + c);
        float4 uv = *(const float4*)(u + c);
        a0 += kv.x * uv.x + kv.y * uv.y + kv.z * uv.z + kv.w * uv.w;
        int c2 = c + 128;
        if (c2 < cols) {
            float4 kv2 = *(const float4*)(row + c2);
            float4 uv2 = *(const float4*)(u + c2);
            a1 += kv2.x * uv2.x + kv2.y * uv2.y + kv2.z * uv2.z + kv2.w * uv2.w;
        }
    }
    float acc = a0 + a1;
    #pragma unroll
    for (int o = 16; o; o >>= 1) acc += __shfl_xor_sync(0xffffffffu, acc, o);
    if (lane == 0) {
        float y = acc * su;
        g_w[wi][r] = y;
        atomicAdd(&g_n2[wi][t], y * y);
    }
}
// u += K^T @ (w/||w||): 256-col x 128-row tiles, 4 accumulators, unroll 8
__global__ void pi_bwd(WP wp, int t) {
    __shared__ float ws[BWD_CH];
    int bid = blockIdx.x, wi = 0;
    for (;;) { int nb = c_nct[wi] * c_nrc[wi]; if (bid < nb) break; bid -= nb; wi++; }
    int ct = bid % c_nct[wi], rc = bid / c_nct[wi];
    int rows = c_rows[wi], cols = c_cols[wi];
    float sv = 1.0f / (sqrtf(g_n2[wi][t]) + EPSF);
    int i0 = rc * BWD_CH;
    int ilen = min(BWD_CH, rows - i0);
    for (int i = threadIdx.x; i < ilen; i += 256) ws[i] = g_w[wi][i0 + i] * sv;
    __syncthreads();
    int j = ct * 256 + threadIdx.x;
    if (j < cols) {
        const float* base = wp.p[wi] + (size_t)i0 * cols + j;
        float a0 = 0.0f, a1 = 0.0f, a2 = 0.0f, a3 = 0.0f;
        int i = 0;
        for (; i + 8 <= ilen; i += 8) {
            a0 += base[(size_t)(i + 0) * cols] * ws[i + 0];
            a1 += base[(size_t)(i + 1) * cols] * ws[i + 1];
            a2 += base[(size_t)(i + 2) * cols] * ws[i + 2];
            a3 += base[(size_t)(i + 3) * cols] * ws[i + 3];
            a0 += base[(size_t)(i + 4) * cols] * ws[i + 4];
            a1 += base[(size_t)(i + 5) * cols] * ws[i + 5];
            a2 += base[(size_t)(i + 6) * cols] * ws[i + 6];
            a3 += base[(size_t)(i + 7) * cols] * ws[i + 7];
        }
        for (; i < ilen; i++) a0 += base[(size_t)i * cols] * ws[i];
        atomicAdd(&g_u[wi][j], (a0 + a1) + (a2 + a3));
    }
}
__global__ void pi_norm_u(int t) {
    int wi = blockIdx.x;
    int cols = c_cols[wi];
    float s = 0.0f;
    for (int j = threadIdx.x; j < cols; j += 256) { float v = g_u[wi][j]; s += v * v; }
    #pragma unroll
    for (int o = 16; o; o >>= 1) s += __shfl_xor_sync(0xffffffffu, s, o);
    __shared__ float red[8];
    if ((threadIdx.x & 31) == 0) red[threadIdx.x >> 5] = s;
    __syncthreads();
    if (threadIdx.x == 0) {
        float tot = 0.0f;
        #pragma unroll
        for (int i = 0; i < 8; i++) tot += red[i];
        g_n2[wi][8 + t] = tot;
    }
}
__global__ void pi_sigma() {
    int wi = threadIdx.x;
    if (wi < 7) {
        float n2 = g_n2[wi][5];
        float s = sqrtf(n2);
        g_sigma[wi] = fmaxf(n2 / (s + EPSF), EPSF);
    }
}

// ---------------- elementwise ----------------
__global__ void rmsnorm_pair(const float* __restrict__ x, const float* __restrict__ sc,
                             bf16* __restrict__ oh, bf16* __restrict__ ol) {
    int row = blockIdx.x;
    const float* xr = x + (size_t)row * DDIM;
    float4 v = *(const float4*)(xr + threadIdx.x * 4);
    float s = v.x * v.x + v.y * v.y + v.z * v.z + v.w * v.w;
    #pragma unroll
    for (int o = 16; o; o >>= 1) s += __shfl_xor_sync(0xffffffffu, s, o);
    __shared__ float red[8];
    if ((threadIdx.x & 31) == 0) red[threadIdx.x >> 5] = s;
    __syncthreads();
    float tot = 0.0f;
    #pragma unroll
    for (int i = 0; i < 8; i++) tot += red[i];
    float r = rsqrtf(tot * (1.0f / (float)DDIM) + EPSF);
    float4 s4 = *(const float4*)(sc + threadIdx.x * 4);
    float y[4] = {v.x * r * s4.x, v.y * r * s4.y, v.z * r * s4.z, v.w * r * s4.w};
    size_t base = (size_t)row * DDIM + threadIdx.x * 4;
    #pragma unroll
    for (int c = 0; c < 4; c++) {
        bf16 h = __float2bfloat16(y[c]);
        oh[base + c] = h;
        ol[base + c] = __float2bfloat16(y[c] - __bfloat162float(h));
    }
}

__global__ void qknorm_pair(bf16* __restrict__ qh, bf16* __restrict__ ql,
                            bf16* __restrict__ kh, bf16* __restrict__ kl,
                            const float* __restrict__ qsc, const float* __restrict__ ksc,
                            const float* __restrict__ sq, const float* __restrict__ sk,
                            const float* __restrict__ bq, const float* __restrict__ bk) {
    int warp = threadIdx.x >> 5, lane = threadIdx.x & 31;
    int gw = blockIdx.x * 8 + warp;
    int n = gw >> 4, h = gw & 15;
    bf16* ph = blockIdx.y ? kh : qh;
    bf16* pl = blockIdx.y ? kl : ql;
    const float* sc = blockIdx.y ? ksc : qsc;
    const float* bb = blockIdx.y ? bk : bq;
    float alpha = (blockIdx.y ? sk[0] / g_sigma[1] : sq[0] / g_sigma[0]);
    size_t off = (size_t)n * DDIM + h * HDIM + lane * 2;
    __nv_bfloat162 hv = *(__nv_bfloat162*)(ph + off);
    __nv_bfloat162 lv = *(__nv_bfloat162*)(pl + off);
    float v0 = fmaf(alpha, __bfloat162float(hv.x) + __bfloat162float(lv.x), bb[h * HDIM + lane * 2]);
    float v1 = fmaf(alpha, __bfloat162float(hv.y) + __bfloat162float(lv.y), bb[h * HDIM + lane * 2 + 1]);
    float s = v0 * v0 + v1 * v1;
    #pragma unroll
    for (int o = 16; o; o >>= 1) s += __shfl_xor_sync(0xffffffffu, s, o);
    float r = rsqrtf(s * (1.0f / (float)HDIM) + EPSF);
    float y0 = v0 * r * sc[lane * 2];
    float y1 = v1 * r * sc[lane * 2 + 1];
    uint32_t hi, lo;
    packsplit(y0, y1, hi, lo);
    *(uint32_t*)(ph + off) = hi;
    *(uint32_t*)(pl + off) = lo;
}

// ---------------- HMMA flash attention (Q in regs, 2 CTAs/SM) ----------------
#define ATSB 144
#define KVT 9216
#define ATT_STAGE (4 * KVT)
#define ATT_SMEM (2 * ATT_STAGE)

__global__ __launch_bounds__(256, 2)
void attn_hmma(const bf16* __restrict__ qh, const bf16* __restrict__ ql,
               const bf16* __restrict__ kh, const bf16* __restrict__ kl,
               const bf16* __restrict__ vh, const bf16* __restrict__ vl,
               bf16* __restrict__ oh, bf16* __restrict__ ol,
               const float* __restrict__ svp, const float* __restrict__ bv) {
    extern __shared__ char smem[];
    uint32_t sb = s2u(smem);
    int tid = threadIdx.x, wid = tid >> 5, lane = tid & 31;
    int bh = blockIdx.y, b = bh >> 4, h = bh & 15;
    int q0 = blockIdx.x * 128;
    size_t base = ((size_t)b * SEQ) * DDIM + (size_t)h * HDIM;
    int wm = wid * 16;

    #pragma unroll
    for (int p = 0; p < 4; p++) {
        int idx = tid + p * 256;
        int r = idx >> 3, c = idx & 7;
        size_t g = base + (size_t)(q0 + r) * DDIM + c * 8;
        uint32_t o = (uint32_t)(r * ATSB + c * 16);
        cpa16(sb + o, qh + g);
        cpa16(sb + 2 * KVT + o, ql + g);
    }
    cpa_commit();
    cpa_wait<0>();
    __syncthreads();
    uint32_t qfh[4][4], qfl[4][4];
    #pragma unroll
    for (int ks = 0; ks < 4; ks++) {
        uint32_t qa = sb + (uint32_t)((wm + (lane & 15)) * ATSB + ks * 32 + (lane >> 4) * 16);
        ldmx4(qfh[ks], qa);
        ldmx4(qfl[ks], qa + 2 * KVT);
    }
    __syncthreads();

    auto load_kv = [&](int kt) {
        uint32_t st = sb + (uint32_t)(kt & 1) * ATT_STAGE;
        int t0 = kt * 64;
        #pragma unroll
        for (int p = 0; p < 2; p++) {
            int idx = tid + p * 256;
            int r = idx >> 3, c = idx & 7;
            size_t g = base + (size_t)(t0 + r) * DDIM + c * 8;
            uint32_t o = (uint32_t)(r * ATSB + c * 16);
            cpa16(st + o, kh + g);
            cpa16(st + KVT + o, kl + g);
            cpa16(st + 2 * KVT + o, vh + g);
            cpa16(st + 3 * KVT + o, vl + g);
        }
        cpa_commit();
    };
    load_kv(0);
    load_kv(1);

    float O[8][4];
    #pragma unroll
    for (int i = 0; i < 8; i++)
        #pragma unroll
        for (int j = 0; j < 4; j++) O[i][j] = 0.0f;
    float m0v = -1e30f, m1v = -1e30f, l0 = 0.0f, l1 = 0.0f;

    for (int kt = 0; kt < 16; kt++) {
        if (kt < 15) cpa_wait<1>(); else cpa_wait<0>();
        __syncthreads();
        uint32_t sK = sb + (uint32_t)(kt & 1) * ATT_STAGE;
        uint32_t sV = sK + 2 * KVT;

        float S[8][4];
        #pragma unroll
        for (int i = 0; i < 8; i++)
            #pragma unroll
            for (int j = 0; j < 4; j++) S[i][j] = 0.0f;

        #pragma unroll
        for (int ks = 0; ks < 4; ks++) {
            #pragma unroll
            for (int nt = 0; nt < 8; nt++) {
                uint32_t kfh[2], kfl[2];
                uint32_t ka = sK + (uint32_t)((nt * 8 + (lane & 7)) * ATSB + ks * 32 + ((lane >> 3) & 1) * 16);
                ldmx2(kfh, ka);
                ldmx2(kfl, ka + KVT);
                mma16816(S[nt], qfh[ks], kfh);
                mma16816(S[nt], qfh[ks], kfl);
                mma16816(S[nt], qfl[ks], kfh);
            }
        }

        #pragma unroll
        for (int nt = 0; nt < 8; nt++)
            #pragma unroll
            for (int j = 0; j < 4; j++) {
                float e = __expf(S[nt][j] * 0.005f);
                S[nt][j] = 50.0f * __fdividef(e - 1.0f, e + 1.0f);
            }

        float mx0 = -1e30f, mx1 = -1e30f;
        #pragma unroll
        for (int nt = 0; nt < 8; nt++) {
            mx0 = fmaxf(mx0, fmaxf(S[nt][0], S[nt][1]));
            mx1 = fmaxf(mx1, fmaxf(S[nt][2], S[nt][3]));
        }
        mx0 = fmaxf(mx0, __shfl_xor_sync(0xffffffffu, mx0, 1));
        mx0 = fmaxf(mx0, __shfl_xor_sync(0xffffffffu, mx0, 2));
        mx1 = fmaxf(mx1, __shfl_xor_sync(0xffffffffu, mx1, 1));
        mx1 = fmaxf(mx1, __shfl_xor_sync(0xffffffffu, mx1, 2));
        float mn0 = fmaxf(m0v, mx0), mn1 = fmaxf(m1v, mx1);
        float c0 = __expf(m0v - mn0), c1 = __expf(m1v - mn1);
        m0v = mn0; m1v = mn1;
        float s0 = 0.0f, s1 = 0.0f;
        #pragma unroll
        for (int nt = 0; nt < 8; nt++) {
            S[nt][0] = __expf(S[nt][0] - mn0);
            S[nt][1] = __expf(S[nt][1] - mn0);
            S[nt][2] = __expf(S[nt][2] - mn1);
            S[nt][3] = __expf(S[nt][3] - mn1);
            s0 += S[nt][0] + S[nt][1];
            s1 += S[nt][2] + S[nt][3];
        }
        s0 += __shfl_xor_sync(0xffffffffu, s0, 1);
        s0 += __shfl_xor_sync(0xffffffffu, s0, 2);
        s1 += __shfl_xor_sync(0xffffffffu, s1, 1);
        s1 += __shfl_xor_sync(0xffffffffu, s1, 2);
        l0 = l0 * c0 + s0;
        l1 = l1 * c1 + s1;
        #pragma unroll
        for (int dt = 0; dt < 8; dt++) {
            O[dt][0] *= c0; O[dt][1] *= c0;
            O[dt][2] *= c1; O[dt][3] *= c1;
        }

        #pragma unroll
        for (int ks2 = 0; ks2 < 4; ks2++) {
            uint32_t ph[4], pl[4];
            packsplit(S[2 * ks2][0], S[2 * ks2][1], ph[0], pl[0]);
            packsplit(S[2 * ks2][2], S[2 * ks2][3], ph[1], pl[1]);
            packsplit(S[2 * ks2 + 1][0], S[2 * ks2 + 1][1], ph[2], pl[2]);
            packsplit(S[2 * ks2 + 1][2], S[2 * ks2 + 1][3], ph[3], pl[3]);
            #pragma unroll
            for (int dt = 0; dt < 8; dt++) {
                uint32_t vfh[2], vfl[2];
                uint32_t va = sV + (uint32_t)((ks2 * 16 + (lane & 15)) * ATSB + dt * 16);
                ldmx2t(vfh, va);
                ldmx2t(vfl, va + KVT);
                mma16816(O[dt], ph, vfh);
                mma16816(O[dt], ph, vfl);
                mma16816(O[dt], pl, vfh);
            }
        }
        __syncthreads();
        if (kt + 2 < 16) load_kv(kt + 2);
    }

    float av = svp[0] / g_sigma[2];
    float i0 = av / l0, i1 = av / l1;
    int r = lane >> 2, c2 = (lane & 3) * 2;
    #pragma unroll
    for (int dt = 0; dt < 8; dt++) {
        #pragma unroll
        for (int half = 0; half < 2; half++) {
            int tok = q0 + wm + r + half * 8;
            float inv = half ? i1 : i0;
            int d = dt * 8 + c2;
            float v0 = fmaf(O[dt][half * 2 + 0], inv, bv[h * HDIM + d]);
            float v1 = fmaf(O[dt][half * 2 + 1], inv, bv[h * HDIM + d + 1]);
            uint32_t hi, lo;
            packsplit(v0, v1, hi, lo);
            size_t g = base + (size_t)tok * DDIM + d;
            *(uint32_t*)(oh + g) = hi;
            *(uint32_t*)(ol + g) = lo;
        }
    }
}

// ---------------- host ----------------
extern "C" void kernel_launch(void* const* d_in, const int* in_sizes, int n_in,
                              void* d_out, int out_size) {
    const float* x   = (const float*)d_in[0];
    const float* ln1 = (const float*)d_in[1];
    const float* wq  = (const float*)d_in[2];
    const float* sq  = (const float*)d_in[3];
    const float* bq  = (const float*)d_in[4];
    const float* wk  = (const float*)d_in[5];
    const float* sk  = (const float*)d_in[6];
    const float* bk  = (const float*)d_in[7];
    const float* wv  = (const float*)d_in[8];
    const float* sv  = (const float*)d_in[9];
    const float* bv  = (const float*)d_in[10];
    const float* qn  = (const float*)d_in[11];
    const float* kn  = (const float*)d_in[12];
    const float* wo  = (const float*)d_in[13];
    const float* so  = (const float*)d_in[14];
    const float* bo  = (const float*)d_in[15];
    const float* ln2 = (const float*)d_in[16];
    const float* wg  = (const float*)d_in[17];
    const float* sg  = (const float*)d_in[18];
    const float* bg  = (const float*)d_in[19];
    const float* wu  = (const float*)d_in[20];
    const float* su  = (const float*)d_in[21];
    const float* bu  = (const float*)d_in[22];
    const float* wd  = (const float*)d_in[23];
    const float* sd  = (const float*)d_in[24];
    const float* bd  = (const float*)d_in[25];
    float* out = (float*)d_out;

    float *p_x1, *p_gate;
    cudaGetSymbolAddress((void**)&p_x1, g_x1);
    cudaGetSymbolAddress((void**)&p_gate, g_gate);

    bf16 *ai_h, *ai_l, *aop_h, *aop_l, *mi_h, *mi_l, *hb_h, *hb_l;
    bf16 *qhp, *qlp, *khp, *klp, *vhp, *vlp;
    cudaGetSymbolAddress((void**)&ai_h, g_ai_h);   cudaGetSymbolAddress((void**)&ai_l, g_ai_l);
    cudaGetSymbolAddress((void**)&aop_h, g_aop_h); cudaGetSymbolAddress((void**)&aop_l, g_aop_l);
    cudaGetSymbolAddress((void**)&mi_h, g_mi_h);   cudaGetSymbolAddress((void**)&mi_l, g_mi_l);
    cudaGetSymbolAddress((void**)&hb_h, g_hb_h);   cudaGetSymbolAddress((void**)&hb_l, g_hb_l);
    cudaGetSymbolAddress((void**)&qhp, g_qh); cudaGetSymbolAddress((void**)&qlp, g_ql);
    cudaGetSymbolAddress((void**)&khp, g_kh); cudaGetSymbolAddress((void**)&klp, g_kl);
    cudaGetSymbolAddress((void**)&vhp, g_vh); cudaGetSymbolAddress((void**)&vlp, g_vl);

    bf16 *wqTh, *wqTl, *wkTh, *wkTl, *wvTh, *wvTl, *woTh, *woTl;
    bf16 *wgTh, *wgTl, *wuTh, *wuTl, *wdTh, *wdTl;
    cudaGetSymbolAddress((void**)&wqTh, g_wqT_h); cudaGetSymbolAddress((void**)&wqTl, g_wqT_l);
    cudaGetSymbolAddress((void**)&wkTh, g_wkT_h); cudaGetSymbolAddress((void**)&wkTl, g_wkT_l);
    cudaGetSymbolAddress((void**)&wvTh, g_wvT_h); cudaGetSymbolAddress((void**)&wvTl, g_wvT_l);
    cudaGetSymbolAddress((void**)&woTh, g_woT_h); cudaGetSymbolAddress((void**)&woTl, g_woT_l);
    cudaGetSymbolAddress((void**)&wgTh, g_wgT_h); cudaGetSymbolAddress((void**)&wgTl, g_wgT_l);
    cudaGetSymbolAddress((void**)&wuTh, g_wuT_h); cudaGetSymbolAddress((void**)&wuTl, g_wuT_l);
    cudaGetSymbolAddress((void**)&wdTh, g_wdT_h); cudaGetSymbolAddress((void**)&wdTl, g_wdT_l);

    cudaFuncSetAttribute(gemm_hmma<1>, cudaFuncAttributeMaxDynamicSharedMemorySize, GEMM_SMEM);
    cudaFuncSetAttribute(gemm_hmma<2>, cudaFuncAttributeMaxDynamicSharedMemorySize, GEMM_SMEM);
    cudaFuncSetAttribute(gemm_hmma<3>, cudaFuncAttributeMaxDynamicSharedMemorySize, GEMM_SMEM);
    cudaFuncSetAttribute(gemm_qkv, cudaFuncAttributeMaxDynamicSharedMemorySize, GEMM_SMEM);
    cudaFuncSetAttribute(attn_hmma, cudaFuncAttributeMaxDynamicSharedMemorySize, ATT_SMEM);

    static cudaStream_t s2 = nullptr;
    static cudaEvent_t evFork = nullptr, evPI = nullptr;
    if (!s2) {
        cudaStreamCreate(&s2);
        cudaEventCreateWithFlags(&evFork, cudaEventDisableTiming);
        cudaEventCreateWithFlags(&evPI, cudaEventDisableTiming);
    }

    WP wp;
    wp.p[0] = wq; wp.p[1] = wk; wp.p[2] = wv; wp.p[3] = wo;
    wp.p[4] = wg; wp.p[5] = wu; wp.p[6] = wd;

    // ---- fork: power iteration on s2 ----
    cudaEventRecord(evFork, 0);
    cudaStreamWaitEvent(s2, evFork, 0);
    pi_init<<<75, 256, 0, s2>>>();
    for (int t = 0; t < 5; t++) {
        pi_fwd<<<1110, 256, 0, s2>>>(wp, t);
        pi_zero_u<<<75, 256, 0, s2>>>();
        pi_bwd<<<BWD_BLOCKS, 256, 0, s2>>>(wp, t);
        pi_norm_u<<<7, 256, 0, s2>>>(t);
    }
    pi_fwd<<<1110, 256, 0, s2>>>(wp, 5);
    pi_sigma<<<1, 32, 0, s2>>>();
    cudaEventRecord(evPI, s2);

    // ---- main stream ----
    WCAll wc;
    wc.W[0] = wq; wc.Oh[0] = wqTh; wc.Ol[0] = wqTl;
    wc.W[1] = wk; wc.Oh[1] = wkTh; wc.Ol[1] = wkTl;
    wc.W[2] = wv; wc.Oh[2] = wvTh; wc.Ol[2] = wvTl;
    wc.W[3] = wo; wc.Oh[3] = woTh; wc.Ol[3] = woTl;
    wc.W[4] = wg; wc.Oh[4] = wgTh; wc.Ol[4] = wgTl;
    wc.W[5] = wu; wc.Oh[5] = wuTh; wc.Ol[5] = wuTl;
    wc.W[6] = wd; wc.Oh[6] = wdTh; wc.Ol[6] = wdTl;
    wconv_all<<<12352, dim3(32, 8)>>>(wc);

    rmsnorm_pair<<<NTOK, 256>>>(x, ln1, ai_h, ai_l);

    QKVArgs qa;
    qa.bh[0] = wqTh; qa.bl[0] = wqTl; qa.ch[0] = qhp; qa.cl[0] = qlp;
    qa.bh[1] = wkTh; qa.bl[1] = wkTl; qa.ch[1] = khp; qa.cl[1] = klp;
    qa.bh[2] = wvTh; qa.bl[2] = wvTl; qa.ch[2] = vhp; qa.cl[2] = vlp;
    gemm_qkv<<<dim3(8, 32, 3), 256, GEMM_SMEM>>>(ai_h, ai_l, qa);

    cudaStreamWaitEvent(0, evPI, 0);

    qknorm_pair<<<dim3(8192, 2), 256>>>(qhp, qlp, khp, klp, qn, kn, sq, sk, bq, bk);

    attn_hmma<<<dim3(8, 64), 256, ATT_SMEM>>>(qhp, qlp, khp, klp, vhp, vlp,
                                              aop_h, aop_l, sv, bv);

    dim3 g1(8, 32);
    gemm_hmma<1><<<g1, 256, GEMM_SMEM>>>(aop_h, aop_l, woTh, woTl, 1024, 1024,
                                         p_x1, nullptr, nullptr, 0, so, 3, bo, x);

    rmsnorm_pair<<<NTOK, 256>>>(p_x1, ln2, mi_h, mi_l);

    dim3 g2(22, 32);
    gemm_hmma<3><<<g2, 256, GEMM_SMEM>>>(mi_h, mi_l, wgTh, wgTl, 1024, 2736,
                                         p_gate, nullptr, nullptr, 0, sg, 4, bg, nullptr);
    gemm_hmma<2><<<g2, 256, GEMM_SMEM>>>(mi_h, mi_l, wuTh, wuTl, 1024, 2736,
                                         nullptr, hb_h, hb_l, KPADM, su, 5, bu, p_gate);
    gemm_hmma<1><<<g1, 256, GEMM_SMEM>>>(hb_h, hb_l, wdTh, wdTl, KPADM, 1024,
                                         out, nullptr, nullptr, 0, sd, 6, bd, p_x1);
}

// round 8
// speedup vs baseline: 2.4628x; 1.0130x over previous
#include <cuda_runtime.h>
#include <cuda_bf16.h>
#include <math.h>
#include <stdint.h>

#define EPSF 1e-6f
#define NTOK 4096
#define DDIM 1024
#define HDIM 64
#define MDIM 2736
#define SEQ  1024
#define KPADM 2752
#define NPADM 2816

typedef __nv_bfloat16 bf16;

// ---------------- scratch ----------------
__device__ float g_x1[NTOK * DDIM];
__device__ float g_gate[NTOK * MDIM];

__device__ bf16 g_ai_h[NTOK * DDIM], g_ai_l[NTOK * DDIM];
__device__ bf16 g_qh[NTOK * DDIM], g_ql[NTOK * DDIM];
__device__ bf16 g_kh[NTOK * DDIM], g_kl[NTOK * DDIM];
__device__ bf16 g_vh[NTOK * DDIM], g_vl[NTOK * DDIM];
__device__ bf16 g_aop_h[NTOK * DDIM], g_aop_l[NTOK * DDIM];
__device__ bf16 g_mi_h[NTOK * DDIM], g_mi_l[NTOK * DDIM];
__device__ bf16 g_hb_h[NTOK * KPADM], g_hb_l[NTOK * KPADM];

__device__ bf16 g_wqT_h[DDIM * DDIM], g_wqT_l[DDIM * DDIM];
__device__ bf16 g_wkT_h[DDIM * DDIM], g_wkT_l[DDIM * DDIM];
__device__ bf16 g_wvT_h[DDIM * DDIM], g_wvT_l[DDIM * DDIM];
__device__ bf16 g_woT_h[DDIM * DDIM], g_woT_l[DDIM * DDIM];
__device__ bf16 g_wgT_h[NPADM * DDIM], g_wgT_l[NPADM * DDIM];
__device__ bf16 g_wuT_h[NPADM * DDIM], g_wuT_l[NPADM * DDIM];
__device__ bf16 g_wdT_h[DDIM * KPADM], g_wdT_l[DDIM * KPADM];

__device__ float g_u[7][MDIM];
__device__ float g_w[7][MDIM];
__device__ float g_n2[7][16];
__device__ float g_sigma[7];

__constant__ int c_rows[7] = {1024, 1024, 1024, 1024, 1024, 1024, 2736};
__constant__ int c_cols[7] = {1024, 1024, 1024, 1024, 2736, 2736, 1024};
__constant__ int c_nct[7]  = {4, 4, 4, 4, 11, 11, 4};
__constant__ int c_nrc[7]  = {8, 8, 8, 8, 8, 8, 22};
#define BWD_CH 128

struct WP { const float* p[7]; };

// ---------------- PTX helpers ----------------
__device__ __forceinline__ uint32_t s2u(const void* p) {
    uint32_t a;
    asm("{ .reg .u64 t; cvta.to.shared.u64 t, %1; cvt.u32.u64 %0, t; }" : "=r"(a) : "l"(p));
    return a;
}
__device__ __forceinline__ void cpa16(uint32_t d, const void* g) {
    asm volatile("cp.async.cg.shared.global [%0], [%1], 16;" :: "r"(d), "l"(g) : "memory");
}
__device__ __forceinline__ void cpa_commit() { asm volatile("cp.async.commit_group;" ::: "memory"); }
template <int N> __device__ __forceinline__ void cpa_wait() {
    asm volatile("cp.async.wait_group %0;" :: "n"(N) : "memory");
}
__device__ __forceinline__ void ldmx4(uint32_t* r, uint32_t a) {
    asm volatile("ldmatrix.sync.aligned.m8n8.x4.shared.b16 {%0,%1,%2,%3}, [%4];"
                 : "=r"(r[0]), "=r"(r[1]), "=r"(r[2]), "=r"(r[3]) : "r"(a));
}
__device__ __forceinline__ void ldmx2(uint32_t* r, uint32_t a) {
    asm volatile("ldmatrix.sync.aligned.m8n8.x2.shared.b16 {%0,%1}, [%2];"
                 : "=r"(r[0]), "=r"(r[1]) : "r"(a));
}
__device__ __forceinline__ void ldmx2t(uint32_t* r, uint32_t a) {
    asm volatile("ldmatrix.sync.aligned.m8n8.x2.trans.shared.b16 {%0,%1}, [%2];"
                 : "=r"(r[0]), "=r"(r[1]) : "r"(a));
}
__device__ __forceinline__ void mma16816(float* c, const uint32_t* a, const uint32_t* b) {
    asm volatile(
        "mma.sync.aligned.m16n8k16.row.col.f32.bf16.bf16.f32 "
        "{%0,%1,%2,%3}, {%4,%5,%6,%7}, {%8,%9}, {%0,%1,%2,%3};"
        : "+f"(c[0]), "+f"(c[1]), "+f"(c[2]), "+f"(c[3])
        : "r"(a[0]), "r"(a[1]), "r"(a[2]), "r"(a[3]), "r"(b[0]), "r"(b[1]));
}
__device__ __forceinline__ void packsplit(float v0, float v1, uint32_t& hi, uint32_t& lo) {
    bf16 h0 = __float2bfloat16(v0), h1 = __float2bfloat16(v1);
    __nv_bfloat162 hh; hh.x = h0; hh.y = h1;
    hi = *(uint32_t*)&hh;
    __nv_bfloat162 ll;
    ll.x = __float2bfloat16(v0 - __bfloat162float(h0));
    ll.y = __float2bfloat16(v1 - __bfloat162float(h1));
    lo = *(uint32_t*)&ll;
}

// ---------------- HMMA split-bf16 GEMM (2-stage, 2 CTAs/SM) ----------------
#define TILEB 10240
#define STAGE_B 40960
#define GEMM_SMEM (2 * STAGE_B)

template <int EPI>
__device__ __forceinline__ void gemm_body(
    const bf16* __restrict__ Ah, const bf16* __restrict__ Al,
    const bf16* __restrict__ Bh, const bf16* __restrict__ Bl,
    int Kp, int N,
    float* __restrict__ Cf, bf16* __restrict__ Ch, bf16* __restrict__ Cl, int Cp,
    const float* __restrict__ sp, int sidx,
    const float* __restrict__ bias, const float* __restrict__ extra) {
    extern __shared__ char smem[];
    uint32_t sb = s2u(smem);
    int tid = threadIdx.x;
    int wid = tid >> 5, lane = tid & 31;
    int m0 = blockIdx.y * 128, n0 = blockIdx.x * 128;
    int wm = (wid & 1) * 64, wn = (wid >> 1) * 32;

    const bf16* bases[4] = {Ah, Al, Bh, Bl};
    int row0s[4] = {m0, m0, n0, n0};

    auto load_chunk = [&](int ck) {
        uint32_t st = sb + (uint32_t)(ck & 1) * STAGE_B;
        #pragma unroll
        for (int op = 0; op < 4; op++) {
            #pragma unroll
            for (int p = 0; p < 2; p++) {
                int idx = tid + p * 256;
                int r = idx >> 2, cg = idx & 3;
                const bf16* g = bases[op] + (size_t)(row0s[op] + r) * Kp + ck * 32 + cg * 8;
                cpa16(st + (uint32_t)op * TILEB + (uint32_t)(r * 80 + cg * 16), g);
            }
        }
        cpa_commit();
    };

    float acc[4][4][4];
    #pragma unroll
    for (int i = 0; i < 4; i++)
        #pragma unroll
        for (int j = 0; j < 4; j++)
            #pragma unroll
            for (int r = 0; r < 4; r++) acc[i][j][r] = 0.0f;

    const int T = Kp >> 5;
    load_chunk(0);
    load_chunk(1);

    uint32_t a_off = (uint32_t)((lane & 15) * 80 + (lane >> 4) * 16);
    uint32_t b_off = (uint32_t)((lane & 7) * 80 + ((lane >> 3) & 1) * 16);

    for (int ck = 0; ck < T; ck++) {
        if (ck + 1 < T) cpa_wait<1>(); else cpa_wait<0>();
        __syncthreads();
        uint32_t st = sb + (uint32_t)(ck & 1) * STAGE_B;
        #pragma unroll
        for (int ks = 0; ks < 2; ks++) {
            uint32_t kb = (uint32_t)(ks * 32);
            uint32_t ah[4][4], al[4][4], bh[4][2], bl[4][2];
            #pragma unroll
            for (int mp = 0; mp < 4; mp++) {
                uint32_t ra = st + (uint32_t)((wm + mp * 16) * 80) + a_off + kb;
                ldmx4(ah[mp], ra);
                ldmx4(al[mp], ra + TILEB);
            }
            #pragma unroll
            for (int np = 0; np < 4; np++) {
                uint32_t rb = st + 2 * TILEB + (uint32_t)((wn + np * 8) * 80) + b_off + kb;
                ldmx2(bh[np], rb);
                ldmx2(bl[np], rb + TILEB);
            }
            #pragma unroll
            for (int mp = 0; mp < 4; mp++)
                #pragma unroll
                for (int np = 0; np < 4; np++) {
                    mma16816(acc[mp][np], ah[mp], bh[np]);
                    mma16816(acc[mp][np], ah[mp], bl[np]);
                    mma16816(acc[mp][np], al[mp], bh[np]);
                }
        }
        __syncthreads();
        if (ck + 2 < T) load_chunk(ck + 2);
    }

    float alpha = 1.0f;
    if (EPI != 0) alpha = sp[0] / g_sigma[sidx];
    int rl = lane >> 2, cl2 = (lane & 3) * 2;

    #pragma unroll
    for (int mp = 0; mp < 4; mp++) {
        #pragma unroll
        for (int np = 0; np < 4; np++) {
            #pragma unroll
            for (int half = 0; half < 2; half++) {
                int gm = m0 + wm + mp * 16 + rl + half * 8;
                int gn = n0 + wn + np * 8 + cl2;
                #pragma unroll
                for (int e = 0; e < 2; e++) {
                    int n = gn + e;
                    if (n >= N) continue;
                    float v = acc[mp][np][half * 2 + e];
                    if (EPI != 0) v = fmaf(alpha, v, bias[n]);
                    if (EPI == 1) v += extra[(size_t)gm * N + n];
                    if (EPI == 2) {
                        float g = extra[(size_t)gm * N + n];
                        v = v * (g / (1.0f + __expf(-g)));
                    }
                    if (EPI == 0 || EPI == 2) {
                        bf16 h = __float2bfloat16(v);
                        Ch[(size_t)gm * Cp + n] = h;
                        Cl[(size_t)gm * Cp + n] = __float2bfloat16(v - __bfloat162float(h));
                    } else {
                        Cf[(size_t)gm * N + n] = v;
                    }
                }
            }
        }
    }
}

template <int EPI>
__global__ __launch_bounds__(256, 2)
void gemm_hmma(const bf16* Ah, const bf16* Al, const bf16* Bh, const bf16* Bl,
               int Kp, int N, float* Cf, bf16* Ch, bf16* Cl, int Cp,
               const float* sp, int sidx, const float* bias, const float* extra) {
    gemm_body<EPI>(Ah, Al, Bh, Bl, Kp, N, Cf, Ch, Cl, Cp, sp, sidx, bias, extra);
}

struct QKVArgs {
    const bf16 *bh[3], *bl[3];
    bf16 *ch[3], *cl[3];
};
__global__ __launch_bounds__(256, 2)
void gemm_qkv(const bf16* Ah, const bf16* Al, QKVArgs a) {
    int z = blockIdx.z;
    gemm_body<0>(Ah, Al, a.bh[z], a.bl[z], DDIM, DDIM,
                 nullptr, a.ch[z], a.cl[z], DDIM, nullptr, 0, nullptr, nullptr);
}

// ---------------- weight transpose + split (subset [w0, w0+cnt)) ----------------
struct WCAll {
    const float* W[7];
    bf16 *Oh[7], *Ol[7];
};
__constant__ int wc_K[7]  = {1024, 1024, 1024, 1024, 1024, 1024, 2736};
__constant__ int wc_N[7]  = {1024, 1024, 1024, 1024, 2736, 2736, 1024};
__constant__ int wc_Kp[7] = {1024, 1024, 1024, 1024, 1024, 1024, KPADM};
__constant__ int wc_nb[7] = {1024, 1024, 1024, 1024, 2752, 2752, 2752};

__global__ void wconv_sub(WCAll a, int w0) {
    __shared__ float t[32][33];
    int bid = blockIdx.x, wi = w0;
    while (bid >= wc_nb[wi]) { bid -= wc_nb[wi]; wi++; }
    int K = wc_K[wi], N = wc_N[wi], Kp = wc_Kp[wi];
    int tiles_x = (N + 31) >> 5;
    int bx = (bid % tiles_x) * 32, by = (bid / tiles_x) * 32;
    const float* W = a.W[wi];
    bf16* Oh = a.Oh[wi];
    bf16* Ol = a.Ol[wi];
    int x = threadIdx.x, y = threadIdx.y;
    for (int yy = y; yy < 32; yy += 8) {
        int k = by + yy, n = bx + x;
        t[yy][x] = (k < K && n < N) ? W[(size_t)k * N + n] : 0.0f;
    }
    __syncthreads();
    for (int yy = y; yy < 32; yy += 8) {
        int n = bx + yy, k = by + x;
        if (n < N && k < K) {
            float v = t[x][yy];
            bf16 h = __float2bfloat16(v);
            Oh[(size_t)n * Kp + k] = h;
            Ol[(size_t)n * Kp + k] = __float2bfloat16(v - __bfloat162float(h));
        }
    }
}

// ---------------- power iteration (subset-parameterized) ----------------
__global__ void pi_init(int w0, int wcnt) {
    int idx = blockIdx.x * 256 + threadIdx.x;
    if (idx < wcnt * MDIM) {
        int wi = w0 + idx / MDIM, j = idx % MDIM;
        int cols = c_cols[wi];
        float val = (j < cols) ? 1.0f / (sqrtf((float)cols) + EPSF) : 0.0f;
        g_u[wi][j] = val;
    }
    if (idx < wcnt * 16) g_n2[w0 + idx / 16][idx % 16] = 0.0f;
}
__global__ void pi_zero_u(int w0, int wcnt) {
    int idx = blockIdx.x * 256 + threadIdx.x;
    if (idx < wcnt * MDIM) g_u[w0 + idx / MDIM][idx % MDIM] = 0.0f;
}
__global__ void pi_fwd(WP wp, int t, int w0, int totrows) {
    int gw = (blockIdx.x * blockDim.x + threadIdx.x) >> 5;
    int lane = threadIdx.x & 31;
    if (gw >= totrows) return;
    int wi = w0, r = gw;
    while (r >= c_rows[wi]) { r -= c_rows[wi]; wi++; }
    int cols = c_cols[wi];
    float su = 1.0f;
    if (t > 0) su = 1.0f / (sqrtf(g_n2[wi][8 + t - 1]) + EPSF);
    const float* row = wp.p[wi] + (size_t)r * cols;
    const float* u = g_u[wi];
    float a0 = 0.0f, a1 = 0.0f, a2 = 0.0f, a3 = 0.0f;
    for (int c = lane * 4; c < cols; c += 512) {
        {
            float4 kv = *(const float4*)(row + c);
            float4 uv = *(const float4*)(u + c);
            a0 += kv.x * uv.x + kv.y * uv.y + kv.z * uv.z + kv.w * uv.w;
        }
        if (c + 128 < cols) {
            float4 kv = *(const float4*)(row + c + 128);
            float4 uv = *(const float4*)(u + c + 128);
            a1 += kv.x * uv.x + kv.y * uv.y + kv.z * uv.z + kv.w * uv.w;
        }
        if (c + 256 < cols) {
            float4 kv = *(const float4*)(row + c + 256);
            float4 uv = *(const float4*)(u + c + 256);
            a2 += kv.x * uv.x + kv.y * uv.y + kv.z * uv.z + kv.w * uv.w;
        }
        if (c + 384 < cols) {
            float4 kv = *(const float4*)(row + c + 384);
            float4 uv = *(const float4*)(u + c + 384);
            a3 += kv.x * uv.x + kv.y * uv.y + kv.z * uv.z + kv.w * uv.w;
        }
    }
    float acc = (a0 + a1) + (a2 + a3);
    #pragma unroll
    for (int o = 16; o; o >>= 1) acc += __shfl_xor_sync(0xffffffffu, acc, o);
    if (lane == 0) {
        float y = acc * su;
        g_w[wi][r] = y;
        atomicAdd(&g_n2[wi][t], y * y);
    }
}
__global__ void pi_bwd(WP wp, int t, int w0) {
    __shared__ float ws[BWD_CH];
    int bid = blockIdx.x, wi = w0;
    for (;;) { int nb = c_nct[wi] * c_nrc[wi]; if (bid < nb) break; bid -= nb; wi++; }
    int ct = bid % c_nct[wi], rc = bid / c_nct[wi];
    int rows = c_rows[wi], cols = c_cols[wi];
    float sv = 1.0f / (sqrtf(g_n2[wi][t]) + EPSF);
    int i0 = rc * BWD_CH;
    int ilen = min(BWD_CH, rows - i0);
    for (int i = threadIdx.x; i < ilen; i += 256) ws[i] = g_w[wi][i0 + i] * sv;
    __syncthreads();
    int j = ct * 256 + threadIdx.x;
    if (j < cols) {
        const float* base = wp.p[wi] + (size_t)i0 * cols + j;
        float a0 = 0.0f, a1 = 0.0f, a2 = 0.0f, a3 = 0.0f;
        int i = 0;
        for (; i + 8 <= ilen; i += 8) {
            a0 += base[(size_t)(i + 0) * cols] * ws[i + 0];
            a1 += base[(size_t)(i + 1) * cols] * ws[i + 1];
            a2 += base[(size_t)(i + 2) * cols] * ws[i + 2];
            a3 += base[(size_t)(i + 3) * cols] * ws[i + 3];
            a0 += base[(size_t)(i + 4) * cols] * ws[i + 4];
            a1 += base[(size_t)(i + 5) * cols] * ws[i + 5];
            a2 += base[(size_t)(i + 6) * cols] * ws[i + 6];
            a3 += base[(size_t)(i + 7) * cols] * ws[i + 7];
        }
        for (; i < ilen; i++) a0 += base[(size_t)i * cols] * ws[i];
        atomicAdd(&g_u[wi][j], (a0 + a1) + (a2 + a3));
    }
}
__global__ void pi_norm_u(int t, int w0) {
    int wi = w0 + blockIdx.x;
    int cols = c_cols[wi];
    float s = 0.0f;
    for (int j = threadIdx.x; j < cols; j += 256) { float v = g_u[wi][j]; s += v * v; }
    #pragma unroll
    for (int o = 16; o; o >>= 1) s += __shfl_xor_sync(0xffffffffu, s, o);
    __shared__ float red[8];
    if ((threadIdx.x & 31) == 0) red[threadIdx.x >> 5] = s;
    __syncthreads();
    if (threadIdx.x == 0) {
        float tot = 0.0f;
        #pragma unroll
        for (int i = 0; i < 8; i++) tot += red[i];
        g_n2[wi][8 + t] = tot;
    }
}
__global__ void pi_sigma(int w0, int wcnt) {
    int wi = w0 + threadIdx.x;
    if (threadIdx.x < wcnt) {
        float n2 = g_n2[wi][5];
        float s = sqrtf(n2);
        g_sigma[wi] = fmaxf(n2 / (s + EPSF), EPSF);
    }
}

// ---------------- elementwise ----------------
__global__ void rmsnorm_pair(const float* __restrict__ x, const float* __restrict__ sc,
                             bf16* __restrict__ oh, bf16* __restrict__ ol) {
    int row = blockIdx.x;
    const float* xr = x + (size_t)row * DDIM;
    float4 v = *(const float4*)(xr + threadIdx.x * 4);
    float s = v.x * v.x + v.y * v.y + v.z * v.z + v.w * v.w;
    #pragma unroll
    for (int o = 16; o; o >>= 1) s += __shfl_xor_sync(0xffffffffu, s, o);
    __shared__ float red[8];
    if ((threadIdx.x & 31) == 0) red[threadIdx.x >> 5] = s;
    __syncthreads();
    float tot = 0.0f;
    #pragma unroll
    for (int i = 0; i < 8; i++) tot += red[i];
    float r = rsqrtf(tot * (1.0f / (float)DDIM) + EPSF);
    float4 s4 = *(const float4*)(sc + threadIdx.x * 4);
    float y[4] = {v.x * r * s4.x, v.y * r * s4.y, v.z * r * s4.z, v.w * r * s4.w};
    size_t base = (size_t)row * DDIM + threadIdx.x * 4;
    #pragma unroll
    for (int c = 0; c < 4; c++) {
        bf16 h = __float2bfloat16(y[c]);
        oh[base + c] = h;
        ol[base + c] = __float2bfloat16(y[c] - __bfloat162float(h));
    }
}

__global__ void qknorm_pair(bf16* __restrict__ qh, bf16* __restrict__ ql,
                            bf16* __restrict__ kh, bf16* __restrict__ kl,
                            const float* __restrict__ qsc, const float* __restrict__ ksc,
                            const float* __restrict__ sq, const float* __restrict__ sk,
                            const float* __restrict__ bq, const float* __restrict__ bk) {
    int warp = threadIdx.x >> 5, lane = threadIdx.x & 31;
    int gw = blockIdx.x * 8 + warp;
    int n = gw >> 4, h = gw & 15;
    bf16* ph = blockIdx.y ? kh : qh;
    bf16* pl = blockIdx.y ? kl : ql;
    const float* sc = blockIdx.y ? ksc : qsc;
    const float* bb = blockIdx.y ? bk : bq;
    float alpha = (blockIdx.y ? sk[0] / g_sigma[1] : sq[0] / g_sigma[0]);
    size_t off = (size_t)n * DDIM + h * HDIM + lane * 2;
    __nv_bfloat162 hv = *(__nv_bfloat162*)(ph + off);
    __nv_bfloat162 lv = *(__nv_bfloat162*)(pl + off);
    float v0 = fmaf(alpha, __bfloat162float(hv.x) + __bfloat162float(lv.x), bb[h * HDIM + lane * 2]);
    float v1 = fmaf(alpha, __bfloat162float(hv.y) + __bfloat162float(lv.y), bb[h * HDIM + lane * 2 + 1]);
    float s = v0 * v0 + v1 * v1;
    #pragma unroll
    for (int o = 16; o; o >>= 1) s += __shfl_xor_sync(0xffffffffu, s, o);
    float r = rsqrtf(s * (1.0f / (float)HDIM) + EPSF);
    float y0 = v0 * r * sc[lane * 2];
    float y1 = v1 * r * sc[lane * 2 + 1];
    uint32_t hi, lo;
    packsplit(y0, y1, hi, lo);
    *(uint32_t*)(ph + off) = hi;
    *(uint32_t*)(pl + off) = lo;
}

// ---------------- HMMA flash attention (Q in regs, 2 CTAs/SM) ----------------
#define ATSB 144
#define KVT 9216
#define ATT_STAGE (4 * KVT)
#define ATT_SMEM (2 * ATT_STAGE)

__global__ __launch_bounds__(256, 2)
void attn_hmma(const bf16* __restrict__ qh, const bf16* __restrict__ ql,
               const bf16* __restrict__ kh, const bf16* __restrict__ kl,
               const bf16* __restrict__ vh, const bf16* __restrict__ vl,
               bf16* __restrict__ oh, bf16* __restrict__ ol,
               const float* __restrict__ svp, const float* __restrict__ bv) {
    extern __shared__ char smem[];
    uint32_t sb = s2u(smem);
    int tid = threadIdx.x, wid = tid >> 5, lane = tid & 31;
    int bh = blockIdx.y, b = bh >> 4, h = bh & 15;
    int q0 = blockIdx.x * 128;
    size_t base = ((size_t)b * SEQ) * DDIM + (size_t)h * HDIM;
    int wm = wid * 16;

    #pragma unroll
    for (int p = 0; p < 4; p++) {
        int idx = tid + p * 256;
        int r = idx >> 3, c = idx & 7;
        size_t g = base + (size_t)(q0 + r) * DDIM + c * 8;
        uint32_t o = (uint32_t)(r * ATSB + c * 16);
        cpa16(sb + o, qh + g);
        cpa16(sb + 2 * KVT + o, ql + g);
    }
    cpa_commit();
    cpa_wait<0>();
    __syncthreads();
    uint32_t qfh[4][4], qfl[4][4];
    #pragma unroll
    for (int ks = 0; ks < 4; ks++) {
        uint32_t qa = sb + (uint32_t)((wm + (lane & 15)) * ATSB + ks * 32 + (lane >> 4) * 16);
        ldmx4(qfh[ks], qa);
        ldmx4(qfl[ks], qa + 2 * KVT);
    }
    __syncthreads();

    auto load_kv = [&](int kt) {
        uint32_t st = sb + (uint32_t)(kt & 1) * ATT_STAGE;
        int t0 = kt * 64;
        #pragma unroll
        for (int p = 0; p < 2; p++) {
            int idx = tid + p * 256;
            int r = idx >> 3, c = idx & 7;
            size_t g = base + (size_t)(t0 + r) * DDIM + c * 8;
            uint32_t o = (uint32_t)(r * ATSB + c * 16);
            cpa16(st + o, kh + g);
            cpa16(st + KVT + o, kl + g);
            cpa16(st + 2 * KVT + o, vh + g);
            cpa16(st + 3 * KVT + o, vl + g);
        }
        cpa_commit();
    };
    load_kv(0);
    load_kv(1);

    float O[8][4];
    #pragma unroll
    for (int i = 0; i < 8; i++)
        #pragma unroll
        for (int j = 0; j < 4; j++) O[i][j] = 0.0f;
    float m0v = -1e30f, m1v = -1e30f, l0 = 0.0f, l1 = 0.0f;

    for (int kt = 0; kt < 16; kt++) {
        if (kt < 15) cpa_wait<1>(); else cpa_wait<0>();
        __syncthreads();
        uint32_t sK = sb + (uint32_t)(kt & 1) * ATT_STAGE;
        uint32_t sV = sK + 2 * KVT;

        float S[8][4];
        #pragma unroll
        for (int i = 0; i < 8; i++)
            #pragma unroll
            for (int j = 0; j < 4; j++) S[i][j] = 0.0f;

        #pragma unroll
        for (int ks = 0; ks < 4; ks++) {
            #pragma unroll
            for (int nt = 0; nt < 8; nt++) {
                uint32_t kfh[2], kfl[2];
                uint32_t ka = sK + (uint32_t)((nt * 8 + (lane & 7)) * ATSB + ks * 32 + ((lane >> 3) & 1) * 16);
                ldmx2(kfh, ka);
                ldmx2(kfl, ka + KVT);
                mma16816(S[nt], qfh[ks], kfh);
                mma16816(S[nt], qfh[ks], kfl);
                mma16816(S[nt], qfl[ks], kfh);
            }
        }

        #pragma unroll
        for (int nt = 0; nt < 8; nt++)
            #pragma unroll
            for (int j = 0; j < 4; j++) {
                float e = __expf(S[nt][j] * 0.005f);
                S[nt][j] = 50.0f * __fdividef(e - 1.0f, e + 1.0f);
            }

        float mx0 = -1e30f, mx1 = -1e30f;
        #pragma unroll
        for (int nt = 0; nt < 8; nt++) {
            mx0 = fmaxf(mx0, fmaxf(S[nt][0], S[nt][1]));
            mx1 = fmaxf(mx1, fmaxf(S[nt][2], S[nt][3]));
        }
        mx0 = fmaxf(mx0, __shfl_xor_sync(0xffffffffu, mx0, 1));
        mx0 = fmaxf(mx0, __shfl_xor_sync(0xffffffffu, mx0, 2));
        mx1 = fmaxf(mx1, __shfl_xor_sync(0xffffffffu, mx1, 1));
        mx1 = fmaxf(mx1, __shfl_xor_sync(0xffffffffu, mx1, 2));
        float mn0 = fmaxf(m0v, mx0), mn1 = fmaxf(m1v, mx1);
        float c0 = __expf(m0v - mn0), c1 = __expf(m1v - mn1);
        m0v = mn0; m1v = mn1;
        float s0 = 0.0f, s1 = 0.0f;
        #pragma unroll
        for (int nt = 0; nt < 8; nt++) {
            S[nt][0] = __expf(S[nt][0] - mn0);
            S[nt][1] = __expf(S[nt][1] - mn0);
            S[nt][2] = __expf(S[nt][2] - mn1);
            S[nt][3] = __expf(S[nt][3] - mn1);
            s0 += S[nt][0] + S[nt][1];
            s1 += S[nt][2] + S[nt][3];
        }
        s0 += __shfl_xor_sync(0xffffffffu, s0, 1);
        s0 += __shfl_xor_sync(0xffffffffu, s0, 2);
        s1 += __shfl_xor_sync(0xffffffffu, s1, 1);
        s1 += __shfl_xor_sync(0xffffffffu, s1, 2);
        l0 = l0 * c0 + s0;
        l1 = l1 * c1 + s1;
        #pragma unroll
        for (int dt = 0; dt < 8; dt++) {
            O[dt][0] *= c0; O[dt][1] *= c0;
            O[dt][2] *= c1; O[dt][3] *= c1;
        }

        #pragma unroll
        for (int ks2 = 0; ks2 < 4; ks2++) {
            uint32_t ph[4], pl[4];
            packsplit(S[2 * ks2][0], S[2 * ks2][1], ph[0], pl[0]);
            packsplit(S[2 * ks2][2], S[2 * ks2][3], ph[1], pl[1]);
            packsplit(S[2 * ks2 + 1][0], S[2 * ks2 + 1][1], ph[2], pl[2]);
            packsplit(S[2 * ks2 + 1][2], S[2 * ks2 + 1][3], ph[3], pl[3]);
            #pragma unroll
            for (int dt = 0; dt < 8; dt++) {
                uint32_t vfh[2], vfl[2];
                uint32_t va = sV + (uint32_t)((ks2 * 16 + (lane & 15)) * ATSB + dt * 16);
                ldmx2t(vfh, va);
                ldmx2t(vfl, va + KVT);
                mma16816(O[dt], ph, vfh);
                mma16816(O[dt], ph, vfl);
                mma16816(O[dt], pl, vfh);
            }
        }
        __syncthreads();
        if (kt + 2 < 16) load_kv(kt + 2);
    }

    float av = svp[0] / g_sigma[2];
    float i0 = av / l0, i1 = av / l1;
    int r = lane >> 2, c2 = (lane & 3) * 2;
    #pragma unroll
    for (int dt = 0; dt < 8; dt++) {
        #pragma unroll
        for (int half = 0; half < 2; half++) {
            int tok = q0 + wm + r + half * 8;
            float inv = half ? i1 : i0;
            int d = dt * 8 + c2;
            float v0 = fmaf(O[dt][half * 2 + 0], inv, bv[h * HDIM + d]);
            float v1 = fmaf(O[dt][half * 2 + 1], inv, bv[h * HDIM + d + 1]);
            uint32_t hi, lo;
            packsplit(v0, v1, hi, lo);
            size_t g = base + (size_t)tok * DDIM + d;
            *(uint32_t*)(oh + g) = hi;
            *(uint32_t*)(ol + g) = lo;
        }
    }
}

// ---------------- host ----------------
extern "C" void kernel_launch(void* const* d_in, const int* in_sizes, int n_in,
                              void* d_out, int out_size) {
    const float* x   = (const float*)d_in[0];
    const float* ln1 = (const float*)d_in[1];
    const float* wq  = (const float*)d_in[2];
    const float* sq  = (const float*)d_in[3];
    const float* bq  = (const float*)d_in[4];
    const float* wk  = (const float*)d_in[5];
    const float* sk  = (const float*)d_in[6];
    const float* bk  = (const float*)d_in[7];
    const float* wv  = (const float*)d_in[8];
    const float* sv  = (const float*)d_in[9];
    const float* bv  = (const float*)d_in[10];
    const float* qn  = (const float*)d_in[11];
    const float* kn  = (const float*)d_in[12];
    const float* wo  = (const float*)d_in[13];
    const float* so  = (const float*)d_in[14];
    const float* bo  = (const float*)d_in[15];
    const float* ln2 = (const float*)d_in[16];
    const float* wg  = (const float*)d_in[17];
    const float* sg  = (const float*)d_in[18];
    const float* bg  = (const float*)d_in[19];
    const float* wu  = (const float*)d_in[20];
    const float* su  = (const float*)d_in[21];
    const float* bu  = (const float*)d_in[22];
    const float* wd  = (const float*)d_in[23];
    const float* sd  = (const float*)d_in[24];
    const float* bd  = (const float*)d_in[25];
    float* out = (float*)d_out;

    float *p_x1, *p_gate;
    cudaGetSymbolAddress((void**)&p_x1, g_x1);
    cudaGetSymbolAddress((void**)&p_gate, g_gate);

    bf16 *ai_h, *ai_l, *aop_h, *aop_l, *mi_h, *mi_l, *hb_h, *hb_l;
    bf16 *qhp, *qlp, *khp, *klp, *vhp, *vlp;
    cudaGetSymbolAddress((void**)&ai_h, g_ai_h);   cudaGetSymbolAddress((void**)&ai_l, g_ai_l);
    cudaGetSymbolAddress((void**)&aop_h, g_aop_h); cudaGetSymbolAddress((void**)&aop_l, g_aop_l);
    cudaGetSymbolAddress((void**)&mi_h, g_mi_h);   cudaGetSymbolAddress((void**)&mi_l, g_mi_l);
    cudaGetSymbolAddress((void**)&hb_h, g_hb_h);   cudaGetSymbolAddress((void**)&hb_l, g_hb_l);
    cudaGetSymbolAddress((void**)&qhp, g_qh); cudaGetSymbolAddress((void**)&qlp, g_ql);
    cudaGetSymbolAddress((void**)&khp, g_kh); cudaGetSymbolAddress((void**)&klp, g_kl);
    cudaGetSymbolAddress((void**)&vhp, g_vh); cudaGetSymbolAddress((void**)&vlp, g_vl);

    bf16 *wqTh, *wqTl, *wkTh, *wkTl, *wvTh, *wvTl, *woTh, *woTl;
    bf16 *wgTh, *wgTl, *wuTh, *wuTl, *wdTh, *wdTl;
    cudaGetSymbolAddress((void**)&wqTh, g_wqT_h); cudaGetSymbolAddress((void**)&wqTl, g_wqT_l);
    cudaGetSymbolAddress((void**)&wkTh, g_wkT_h); cudaGetSymbolAddress((void**)&wkTl, g_wkT_l);
    cudaGetSymbolAddress((void**)&wvTh, g_wvT_h); cudaGetSymbolAddress((void**)&wvTl, g_wvT_l);
    cudaGetSymbolAddress((void**)&woTh, g_woT_h); cudaGetSymbolAddress((void**)&woTl, g_woT_l);
    cudaGetSymbolAddress((void**)&wgTh, g_wgT_h); cudaGetSymbolAddress((void**)&wgTl, g_wgT_l);
    cudaGetSymbolAddress((void**)&wuTh, g_wuT_h); cudaGetSymbolAddress((void**)&wuTl, g_wuT_l);
    cudaGetSymbolAddress((void**)&wdTh, g_wdT_h); cudaGetSymbolAddress((void**)&wdTl, g_wdT_l);

    cudaFuncSetAttribute(gemm_hmma<1>, cudaFuncAttributeMaxDynamicSharedMemorySize, GEMM_SMEM);
    cudaFuncSetAttribute(gemm_hmma<2>, cudaFuncAttributeMaxDynamicSharedMemorySize, GEMM_SMEM);
    cudaFuncSetAttribute(gemm_hmma<3>, cudaFuncAttributeMaxDynamicSharedMemorySize, GEMM_SMEM);
    cudaFuncSetAttribute(gemm_qkv, cudaFuncAttributeMaxDynamicSharedMemorySize, GEMM_SMEM);
    cudaFuncSetAttribute(attn_hmma, cudaFuncAttributeMaxDynamicSharedMemorySize, ATT_SMEM);

    static cudaStream_t s2 = nullptr, s3 = nullptr;
    static cudaEvent_t evFork = nullptr, evA = nullptr, evB = nullptr;
    if (!s2) {
        cudaStreamCreate(&s2);
        cudaStreamCreate(&s3);
        cudaEventCreateWithFlags(&evFork, cudaEventDisableTiming);
        cudaEventCreateWithFlags(&evA, cudaEventDisableTiming);
        cudaEventCreateWithFlags(&evB, cudaEventDisableTiming);
    }

    WP wp;
    wp.p[0] = wq; wp.p[1] = wk; wp.p[2] = wv; wp.p[3] = wo;
    wp.p[4] = wg; wp.p[5] = wu; wp.p[6] = wd;

    WCAll wc;
    wc.W[0] = wq; wc.Oh[0] = wqTh; wc.Ol[0] = wqTl;
    wc.W[1] = wk; wc.Oh[1] = wkTh; wc.Ol[1] = wkTl;
    wc.W[2] = wv; wc.Oh[2] = wvTh; wc.Ol[2] = wvTl;
    wc.W[3] = wo; wc.Oh[3] = woTh; wc.Ol[3] = woTl;
    wc.W[4] = wg; wc.Oh[4] = wgTh; wc.Ol[4] = wgTl;
    wc.W[5] = wu; wc.Oh[5] = wuTh; wc.Ol[5] = wuTl;
    wc.W[6] = wd; wc.Oh[6] = wdTh; wc.Ol[6] = wdTl;

    cudaEventRecord(evFork, 0);
    cudaStreamWaitEvent(s2, evFork, 0);
    cudaStreamWaitEvent(s3, evFork, 0);

    // ---- chain A on s2: PI over {wq,wk,wv} (rows 3072, bwd blocks 96) ----
    pi_init<<<33, 256, 0, s2>>>(0, 3);
    for (int t = 0; t < 5; t++) {
        pi_fwd<<<384, 256, 0, s2>>>(wp, t, 0, 3072);
        pi_zero_u<<<33, 256, 0, s2>>>(0, 3);
        pi_bwd<<<96, 256, 0, s2>>>(wp, t, 0);
        pi_norm_u<<<3, 256, 0, s2>>>(t, 0);
    }
    pi_fwd<<<384, 256, 0, s2>>>(wp, 5, 0, 3072);
    pi_sigma<<<1, 32, 0, s2>>>(0, 3);
    cudaEventRecord(evA, s2);

    // ---- chain B on s3: wconv rest + PI over {wo,wg,wu,wd} (rows 5808, bwd 296) ----
    wconv_sub<<<9280, dim3(32, 8), 0, s3>>>(wc, 3);
    pi_init<<<43, 256, 0, s3>>>(3, 4);
    for (int t = 0; t < 5; t++) {
        pi_fwd<<<726, 256, 0, s3>>>(wp, t, 3, 5808);
        pi_zero_u<<<43, 256, 0, s3>>>(3, 4);
        pi_bwd<<<296, 256, 0, s3>>>(wp, t, 3);
        pi_norm_u<<<4, 256, 0, s3>>>(t, 3);
    }
    pi_fwd<<<726, 256, 0, s3>>>(wp, 5, 3, 5808);
    pi_sigma<<<1, 32, 0, s3>>>(3, 4);
    cudaEventRecord(evB, s3);

    // ---- main stream: qkv wconv + rmsnorm + QKV ----
    wconv_sub<<<3072, dim3(32, 8)>>>(wc, 0);
    rmsnorm_pair<<<NTOK, 256>>>(x, ln1, ai_h, ai_l);

    QKVArgs qa;
    qa.bh[0] = wqTh; qa.bl[0] = wqTl; qa.ch[0] = qhp; qa.cl[0] = qlp;
    qa.bh[1] = wkTh; qa.bl[1] = wkTl; qa.ch[1] = khp; qa.cl[1] = klp;
    qa.bh[2] = wvTh; qa.bl[2] = wvTl; qa.ch[2] = vhp; qa.cl[2] = vlp;
    gemm_qkv<<<dim3(8, 32, 3), 256, GEMM_SMEM>>>(ai_h, ai_l, qa);

    cudaStreamWaitEvent(0, evA, 0);   // sigma 0..2

    qknorm_pair<<<dim3(8192, 2), 256>>>(qhp, qlp, khp, klp, qn, kn, sq, sk, bq, bk);

    attn_hmma<<<dim3(8, 64), 256, ATT_SMEM>>>(qhp, qlp, khp, klp, vhp, vlp,
                                              aop_h, aop_l, sv, bv);

    cudaStreamWaitEvent(0, evB, 0);   // sigma 3..6 + rest wconv

    dim3 g1(8, 32);
    gemm_hmma<1><<<g1, 256, GEMM_SMEM>>>(aop_h, aop_l, woTh, woTl, 1024, 1024,
                                         p_x1, nullptr, nullptr, 0, so, 3, bo, x);

    rmsnorm_pair<<<NTOK, 256>>>(p_x1, ln2, mi_h, mi_l);

    dim3 g2(22, 32);
    gemm_hmma<3><<<g2, 256, GEMM_SMEM>>>(mi_h, mi_l, wgTh, wgTl, 1024, 2736,
                                         p_gate, nullptr, nullptr, 0, sg, 4, bg, nullptr);
    gemm_hmma<2><<<g2, 256, GEMM_SMEM>>>(mi_h, mi_l, wuTh, wuTl, 1024, 2736,
                                         nullptr, hb_h, hb_l, KPADM, su, 5, bu, p_gate);
    gemm_hmma<1><<<g1, 256, GEMM_SMEM>>>(hb_h, hb_l, wdTh, wdTl, KPADM, 1024,
                                         out, nullptr, nullptr, 0, sd, 6, bd, p_x1);
}

// round 9
// speedup vs baseline: 3.2227x; 1.3085x over previous
#include <cuda_runtime.h>
#include <cuda_fp16.h>
#include <math.h>
#include <stdint.h>

#define EPSF 1e-6f
#define NTOK 4096
#define DDIM 1024
#define HDIM 64
#define MDIM 2736
#define SEQ  1024
#define KPADM 2752
#define NPADM 2816

typedef __half fp16;

// ---------------- scratch ----------------
__device__ float g_x1[NTOK * DDIM];
__device__ float g_gate[NTOK * MDIM];

__device__ fp16 g_ai[NTOK * DDIM];
__device__ fp16 g_q[NTOK * DDIM], g_ql[NTOK * DDIM];
__device__ fp16 g_kh[NTOK * DDIM], g_kl[NTOK * DDIM];
__device__ fp16 g_vh[NTOK * DDIM], g_vl[NTOK * DDIM];
__device__ fp16 g_aop[NTOK * DDIM];
__device__ fp16 g_mi[NTOK * DDIM];
__device__ fp16 g_hb[NTOK * KPADM];

__device__ fp16 g_wqT_h[DDIM * DDIM], g_wqT_l[DDIM * DDIM];
__device__ fp16 g_wkT_h[DDIM * DDIM], g_wkT_l[DDIM * DDIM];
__device__ fp16 g_wvT_h[DDIM * DDIM], g_wvT_l[DDIM * DDIM];
__device__ fp16 g_woT_h[DDIM * DDIM], g_woT_l[DDIM * DDIM];
__device__ fp16 g_wgT_h[NPADM * DDIM], g_wgT_l[NPADM * DDIM];
__device__ fp16 g_wuT_h[NPADM * DDIM], g_wuT_l[NPADM * DDIM];
__device__ fp16 g_wdT_h[DDIM * KPADM], g_wdT_l[DDIM * KPADM];

__device__ float g_u[7][MDIM];
__device__ float g_w[7][MDIM];
__device__ float g_n2[7][16];
__device__ float g_sigma[7];

__constant__ int c_rows[7] = {1024, 1024, 1024, 1024, 1024, 1024, 2736};
__constant__ int c_cols[7] = {1024, 1024, 1024, 1024, 2736, 2736, 1024};
__constant__ int c_nct[7]  = {4, 4, 4, 4, 11, 11, 4};
__constant__ int c_nrc[7]  = {8, 8, 8, 8, 8, 8, 22};
#define BWD_CH 128

struct WP { const float* p[7]; };

// ---------------- PTX helpers ----------------
__device__ __forceinline__ uint32_t s2u(const void* p) {
    uint32_t a;
    asm("{ .reg .u64 t; cvta.to.shared.u64 t, %1; cvt.u32.u64 %0, t; }" : "=r"(a) : "l"(p));
    return a;
}
__device__ __forceinline__ void cpa16(uint32_t d, const void* g) {
    asm volatile("cp.async.cg.shared.global [%0], [%1], 16;" :: "r"(d), "l"(g) : "memory");
}
__device__ __forceinline__ void cpa_commit() { asm volatile("cp.async.commit_group;" ::: "memory"); }
template <int N> __device__ __forceinline__ void cpa_wait() {
    asm volatile("cp.async.wait_group %0;" :: "n"(N) : "memory");
}
__device__ __forceinline__ void ldmx4(uint32_t* r, uint32_t a) {
    asm volatile("ldmatrix.sync.aligned.m8n8.x4.shared.b16 {%0,%1,%2,%3}, [%4];"
                 : "=r"(r[0]), "=r"(r[1]), "=r"(r[2]), "=r"(r[3]) : "r"(a));
}
__device__ __forceinline__ void ldmx2(uint32_t* r, uint32_t a) {
    asm volatile("ldmatrix.sync.aligned.m8n8.x2.shared.b16 {%0,%1}, [%2];"
                 : "=r"(r[0]), "=r"(r[1]) : "r"(a));
}
__device__ __forceinline__ void ldmx2t(uint32_t* r, uint32_t a) {
    asm volatile("ldmatrix.sync.aligned.m8n8.x2.trans.shared.b16 {%0,%1}, [%2];"
                 : "=r"(r[0]), "=r"(r[1]) : "r"(a));
}
__device__ __forceinline__ void mma16816(float* c, const uint32_t* a, const uint32_t* b) {
    asm volatile(
        "mma.sync.aligned.m16n8k16.row.col.f32.f16.f16.f32 "
        "{%0,%1,%2,%3}, {%4,%5,%6,%7}, {%8,%9}, {%0,%1,%2,%3};"
        : "+f"(c[0]), "+f"(c[1]), "+f"(c[2]), "+f"(c[3])
        : "r"(a[0]), "r"(a[1]), "r"(a[2]), "r"(a[3]), "r"(b[0]), "r"(b[1]));
}
__device__ __forceinline__ uint32_t pack2h(float v0, float v1) {
    __half2 h = __floats2half2_rn(v0, v1);
    return *(uint32_t*)&h;
}
__device__ __forceinline__ void packsplit(float v0, float v1, uint32_t& hi, uint32_t& lo) {
    fp16 h0 = __float2half_rn(v0), h1 = __float2half_rn(v1);
    __half2 hh; hh.x = h0; hh.y = h1;
    hi = *(uint32_t*)&hh;
    __half2 ll;
    ll.x = __float2half_rn(v0 - __half2float(h0));
    ll.y = __float2half_rn(v1 - __half2float(h1));
    lo = *(uint32_t*)&ll;
}

// ---------------- HMMA fp16 one-sided-split GEMM (2-stage, 2 CTAs/SM) ----------------
// C = A(fp16 single) @ (Bh+Bl)^T.  EPI 0: pair out raw (QKV)
// 1: fp32 alpha*acc+bias+extra   2: fp16 single (alpha*acc+bias)*silu(extra)   3: fp32 alpha+bias
#define TILEB 10240
#define STAGE_B 30720
#define GEMM_SMEM (2 * STAGE_B)

template <int EPI>
__device__ __forceinline__ void gemm_body(
    const fp16* __restrict__ A,
    const fp16* __restrict__ Bh, const fp16* __restrict__ Bl,
    int Kp, int N,
    float* __restrict__ Cf, fp16* __restrict__ Ch, fp16* __restrict__ Cl, int Cp,
    const float* __restrict__ sp, int sidx,
    const float* __restrict__ bias, const float* __restrict__ extra) {
    extern __shared__ char smem[];
    uint32_t sb = s2u(smem);
    int tid = threadIdx.x;
    int wid = tid >> 5, lane = tid & 31;
    int m0 = blockIdx.y * 128, n0 = blockIdx.x * 128;
    int wm = (wid & 1) * 64, wn = (wid >> 1) * 32;

    const fp16* bases[3] = {A, Bh, Bl};
    int row0s[3] = {m0, n0, n0};

    auto load_chunk = [&](int ck) {
        uint32_t st = sb + (uint32_t)(ck & 1) * STAGE_B;
        #pragma unroll
        for (int op = 0; op < 3; op++) {
            #pragma unroll
            for (int p = 0; p < 2; p++) {
                int idx = tid + p * 256;
                int r = idx >> 2, cg = idx & 3;
                const fp16* g = bases[op] + (size_t)(row0s[op] + r) * Kp + ck * 32 + cg * 8;
                cpa16(st + (uint32_t)op * TILEB + (uint32_t)(r * 80 + cg * 16), g);
            }
        }
        cpa_commit();
    };

    float acc[4][4][4];
    #pragma unroll
    for (int i = 0; i < 4; i++)
        #pragma unroll
        for (int j = 0; j < 4; j++)
            #pragma unroll
            for (int r = 0; r < 4; r++) acc[i][j][r] = 0.0f;

    const int T = Kp >> 5;
    load_chunk(0);
    load_chunk(1);

    uint32_t a_off = (uint32_t)((lane & 15) * 80 + (lane >> 4) * 16);
    uint32_t b_off = (uint32_t)((lane & 7) * 80 + ((lane >> 3) & 1) * 16);

    for (int ck = 0; ck < T; ck++) {
        if (ck + 1 < T) cpa_wait<1>(); else cpa_wait<0>();
        __syncthreads();
        uint32_t st = sb + (uint32_t)(ck & 1) * STAGE_B;
        #pragma unroll
        for (int ks = 0; ks < 2; ks++) {
            uint32_t kb = (uint32_t)(ks * 32);
            uint32_t af[4][4], bh[4][2], bl[4][2];
            #pragma unroll
            for (int mp = 0; mp < 4; mp++)
                ldmx4(af[mp], st + (uint32_t)((wm + mp * 16) * 80) + a_off + kb);
            #pragma unroll
            for (int np = 0; np < 4; np++) {
                uint32_t rb = st + TILEB + (uint32_t)((wn + np * 8) * 80) + b_off + kb;
                ldmx2(bh[np], rb);
                ldmx2(bl[np], rb + TILEB);
            }
            #pragma unroll
            for (int mp = 0; mp < 4; mp++)
                #pragma unroll
                for (int np = 0; np < 4; np++) {
                    mma16816(acc[mp][np], af[mp], bh[np]);
                    mma16816(acc[mp][np], af[mp], bl[np]);
                }
        }
        __syncthreads();
        if (ck + 2 < T) load_chunk(ck + 2);
    }

    float alpha = 1.0f;
    if (EPI != 0) alpha = sp[0] / g_sigma[sidx];
    int rl = lane >> 2, cl2 = (lane & 3) * 2;

    #pragma unroll
    for (int mp = 0; mp < 4; mp++) {
        #pragma unroll
        for (int np = 0; np < 4; np++) {
            #pragma unroll
            for (int half = 0; half < 2; half++) {
                int gm = m0 + wm + mp * 16 + rl + half * 8;
                int gn = n0 + wn + np * 8 + cl2;
                if (gn + 1 < N || gn < N) {
                    float v0 = acc[mp][np][half * 2 + 0];
                    float v1 = acc[mp][np][half * 2 + 1];
                    #pragma unroll
                    for (int e = 0; e < 2; e++) {
                        int n = gn + e;
                        if (n >= N) continue;
                        float v = (e ? v1 : v0);
                        if (EPI != 0) v = fmaf(alpha, v, bias[n]);
                        if (EPI == 1) v += extra[(size_t)gm * N + n];
                        if (EPI == 2) {
                            float g = extra[(size_t)gm * N + n];
                            v = v * (g / (1.0f + __expf(-g)));
                        }
                        if (EPI == 0) {
                            fp16 h = __float2half_rn(v);
                            Ch[(size_t)gm * Cp + n] = h;
                            Cl[(size_t)gm * Cp + n] = __float2half_rn(v - __half2float(h));
                        } else if (EPI == 2) {
                            Ch[(size_t)gm * Cp + n] = __float2half_rn(v);
                        } else {
                            Cf[(size_t)gm * N + n] = v;
                        }
                    }
                }
            }
        }
    }
}

template <int EPI>
__global__ __launch_bounds__(256, 2)
void gemm_hmma(const fp16* A, const fp16* Bh, const fp16* Bl,
               int Kp, int N, float* Cf, fp16* Ch, fp16* Cl, int Cp,
               const float* sp, int sidx, const float* bias, const float* extra) {
    gemm_body<EPI>(A, Bh, Bl, Kp, N, Cf, Ch, Cl, Cp, sp, sidx, bias, extra);
}

struct QKVArgs {
    const fp16 *bh[3], *bl[3];
    fp16 *ch[3], *cl[3];
};
__global__ __launch_bounds__(256, 2)
void gemm_qkv(const fp16* A, QKVArgs a) {
    int z = blockIdx.z;
    gemm_body<0>(A, a.bh[z], a.bl[z], DDIM, DDIM,
                 nullptr, a.ch[z], a.cl[z], DDIM, nullptr, 0, nullptr, nullptr);
}

// ---------------- weight transpose + fp16 split ----------------
struct WCAll {
    const float* W[7];
    fp16 *Oh[7], *Ol[7];
};
__constant__ int wc_K[7]  = {1024, 1024, 1024, 1024, 1024, 1024, 2736};
__constant__ int wc_N[7]  = {1024, 1024, 1024, 1024, 2736, 2736, 1024};
__constant__ int wc_Kp[7] = {1024, 1024, 1024, 1024, 1024, 1024, KPADM};
__constant__ int wc_nb[7] = {1024, 1024, 1024, 1024, 2752, 2752, 2752};

__global__ void wconv_sub(WCAll a, int w0) {
    __shared__ float t[32][33];
    int bid = blockIdx.x, wi = w0;
    while (bid >= wc_nb[wi]) { bid -= wc_nb[wi]; wi++; }
    int K = wc_K[wi], N = wc_N[wi], Kp = wc_Kp[wi];
    int tiles_x = (N + 31) >> 5;
    int bx = (bid % tiles_x) * 32, by = (bid / tiles_x) * 32;
    const float* W = a.W[wi];
    fp16* Oh = a.Oh[wi];
    fp16* Ol = a.Ol[wi];
    int x = threadIdx.x, y = threadIdx.y;
    for (int yy = y; yy < 32; yy += 8) {
        int k = by + yy, n = bx + x;
        t[yy][x] = (k < K && n < N) ? W[(size_t)k * N + n] : 0.0f;
    }
    __syncthreads();
    for (int yy = y; yy < 32; yy += 8) {
        int n = bx + yy, k = by + x;
        if (n < N && k < K) {
            float v = t[x][yy];
            fp16 h = __float2half_rn(v);
            Oh[(size_t)n * Kp + k] = h;
            Ol[(size_t)n * Kp + k] = __float2half_rn(v - __half2float(h));
        }
    }
}

// ---------------- power iteration (unchanged from R8) ----------------
__global__ void pi_init(int w0, int wcnt) {
    int idx = blockIdx.x * 256 + threadIdx.x;
    if (idx < wcnt * MDIM) {
        int wi = w0 + idx / MDIM, j = idx % MDIM;
        int cols = c_cols[wi];
        float val = (j < cols) ? 1.0f / (sqrtf((float)cols) + EPSF) : 0.0f;
        g_u[wi][j] = val;
    }
    if (idx < wcnt * 16) g_n2[w0 + idx / 16][idx % 16] = 0.0f;
}
__global__ void pi_zero_u(int w0, int wcnt) {
    int idx = blockIdx.x * 256 + threadIdx.x;
    if (idx < wcnt * MDIM) g_u[w0 + idx / MDIM][idx % MDIM] = 0.0f;
}
__global__ void pi_fwd(WP wp, int t, int w0, int totrows) {
    int gw = (blockIdx.x * blockDim.x + threadIdx.x) >> 5;
    int lane = threadIdx.x & 31;
    if (gw >= totrows) return;
    int wi = w0, r = gw;
    while (r >= c_rows[wi]) { r -= c_rows[wi]; wi++; }
    int cols = c_cols[wi];
    float su = 1.0f;
    if (t > 0) su = 1.0f / (sqrtf(g_n2[wi][8 + t - 1]) + EPSF);
    const float* row = wp.p[wi] + (size_t)r * cols;
    const float* u = g_u[wi];
    float a0 = 0.0f, a1 = 0.0f, a2 = 0.0f, a3 = 0.0f;
    for (int c = lane * 4; c < cols; c += 512) {
        {
            float4 kv = *(const float4*)(row + c);
            float4 uv = *(const float4*)(u + c);
            a0 += kv.x * uv.x + kv.y * uv.y + kv.z * uv.z + kv.w * uv.w;
        }
        if (c + 128 < cols) {
            float4 kv = *(const float4*)(row + c + 128);
            float4 uv = *(const float4*)(u + c + 128);
            a1 += kv.x * uv.x + kv.y * uv.y + kv.z * uv.z + kv.w * uv.w;
        }
        if (c + 256 < cols) {
            float4 kv = *(const float4*)(row + c + 256);
            float4 uv = *(const float4*)(u + c + 256);
            a2 += kv.x * uv.x + kv.y * uv.y + kv.z * uv.z + kv.w * uv.w;
        }
        if (c + 384 < cols) {
            float4 kv = *(const float4*)(row + c + 384);
            float4 uv = *(const float4*)(u + c + 384);
            a3 += kv.x * uv.x + kv.y * uv.y + kv.z * uv.z + kv.w * uv.w;
        }
    }
    float acc = (a0 + a1) + (a2 + a3);
    #pragma unroll
    for (int o = 16; o; o >>= 1) acc += __shfl_xor_sync(0xffffffffu, acc, o);
    if (lane == 0) {
        float y = acc * su;
        g_w[wi][r] = y;
        atomicAdd(&g_n2[wi][t], y * y);
    }
}
__global__ void pi_bwd(WP wp, int t, int w0) {
    __shared__ float ws[BWD_CH];
    int bid = blockIdx.x, wi = w0;
    for (;;) { int nb = c_nct[wi] * c_nrc[wi]; if (bid < nb) break; bid -= nb; wi++; }
    int ct = bid % c_nct[wi], rc = bid / c_nct[wi];
    int rows = c_rows[wi], cols = c_cols[wi];
    float sv = 1.0f / (sqrtf(g_n2[wi][t]) + EPSF);
    int i0 = rc * BWD_CH;
    int ilen = min(BWD_CH, rows - i0);
    for (int i = threadIdx.x; i < ilen; i += 256) ws[i] = g_w[wi][i0 + i] * sv;
    __syncthreads();
    int j = ct * 256 + threadIdx.x;
    if (j < cols) {
        const float* base = wp.p[wi] + (size_t)i0 * cols + j;
        float a0 = 0.0f, a1 = 0.0f, a2 = 0.0f, a3 = 0.0f;
        int i = 0;
        for (; i + 8 <= ilen; i += 8) {
            a0 += base[(size_t)(i + 0) * cols] * ws[i + 0];
            a1 += base[(size_t)(i + 1) * cols] * ws[i + 1];
            a2 += base[(size_t)(i + 2) * cols] * ws[i + 2];
            a3 += base[(size_t)(i + 3) * cols] * ws[i + 3];
            a0 += base[(size_t)(i + 4) * cols] * ws[i + 4];
            a1 += base[(size_t)(i + 5) * cols] * ws[i + 5];
            a2 += base[(size_t)(i + 6) * cols] * ws[i + 6];
            a3 += base[(size_t)(i + 7) * cols] * ws[i + 7];
        }
        for (; i < ilen; i++) a0 += base[(size_t)i * cols] * ws[i];
        atomicAdd(&g_u[wi][j], (a0 + a1) + (a2 + a3));
    }
}
__global__ void pi_norm_u(int t, int w0) {
    int wi = w0 + blockIdx.x;
    int cols = c_cols[wi];
    float s = 0.0f;
    for (int j = threadIdx.x; j < cols; j += 256) { float v = g_u[wi][j]; s += v * v; }
    #pragma unroll
    for (int o = 16; o; o >>= 1) s += __shfl_xor_sync(0xffffffffu, s, o);
    __shared__ float red[8];
    if ((threadIdx.x & 31) == 0) red[threadIdx.x >> 5] = s;
    __syncthreads();
    if (threadIdx.x == 0) {
        float tot = 0.0f;
        #pragma unroll
        for (int i = 0; i < 8; i++) tot += red[i];
        g_n2[wi][8 + t] = tot;
    }
}
__global__ void pi_sigma(int w0, int wcnt) {
    int wi = w0 + threadIdx.x;
    if (threadIdx.x < wcnt) {
        float n2 = g_n2[wi][5];
        float s = sqrtf(n2);
        g_sigma[wi] = fmaxf(n2 / (s + EPSF), EPSF);
    }
}

// ---------------- elementwise ----------------
__global__ void rmsnorm_h(const float* __restrict__ x, const float* __restrict__ sc,
                          fp16* __restrict__ o) {
    int row = blockIdx.x;
    const float* xr = x + (size_t)row * DDIM;
    float4 v = *(const float4*)(xr + threadIdx.x * 4);
    float s = v.x * v.x + v.y * v.y + v.z * v.z + v.w * v.w;
    #pragma unroll
    for (int off = 16; off; off >>= 1) s += __shfl_xor_sync(0xffffffffu, s, off);
    __shared__ float red[8];
    if ((threadIdx.x & 31) == 0) red[threadIdx.x >> 5] = s;
    __syncthreads();
    float tot = 0.0f;
    #pragma unroll
    for (int i = 0; i < 8; i++) tot += red[i];
    float r = rsqrtf(tot * (1.0f / (float)DDIM) + EPSF);
    float4 s4 = *(const float4*)(sc + threadIdx.x * 4);
    size_t base = (size_t)row * DDIM + threadIdx.x * 4;
    *(uint32_t*)(o + base) = pack2h(v.x * r * s4.x, v.y * r * s4.y);
    *(uint32_t*)(o + base + 2) = pack2h(v.z * r * s4.z, v.w * r * s4.w);
}

__global__ void qknorm_pair(fp16* __restrict__ qh, fp16* __restrict__ ql,
                            fp16* __restrict__ kh, fp16* __restrict__ kl,
                            const float* __restrict__ qsc, const float* __restrict__ ksc,
                            const float* __restrict__ sq, const float* __restrict__ sk,
                            const float* __restrict__ bq, const float* __restrict__ bk) {
    int warp = threadIdx.x >> 5, lane = threadIdx.x & 31;
    int gw = blockIdx.x * 8 + warp;
    int n = gw >> 4, h = gw & 15;
    fp16* ph = blockIdx.y ? kh : qh;
    fp16* pl = blockIdx.y ? kl : ql;
    const float* sc = blockIdx.y ? ksc : qsc;
    const float* bb = blockIdx.y ? bk : bq;
    float alpha = (blockIdx.y ? sk[0] / g_sigma[1] : sq[0] / g_sigma[0]);
    size_t off = (size_t)n * DDIM + h * HDIM + lane * 2;
    __half2 hv = *(__half2*)(ph + off);
    __half2 lv = *(__half2*)(pl + off);
    float v0 = fmaf(alpha, __half2float(hv.x) + __half2float(lv.x), bb[h * HDIM + lane * 2]);
    float v1 = fmaf(alpha, __half2float(hv.y) + __half2float(lv.y), bb[h * HDIM + lane * 2 + 1]);
    float s = v0 * v0 + v1 * v1;
    #pragma unroll
    for (int o = 16; o; o >>= 1) s += __shfl_xor_sync(0xffffffffu, s, o);
    float r = rsqrtf(s * (1.0f / (float)HDIM) + EPSF);
    float y0 = v0 * r * sc[lane * 2];
    float y1 = v1 * r * sc[lane * 2 + 1];
    uint32_t hi, lo;
    packsplit(y0, y1, hi, lo);
    *(uint32_t*)(ph + off) = hi;
    *(uint32_t*)(pl + off) = lo;
}

// ---------------- HMMA fp16 flash attention (Q in regs, 2 CTAs/SM) ----------------
#define ATSB 144
#define KVT 9216
#define ATT_STAGE (4 * KVT)
#define ATT_SMEM (2 * ATT_STAGE)

__global__ __launch_bounds__(256, 2)
void attn_hmma(const fp16* __restrict__ qh,
               const fp16* __restrict__ kh, const fp16* __restrict__ kl,
               const fp16* __restrict__ vh, const fp16* __restrict__ vl,
               fp16* __restrict__ o,
               const float* __restrict__ svp, const float* __restrict__ bv) {
    extern __shared__ char smem[];
    uint32_t sb = s2u(smem);
    int tid = threadIdx.x, wid = tid >> 5, lane = tid & 31;
    int bh = blockIdx.y, b = bh >> 4, h = bh & 15;
    int q0 = blockIdx.x * 128;
    size_t base = ((size_t)b * SEQ) * DDIM + (size_t)h * HDIM;
    int wm = wid * 16;

    // stage Q (single) into stage0, extract frags
    #pragma unroll
    for (int p = 0; p < 4; p++) {
        int idx = tid + p * 256;
        int r = idx >> 3, c = idx & 7;
        size_t g = base + (size_t)(q0 + r) * DDIM + c * 8;
        cpa16(sb + (uint32_t)(r * ATSB + c * 16), qh + g);
    }
    cpa_commit();
    cpa_wait<0>();
    __syncthreads();
    uint32_t qf[4][4];
    #pragma unroll
    for (int ks = 0; ks < 4; ks++) {
        uint32_t qa = sb + (uint32_t)((wm + (lane & 15)) * ATSB + ks * 32 + (lane >> 4) * 16);
        ldmx4(qf[ks], qa);
    }
    __syncthreads();

    auto load_kv = [&](int kt) {
        uint32_t st = sb + (uint32_t)(kt & 1) * ATT_STAGE;
        int t0 = kt * 64;
        #pragma unroll
        for (int p = 0; p < 2; p++) {
            int idx = tid + p * 256;
            int r = idx >> 3, c = idx & 7;
            size_t g = base + (size_t)(t0 + r) * DDIM + c * 8;
            uint32_t off = (uint32_t)(r * ATSB + c * 16);
            cpa16(st + off, kh + g);
            cpa16(st + KVT + off, kl + g);
            cpa16(st + 2 * KVT + off, vh + g);
            cpa16(st + 3 * KVT + off, vl + g);
        }
        cpa_commit();
    };
    load_kv(0);
    load_kv(1);

    float O[8][4];
    #pragma unroll
    for (int i = 0; i < 8; i++)
        #pragma unroll
        for (int j = 0; j < 4; j++) O[i][j] = 0.0f;
    float m0v = -1e30f, m1v = -1e30f, l0 = 0.0f, l1 = 0.0f;

    for (int kt = 0; kt < 16; kt++) {
        if (kt < 15) cpa_wait<1>(); else cpa_wait<0>();
        __syncthreads();
        uint32_t sK = sb + (uint32_t)(kt & 1) * ATT_STAGE;
        uint32_t sV = sK + 2 * KVT;

        float S[8][4];
        #pragma unroll
        for (int i = 0; i < 8; i++)
            #pragma unroll
            for (int j = 0; j < 4; j++) S[i][j] = 0.0f;

        #pragma unroll
        for (int ks = 0; ks < 4; ks++) {
            #pragma unroll
            for (int nt = 0; nt < 8; nt++) {
                uint32_t kfh[2], kfl[2];
                uint32_t ka = sK + (uint32_t)((nt * 8 + (lane & 7)) * ATSB + ks * 32 + ((lane >> 3) & 1) * 16);
                ldmx2(kfh, ka);
                ldmx2(kfl, ka + KVT);
                mma16816(S[nt], qf[ks], kfh);
                mma16816(S[nt], qf[ks], kfl);
            }
        }

        #pragma unroll
        for (int nt = 0; nt < 8; nt++)
            #pragma unroll
            for (int j = 0; j < 4; j++) {
                float e = __expf(S[nt][j] * 0.005f);
                S[nt][j] = 50.0f * __fdividef(e - 1.0f, e + 1.0f);
            }

        float mx0 = -1e30f, mx1 = -1e30f;
        #pragma unroll
        for (int nt = 0; nt < 8; nt++) {
            mx0 = fmaxf(mx0, fmaxf(S[nt][0], S[nt][1]));
            mx1 = fmaxf(mx1, fmaxf(S[nt][2], S[nt][3]));
        }
        mx0 = fmaxf(mx0, __shfl_xor_sync(0xffffffffu, mx0, 1));
        mx0 = fmaxf(mx0, __shfl_xor_sync(0xffffffffu, mx0, 2));
        mx1 = fmaxf(mx1, __shfl_xor_sync(0xffffffffu, mx1, 1));
        mx1 = fmaxf(mx1, __shfl_xor_sync(0xffffffffu, mx1, 2));
        float mn0 = fmaxf(m0v, mx0), mn1 = fmaxf(m1v, mx1);
        float c0 = __expf(m0v - mn0), c1 = __expf(m1v - mn1);
        m0v = mn0; m1v = mn1;
        float s0 = 0.0f, s1 = 0.0f;
        #pragma unroll
        for (int nt = 0; nt < 8; nt++) {
            S[nt][0] = __expf(S[nt][0] - mn0);
            S[nt][1] = __expf(S[nt][1] - mn0);
            S[nt][2] = __expf(S[nt][2] - mn1);
            S[nt][3] = __expf(S[nt][3] - mn1);
            s0 += S[nt][0] + S[nt][1];
            s1 += S[nt][2] + S[nt][3];
        }
        s0 += __shfl_xor_sync(0xffffffffu, s0, 1);
        s0 += __shfl_xor_sync(0xffffffffu, s0, 2);
        s1 += __shfl_xor_sync(0xffffffffu, s1, 1);
        s1 += __shfl_xor_sync(0xffffffffu, s1, 2);
        l0 = l0 * c0 + s0;
        l1 = l1 * c1 + s1;
        #pragma unroll
        for (int dt = 0; dt < 8; dt++) {
            O[dt][0] *= c0; O[dt][1] *= c0;
            O[dt][2] *= c1; O[dt][3] *= c1;
        }

        #pragma unroll
        for (int ks2 = 0; ks2 < 4; ks2++) {
            uint32_t pf[4];
            pf[0] = pack2h(S[2 * ks2][0], S[2 * ks2][1]);
            pf[1] = pack2h(S[2 * ks2][2], S[2 * ks2][3]);
            pf[2] = pack2h(S[2 * ks2 + 1][0], S[2 * ks2 + 1][1]);
            pf[3] = pack2h(S[2 * ks2 + 1][2], S[2 * ks2 + 1][3]);
            #pragma unroll
            for (int dt = 0; dt < 8; dt++) {
                uint32_t vfh[2], vfl[2];
                uint32_t va = sV + (uint32_t)((ks2 * 16 + (lane & 15)) * ATSB + dt * 16);
                ldmx2t(vfh, va);
                ldmx2t(vfl, va + KVT);
                mma16816(O[dt], pf, vfh);
                mma16816(O[dt], pf, vfl);
            }
        }
        __syncthreads();
        if (kt + 2 < 16) load_kv(kt + 2);
    }

    float av = svp[0] / g_sigma[2];
    float i0 = av / l0, i1 = av / l1;
    int r = lane >> 2, c2 = (lane & 3) * 2;
    #pragma unroll
    for (int dt = 0; dt < 8; dt++) {
        #pragma unroll
        for (int half = 0; half < 2; half++) {
            int tok = q0 + wm + r + half * 8;
            float inv = half ? i1 : i0;
            int d = dt * 8 + c2;
            float v0 = fmaf(O[dt][half * 2 + 0], inv, bv[h * HDIM + d]);
            float v1 = fmaf(O[dt][half * 2 + 1], inv, bv[h * HDIM + d + 1]);
            *(uint32_t*)(o + base + (size_t)tok * DDIM + d) = pack2h(v0, v1);
        }
    }
}

// ---------------- host ----------------
extern "C" void kernel_launch(void* const* d_in, const int* in_sizes, int n_in,
                              void* d_out, int out_size) {
    const float* x   = (const float*)d_in[0];
    const float* ln1 = (const float*)d_in[1];
    const float* wq  = (const float*)d_in[2];
    const float* sq  = (const float*)d_in[3];
    const float* bq  = (const float*)d_in[4];
    const float* wk  = (const float*)d_in[5];
    const float* sk  = (const float*)d_in[6];
    const float* bk  = (const float*)d_in[7];
    const float* wv  = (const float*)d_in[8];
    const float* sv  = (const float*)d_in[9];
    const float* bv  = (const float*)d_in[10];
    const float* qn  = (const float*)d_in[11];
    const float* kn  = (const float*)d_in[12];
    const float* wo  = (const float*)d_in[13];
    const float* so  = (const float*)d_in[14];
    const float* bo  = (const float*)d_in[15];
    const float* ln2 = (const float*)d_in[16];
    const float* wg  = (const float*)d_in[17];
    const float* sg  = (const float*)d_in[18];
    const float* bg  = (const float*)d_in[19];
    const float* wu  = (const float*)d_in[20];
    const float* su  = (const float*)d_in[21];
    const float* bu  = (const float*)d_in[22];
    const float* wd  = (const float*)d_in[23];
    const float* sd  = (const float*)d_in[24];
    const float* bd  = (const float*)d_in[25];
    float* out = (float*)d_out;

    float *p_x1, *p_gate;
    cudaGetSymbolAddress((void**)&p_x1, g_x1);
    cudaGetSymbolAddress((void**)&p_gate, g_gate);

    fp16 *ai, *aop, *mi, *hb;
    fp16 *qhp, *qlp, *khp, *klp, *vhp, *vlp;
    cudaGetSymbolAddress((void**)&ai, g_ai);
    cudaGetSymbolAddress((void**)&aop, g_aop);
    cudaGetSymbolAddress((void**)&mi, g_mi);
    cudaGetSymbolAddress((void**)&hb, g_hb);
    cudaGetSymbolAddress((void**)&qhp, g_q);  cudaGetSymbolAddress((void**)&qlp, g_ql);
    cudaGetSymbolAddress((void**)&khp, g_kh); cudaGetSymbolAddress((void**)&klp, g_kl);
    cudaGetSymbolAddress((void**)&vhp, g_vh); cudaGetSymbolAddress((void**)&vlp, g_vl);

    fp16 *wqTh, *wqTl, *wkTh, *wkTl, *wvTh, *wvTl, *woTh, *woTl;
    fp16 *wgTh, *wgTl, *wuTh, *wuTl, *wdTh, *wdTl;
    cudaGetSymbolAddress((void**)&wqTh, g_wqT_h); cudaGetSymbolAddress((void**)&wqTl, g_wqT_l);
    cudaGetSymbolAddress((void**)&wkTh, g_wkT_h); cudaGetSymbolAddress((void**)&wkTl, g_wkT_l);
    cudaGetSymbolAddress((void**)&wvTh, g_wvT_h); cudaGetSymbolAddress((void**)&wvTl, g_wvT_l);
    cudaGetSymbolAddress((void**)&woTh, g_woT_h); cudaGetSymbolAddress((void**)&woTl, g_woT_l);
    cudaGetSymbolAddress((void**)&wgTh, g_wgT_h); cudaGetSymbolAddress((void**)&wgTl, g_wgT_l);
    cudaGetSymbolAddress((void**)&wuTh, g_wuT_h); cudaGetSymbolAddress((void**)&wuTl, g_wuT_l);
    cudaGetSymbolAddress((void**)&wdTh, g_wdT_h); cudaGetSymbolAddress((void**)&wdTl, g_wdT_l);

    cudaFuncSetAttribute(gemm_hmma<1>, cudaFuncAttributeMaxDynamicSharedMemorySize, GEMM_SMEM);
    cudaFuncSetAttribute(gemm_hmma<2>, cudaFuncAttributeMaxDynamicSharedMemorySize, GEMM_SMEM);
    cudaFuncSetAttribute(gemm_hmma<3>, cudaFuncAttributeMaxDynamicSharedMemorySize, GEMM_SMEM);
    cudaFuncSetAttribute(gemm_qkv, cudaFuncAttributeMaxDynamicSharedMemorySize, GEMM_SMEM);
    cudaFuncSetAttribute(attn_hmma, cudaFuncAttributeMaxDynamicSharedMemorySize, ATT_SMEM);

    static cudaStream_t s2 = nullptr, s3 = nullptr;
    static cudaEvent_t evFork = nullptr, evA = nullptr, evB = nullptr;
    if (!s2) {
        cudaStreamCreate(&s2);
        cudaStreamCreate(&s3);
        cudaEventCreateWithFlags(&evFork, cudaEventDisableTiming);
        cudaEventCreateWithFlags(&evA, cudaEventDisableTiming);
        cudaEventCreateWithFlags(&evB, cudaEventDisableTiming);
    }

    WP wp;
    wp.p[0] = wq; wp.p[1] = wk; wp.p[2] = wv; wp.p[3] = wo;
    wp.p[4] = wg; wp.p[5] = wu; wp.p[6] = wd;

    WCAll wc;
    wc.W[0] = wq; wc.Oh[0] = wqTh; wc.Ol[0] = wqTl;
    wc.W[1] = wk; wc.Oh[1] = wkTh; wc.Ol[1] = wkTl;
    wc.W[2] = wv; wc.Oh[2] = wvTh; wc.Ol[2] = wvTl;
    wc.W[3] = wo; wc.Oh[3] = woTh; wc.Ol[3] = woTl;
    wc.W[4] = wg; wc.Oh[4] = wgTh; wc.Ol[4] = wgTl;
    wc.W[5] = wu; wc.Oh[5] = wuTh; wc.Ol[5] = wuTl;
    wc.W[6] = wd; wc.Oh[6] = wdTh; wc.Ol[6] = wdTl;

    cudaEventRecord(evFork, 0);
    cudaStreamWaitEvent(s2, evFork, 0);
    cudaStreamWaitEvent(s3, evFork, 0);

    // ---- chain A on s2: PI over {wq,wk,wv} ----
    pi_init<<<33, 256, 0, s2>>>(0, 3);
    for (int t = 0; t < 5; t++) {
        pi_fwd<<<384, 256, 0, s2>>>(wp, t, 0, 3072);
        pi_zero_u<<<33, 256, 0, s2>>>(0, 3);
        pi_bwd<<<96, 256, 0, s2>>>(wp, t, 0);
        pi_norm_u<<<3, 256, 0, s2>>>(t, 0);
    }
    pi_fwd<<<384, 256, 0, s2>>>(wp, 5, 0, 3072);
    pi_sigma<<<1, 32, 0, s2>>>(0, 3);
    cudaEventRecord(evA, s2);

    // ---- chain B on s3: wconv rest + PI over {wo,wg,wu,wd} ----
    wconv_sub<<<9280, dim3(32, 8), 0, s3>>>(wc, 3);
    pi_init<<<43, 256, 0, s3>>>(3, 4);
    for (int t = 0; t < 5; t++) {
        pi_fwd<<<726, 256, 0, s3>>>(wp, t, 3, 5808);
        pi_zero_u<<<43, 256, 0, s3>>>(3, 4);
        pi_bwd<<<296, 256, 0, s3>>>(wp, t, 3);
        pi_norm_u<<<4, 256, 0, s3>>>(t, 3);
    }
    pi_fwd<<<726, 256, 0, s3>>>(wp, 5, 3, 5808);
    pi_sigma<<<1, 32, 0, s3>>>(3, 4);
    cudaEventRecord(evB, s3);

    // ---- main stream ----
    wconv_sub<<<3072, dim3(32, 8)>>>(wc, 0);
    rmsnorm_h<<<NTOK, 256>>>(x, ln1, ai);

    QKVArgs qa;
    qa.bh[0] = wqTh; qa.bl[0] = wqTl; qa.ch[0] = qhp; qa.cl[0] = qlp;
    qa.bh[1] = wkTh; qa.bl[1] = wkTl; qa.ch[1] = khp; qa.cl[1] = klp;
    qa.bh[2] = wvTh; qa.bl[2] = wvTl; qa.ch[2] = vhp; qa.cl[2] = vlp;
    gemm_qkv<<<dim3(8, 32, 3), 256, GEMM_SMEM>>>(ai, qa);

    cudaStreamWaitEvent(0, evA, 0);

    qknorm_pair<<<dim3(8192, 2), 256>>>(qhp, qlp, khp, klp, qn, kn, sq, sk, bq, bk);

    attn_hmma<<<dim3(8, 64), 256, ATT_SMEM>>>(qhp, khp, klp, vhp, vlp, aop, sv, bv);

    cudaStreamWaitEvent(0, evB, 0);

    dim3 g1(8, 32);
    gemm_hmma<1><<<g1, 256, GEMM_SMEM>>>(aop, woTh, woTl, 1024, 1024,
                                         p_x1, nullptr, nullptr, 0, so, 3, bo, x);

    rmsnorm_h<<<NTOK, 256>>>(p_x1, ln2, mi);

    dim3 g2(22, 32);
    gemm_hmma<3><<<g2, 256, GEMM_SMEM>>>(mi, wgTh, wgTl, 1024, 2736,
                                         p_gate, nullptr, nullptr, 0, sg, 4, bg, nullptr);
    gemm_hmma<2><<<g2, 256, GEMM_SMEM>>>(mi, wuTh, wuTl, 1024, 2736,
                                         nullptr, hb, nullptr, KPADM, su, 5, bu, p_gate);
    gemm_hmma<1><<<g1, 256, GEMM_SMEM>>>(hb, wdTh, wdTl, KPADM, 1024,
                                         out, nullptr, nullptr, 0, sd, 6, bd, p_x1);
}

// round 10
// speedup vs baseline: 4.5471x; 1.4110x over previous
#include <cuda_runtime.h>
#include <cuda_fp16.h>
#include <math.h>
#include <stdint.h>

#define EPSF 1e-6f
#define NTOK 4096
#define DDIM 1024
#define HDIM 64
#define MDIM 2736
#define SEQ  1024
#define KPADM 2752
#define NPADM 2816

typedef __half fp16;

// ---------------- scratch ----------------
__device__ float g_x1[NTOK * DDIM];
__device__ float g_gate[NTOK * MDIM];

__device__ fp16 g_ai[NTOK * DDIM];
__device__ fp16 g_q[NTOK * DDIM];
__device__ fp16 g_k[NTOK * DDIM];
__device__ fp16 g_v[NTOK * DDIM];
__device__ fp16 g_aop[NTOK * DDIM];
__device__ fp16 g_mi[NTOK * DDIM];
__device__ fp16 g_hb[NTOK * KPADM];

__device__ fp16 g_wqT[DDIM * DDIM];
__device__ fp16 g_wkT[DDIM * DDIM];
__device__ fp16 g_wvT[DDIM * DDIM];
__device__ fp16 g_woT[DDIM * DDIM];
__device__ fp16 g_wgT[NPADM * DDIM];
__device__ fp16 g_wuT[NPADM * DDIM];
__device__ fp16 g_wdT[DDIM * KPADM];

__device__ float g_u[7][MDIM];
__device__ float g_w[7][MDIM];
__device__ float g_n2[7][16];
__device__ float g_sigma[7];

__constant__ int c_rows[7] = {1024, 1024, 1024, 1024, 1024, 1024, 2736};
__constant__ int c_cols[7] = {1024, 1024, 1024, 1024, 2736, 2736, 1024};
__constant__ int c_nct[7]  = {4, 4, 4, 4, 11, 11, 4};
__constant__ int c_nrc[7]  = {8, 8, 8, 8, 8, 8, 22};
#define BWD_CH 128

struct WP { const float* p[7]; };

// ---------------- PTX helpers ----------------
__device__ __forceinline__ uint32_t s2u(const void* p) {
    uint32_t a;
    asm("{ .reg .u64 t; cvta.to.shared.u64 t, %1; cvt.u32.u64 %0, t; }" : "=r"(a) : "l"(p));
    return a;
}
__device__ __forceinline__ void cpa16(uint32_t d, const void* g) {
    asm volatile("cp.async.cg.shared.global [%0], [%1], 16;" :: "r"(d), "l"(g) : "memory");
}
__device__ __forceinline__ void cpa_commit() { asm volatile("cp.async.commit_group;" ::: "memory"); }
template <int N> __device__ __forceinline__ void cpa_wait() {
    asm volatile("cp.async.wait_group %0;" :: "n"(N) : "memory");
}
__device__ __forceinline__ void ldmx4(uint32_t* r, uint32_t a) {
    asm volatile("ldmatrix.sync.aligned.m8n8.x4.shared.b16 {%0,%1,%2,%3}, [%4];"
                 : "=r"(r[0]), "=r"(r[1]), "=r"(r[2]), "=r"(r[3]) : "r"(a));
}
__device__ __forceinline__ void ldmx2(uint32_t* r, uint32_t a) {
    asm volatile("ldmatrix.sync.aligned.m8n8.x2.shared.b16 {%0,%1}, [%2];"
                 : "=r"(r[0]), "=r"(r[1]) : "r"(a));
}
__device__ __forceinline__ void ldmx2t(uint32_t* r, uint32_t a) {
    asm volatile("ldmatrix.sync.aligned.m8n8.x2.trans.shared.b16 {%0,%1}, [%2];"
                 : "=r"(r[0]), "=r"(r[1]) : "r"(a));
}
__device__ __forceinline__ void mma16816(float* c, const uint32_t* a, const uint32_t* b) {
    asm volatile(
        "mma.sync.aligned.m16n8k16.row.col.f32.f16.f16.f32 "
        "{%0,%1,%2,%3}, {%4,%5,%6,%7}, {%8,%9}, {%0,%1,%2,%3};"
        : "+f"(c[0]), "+f"(c[1]), "+f"(c[2]), "+f"(c[3])
        : "r"(a[0]), "r"(a[1]), "r"(a[2]), "r"(a[3]), "r"(b[0]), "r"(b[1]));
}
__device__ __forceinline__ uint32_t pack2h(float v0, float v1) {
    __half2 h = __floats2half2_rn(v0, v1);
    return *(uint32_t*)&h;
}

// ---------------- HMMA fp16 GEMM (3-stage, 2 CTAs/SM) ----------------
// EPI 0: fp16 raw out   1: fp32 alpha*acc+bias+extra   2: fp16 (alpha*acc+bias)*silu(extra)
// 3: fp32 alpha*acc+bias
#define TILEB 10240
#define STAGE_B 20480
#define GEMM_SMEM (3 * STAGE_B)

template <int EPI>
__device__ __forceinline__ void gemm_body(
    const fp16* __restrict__ A, const fp16* __restrict__ B,
    int Kp, int N,
    float* __restrict__ Cf, fp16* __restrict__ Ch, int Cp,
    const float* __restrict__ sp, int sidx,
    const float* __restrict__ bias, const float* __restrict__ extra) {
    extern __shared__ char smem[];
    uint32_t sb = s2u(smem);
    int tid = threadIdx.x;
    int wid = tid >> 5, lane = tid & 31;
    int m0 = blockIdx.y * 128, n0 = blockIdx.x * 128;
    int wm = (wid & 1) * 64, wn = (wid >> 1) * 32;

    const fp16* bases[2] = {A, B};
    int row0s[2] = {m0, n0};

    auto load_chunk = [&](int ck) {
        uint32_t st = sb + (uint32_t)(ck % 3) * STAGE_B;
        #pragma unroll
        for (int op = 0; op < 2; op++) {
            #pragma unroll
            for (int p = 0; p < 2; p++) {
                int idx = tid + p * 256;
                int r = idx >> 2, cg = idx & 3;
                const fp16* g = bases[op] + (size_t)(row0s[op] + r) * Kp + ck * 32 + cg * 8;
                cpa16(st + (uint32_t)op * TILEB + (uint32_t)(r * 80 + cg * 16), g);
            }
        }
        cpa_commit();
    };

    float acc[4][4][4];
    #pragma unroll
    for (int i = 0; i < 4; i++)
        #pragma unroll
        for (int j = 0; j < 4; j++)
            #pragma unroll
            for (int r = 0; r < 4; r++) acc[i][j][r] = 0.0f;

    const int T = Kp >> 5;
    load_chunk(0);
    load_chunk(1);
    load_chunk(2);

    uint32_t a_off = (uint32_t)((lane & 15) * 80 + (lane >> 4) * 16);
    uint32_t b_off = (uint32_t)((lane & 7) * 80 + ((lane >> 3) & 1) * 16);

    for (int ck = 0; ck < T; ck++) {
        if (ck + 2 < T) cpa_wait<2>();
        else if (ck + 1 < T) cpa_wait<1>();
        else cpa_wait<0>();
        __syncthreads();
        uint32_t st = sb + (uint32_t)(ck % 3) * STAGE_B;
        #pragma unroll
        for (int ks = 0; ks < 2; ks++) {
            uint32_t kb = (uint32_t)(ks * 32);
            uint32_t af[4][4], bf[4][2];
            #pragma unroll
            for (int mp = 0; mp < 4; mp++)
                ldmx4(af[mp], st + (uint32_t)((wm + mp * 16) * 80) + a_off + kb);
            #pragma unroll
            for (int np = 0; np < 4; np++)
                ldmx2(bf[np], st + TILEB + (uint32_t)((wn + np * 8) * 80) + b_off + kb);
            #pragma unroll
            for (int mp = 0; mp < 4; mp++)
                #pragma unroll
                for (int np = 0; np < 4; np++)
                    mma16816(acc[mp][np], af[mp], bf[np]);
        }
        __syncthreads();
        if (ck + 3 < T) load_chunk(ck + 3);
    }

    float alpha = 1.0f;
    if (EPI != 0) alpha = sp[0] / g_sigma[sidx];
    int rl = lane >> 2, cl2 = (lane & 3) * 2;

    #pragma unroll
    for (int mp = 0; mp < 4; mp++) {
        #pragma unroll
        for (int np = 0; np < 4; np++) {
            #pragma unroll
            for (int half = 0; half < 2; half++) {
                int gm = m0 + wm + mp * 16 + rl + half * 8;
                int gn = n0 + wn + np * 8 + cl2;
                #pragma unroll
                for (int e = 0; e < 2; e++) {
                    int n = gn + e;
                    if (n >= N) continue;
                    float v = acc[mp][np][half * 2 + e];
                    if (EPI != 0) v = fmaf(alpha, v, bias[n]);
                    if (EPI == 1) v += extra[(size_t)gm * N + n];
                    if (EPI == 2) {
                        float g = extra[(size_t)gm * N + n];
                        v = v * (g / (1.0f + __expf(-g)));
                    }
                    if (EPI == 0 || EPI == 2) {
                        Ch[(size_t)gm * Cp + n] = __float2half_rn(v);
                    } else {
                        Cf[(size_t)gm * N + n] = v;
                    }
                }
            }
        }
    }
}

template <int EPI>
__global__ __launch_bounds__(256, 2)
void gemm_hmma(const fp16* A, const fp16* B,
               int Kp, int N, float* Cf, fp16* Ch, int Cp,
               const float* sp, int sidx, const float* bias, const float* extra) {
    gemm_body<EPI>(A, B, Kp, N, Cf, Ch, Cp, sp, sidx, bias, extra);
}

struct QKVArgs {
    const fp16* b[3];
    fp16* c[3];
};
__global__ __launch_bounds__(256, 2)
void gemm_qkv(const fp16* A, QKVArgs a) {
    int z = blockIdx.z;
    gemm_body<0>(A, a.b[z], DDIM, DDIM, nullptr, a.c[z], DDIM, nullptr, 0, nullptr, nullptr);
}

// ---------------- weight transpose -> fp16 ----------------
struct WCAll {
    const float* W[7];
    fp16* O[7];
};
__constant__ int wc_K[7]  = {1024, 1024, 1024, 1024, 1024, 1024, 2736};
__constant__ int wc_N[7]  = {1024, 1024, 1024, 1024, 2736, 2736, 1024};
__constant__ int wc_Kp[7] = {1024, 1024, 1024, 1024, 1024, 1024, KPADM};
__constant__ int wc_nb[7] = {1024, 1024, 1024, 1024, 2752, 2752, 2752};

__global__ void wconv_sub(WCAll a, int w0) {
    __shared__ float t[32][33];
    int bid = blockIdx.x, wi = w0;
    while (bid >= wc_nb[wi]) { bid -= wc_nb[wi]; wi++; }
    int K = wc_K[wi], N = wc_N[wi], Kp = wc_Kp[wi];
    int tiles_x = (N + 31) >> 5;
    int bx = (bid % tiles_x) * 32, by = (bid / tiles_x) * 32;
    const float* W = a.W[wi];
    fp16* O = a.O[wi];
    int x = threadIdx.x, y = threadIdx.y;
    for (int yy = y; yy < 32; yy += 8) {
        int k = by + yy, n = bx + x;
        t[yy][x] = (k < K && n < N) ? W[(size_t)k * N + n] : 0.0f;
    }
    __syncthreads();
    for (int yy = y; yy < 32; yy += 8) {
        int n = bx + yy, k = by + x;
        if (n < N && k < K)
            O[(size_t)n * Kp + k] = __float2half_rn(t[x][yy]);
    }
}

// ---------------- power iteration ----------------
__global__ void pi_init(int w0, int wcnt) {
    int idx = blockIdx.x * 256 + threadIdx.x;
    if (idx < wcnt * MDIM) {
        int wi = w0 + idx / MDIM, j = idx % MDIM;
        int cols = c_cols[wi];
        float val = (j < cols) ? 1.0f / (sqrtf((float)cols) + EPSF) : 0.0f;
        g_u[wi][j] = val;
    }
    if (idx < wcnt * 16) g_n2[w0 + idx / 16][idx % 16] = 0.0f;
}
__global__ void pi_zero_u(int w0, int wcnt) {
    int idx = blockIdx.x * 256 + threadIdx.x;
    if (idx < wcnt * MDIM) g_u[w0 + idx / MDIM][idx % MDIM] = 0.0f;
}
__global__ void pi_fwd(WP wp, int t, int w0, int totrows) {
    int gw = (blockIdx.x * blockDim.x + threadIdx.x) >> 5;
    int lane = threadIdx.x & 31;
    if (gw >= totrows) return;
    int wi = w0, r = gw;
    while (r >= c_rows[wi]) { r -= c_rows[wi]; wi++; }
    int cols = c_cols[wi];
    float su = 1.0f;
    if (t > 0) su = 1.0f / (sqrtf(g_n2[wi][8 + t - 1]) + EPSF);
    const float* row = wp.p[wi] + (size_t)r * cols;
    const float* u = g_u[wi];
    float a0 = 0.0f, a1 = 0.0f, a2 = 0.0f, a3 = 0.0f;
    for (int c = lane * 4; c < cols; c += 512) {
        {
            float4 kv = *(const float4*)(row + c);
            float4 uv = *(const float4*)(u + c);
            a0 += kv.x * uv.x + kv.y * uv.y + kv.z * uv.z + kv.w * uv.w;
        }
        if (c + 128 < cols) {
            float4 kv = *(const float4*)(row + c + 128);
            float4 uv = *(const float4*)(u + c + 128);
            a1 += kv.x * uv.x + kv.y * uv.y + kv.z * uv.z + kv.w * uv.w;
        }
        if (c + 256 < cols) {
            float4 kv = *(const float4*)(row + c + 256);
            float4 uv = *(const float4*)(u + c + 256);
            a2 += kv.x * uv.x + kv.y * uv.y + kv.z * uv.z + kv.w * uv.w;
        }
        if (c + 384 < cols) {
            float4 kv = *(const float4*)(row + c + 384);
            float4 uv = *(const float4*)(u + c + 384);
            a3 += kv.x * uv.x + kv.y * uv.y + kv.z * uv.z + kv.w * uv.w;
        }
    }
    float acc = (a0 + a1) + (a2 + a3);
    #pragma unroll
    for (int o = 16; o; o >>= 1) acc += __shfl_xor_sync(0xffffffffu, acc, o);
    if (lane == 0) {
        float y = acc * su;
        g_w[wi][r] = y;
        atomicAdd(&g_n2[wi][t], y * y);
    }
}
__global__ void pi_bwd(WP wp, int t, int w0) {
    __shared__ float ws[BWD_CH];
    int bid = blockIdx.x, wi = w0;
    for (;;) { int nb = c_nct[wi] * c_nrc[wi]; if (bid < nb) break; bid -= nb; wi++; }
    int ct = bid % c_nct[wi], rc = bid / c_nct[wi];
    int rows = c_rows[wi], cols = c_cols[wi];
    float sv = 1.0f / (sqrtf(g_n2[wi][t]) + EPSF);
    int i0 = rc * BWD_CH;
    int ilen = min(BWD_CH, rows - i0);
    for (int i = threadIdx.x; i < ilen; i += 256) ws[i] = g_w[wi][i0 + i] * sv;
    __syncthreads();
    int j = ct * 256 + threadIdx.x;
    if (j < cols) {
        const float* base = wp.p[wi] + (size_t)i0 * cols + j;
        float a0 = 0.0f, a1 = 0.0f, a2 = 0.0f, a3 = 0.0f;
        int i = 0;
        for (; i + 8 <= ilen; i += 8) {
            a0 += base[(size_t)(i + 0) * cols] * ws[i + 0];
            a1 += base[(size_t)(i + 1) * cols] * ws[i + 1];
            a2 += base[(size_t)(i + 2) * cols] * ws[i + 2];
            a3 += base[(size_t)(i + 3) * cols] * ws[i + 3];
            a0 += base[(size_t)(i + 4) * cols] * ws[i + 4];
            a1 += base[(size_t)(i + 5) * cols] * ws[i + 5];
            a2 += base[(size_t)(i + 6) * cols] * ws[i + 6];
            a3 += base[(size_t)(i + 7) * cols] * ws[i + 7];
        }
        for (; i < ilen; i++) a0 += base[(size_t)i * cols] * ws[i];
        atomicAdd(&g_u[wi][j], (a0 + a1) + (a2 + a3));
    }
}
__global__ void pi_norm_u(int t, int w0) {
    int wi = w0 + blockIdx.x;
    int cols = c_cols[wi];
    float s = 0.0f;
    for (int j = threadIdx.x; j < cols; j += 256) { float v = g_u[wi][j]; s += v * v; }
    #pragma unroll
    for (int o = 16; o; o >>= 1) s += __shfl_xor_sync(0xffffffffu, s, o);
    __shared__ float red[8];
    if ((threadIdx.x & 31) == 0) red[threadIdx.x >> 5] = s;
    __syncthreads();
    if (threadIdx.x == 0) {
        float tot = 0.0f;
        #pragma unroll
        for (int i = 0; i < 8; i++) tot += red[i];
        g_n2[wi][8 + t] = tot;
    }
}
__global__ void pi_sigma(int w0, int wcnt) {
    int wi = w0 + threadIdx.x;
    if (threadIdx.x < wcnt) {
        float n2 = g_n2[wi][5];
        float s = sqrtf(n2);
        g_sigma[wi] = fmaxf(n2 / (s + EPSF), EPSF);
    }
}

// ---------------- elementwise ----------------
__global__ void rmsnorm_h(const float* __restrict__ x, const float* __restrict__ sc,
                          fp16* __restrict__ o) {
    int row = blockIdx.x;
    const float* xr = x + (size_t)row * DDIM;
    float4 v = *(const float4*)(xr + threadIdx.x * 4);
    float s = v.x * v.x + v.y * v.y + v.z * v.z + v.w * v.w;
    #pragma unroll
    for (int off = 16; off; off >>= 1) s += __shfl_xor_sync(0xffffffffu, s, off);
    __shared__ float red[8];
    if ((threadIdx.x & 31) == 0) red[threadIdx.x >> 5] = s;
    __syncthreads();
    float tot = 0.0f;
    #pragma unroll
    for (int i = 0; i < 8; i++) tot += red[i];
    float r = rsqrtf(tot * (1.0f / (float)DDIM) + EPSF);
    float4 s4 = *(const float4*)(sc + threadIdx.x * 4);
    size_t base = (size_t)row * DDIM + threadIdx.x * 4;
    *(uint32_t*)(o + base) = pack2h(v.x * r * s4.x, v.y * r * s4.y);
    *(uint32_t*)(o + base + 2) = pack2h(v.z * r * s4.z, v.w * r * s4.w);
}

__global__ void qknorm_h(fp16* __restrict__ q, fp16* __restrict__ k,
                         const float* __restrict__ qsc, const float* __restrict__ ksc,
                         const float* __restrict__ sq, const float* __restrict__ sk,
                         const float* __restrict__ bq, const float* __restrict__ bk) {
    int warp = threadIdx.x >> 5, lane = threadIdx.x & 31;
    int gw = blockIdx.x * 8 + warp;
    int n = gw >> 4, h = gw & 15;
    fp16* p = blockIdx.y ? k : q;
    const float* sc = blockIdx.y ? ksc : qsc;
    const float* bb = blockIdx.y ? bk : bq;
    float alpha = (blockIdx.y ? sk[0] / g_sigma[1] : sq[0] / g_sigma[0]);
    size_t off = (size_t)n * DDIM + h * HDIM + lane * 2;
    __half2 hv = *(__half2*)(p + off);
    float v0 = fmaf(alpha, __half2float(hv.x), bb[h * HDIM + lane * 2]);
    float v1 = fmaf(alpha, __half2float(hv.y), bb[h * HDIM + lane * 2 + 1]);
    float s = v0 * v0 + v1 * v1;
    #pragma unroll
    for (int o = 16; o; o >>= 1) s += __shfl_xor_sync(0xffffffffu, s, o);
    float r = rsqrtf(s * (1.0f / (float)HDIM) + EPSF);
    *(uint32_t*)(p + off) = pack2h(v0 * r * sc[lane * 2], v1 * r * sc[lane * 2 + 1]);
}

// ---------------- HMMA fp16 flash attention (Q in regs, 2 CTAs/SM) ----------------
#define ATSB 144
#define KVT 9216
#define ATT_STAGE (2 * KVT)
#define ATT_SMEM (2 * ATT_STAGE)

__global__ __launch_bounds__(256, 2)
void attn_hmma(const fp16* __restrict__ q,
               const fp16* __restrict__ k, const fp16* __restrict__ v,
               fp16* __restrict__ o,
               const float* __restrict__ svp, const float* __restrict__ bv) {
    extern __shared__ char smem[];
    uint32_t sb = s2u(smem);
    int tid = threadIdx.x, wid = tid >> 5, lane = tid & 31;
    int bh = blockIdx.y, b = bh >> 4, h = bh & 15;
    int q0 = blockIdx.x * 128;
    size_t base = ((size_t)b * SEQ) * DDIM + (size_t)h * HDIM;
    int wm = wid * 16;

    // stage Q into stage0 region, extract frags
    #pragma unroll
    for (int p = 0; p < 4; p++) {
        int idx = tid + p * 256;
        int r = idx >> 3, c = idx & 7;
        size_t g = base + (size_t)(q0 + r) * DDIM + c * 8;
        cpa16(sb + (uint32_t)(r * ATSB + c * 16), q + g);
    }
    cpa_commit();
    cpa_wait<0>();
    __syncthreads();
    uint32_t qf[4][4];
    #pragma unroll
    for (int ks = 0; ks < 4; ks++) {
        uint32_t qa = sb + (uint32_t)((wm + (lane & 15)) * ATSB + ks * 32 + (lane >> 4) * 16);
        ldmx4(qf[ks], qa);
    }
    __syncthreads();

    auto load_kv = [&](int kt) {
        uint32_t st = sb + (uint32_t)(kt & 1) * ATT_STAGE;
        int t0 = kt * 64;
        #pragma unroll
        for (int p = 0; p < 2; p++) {
            int idx = tid + p * 256;
            int r = idx >> 3, c = idx & 7;
            size_t g = base + (size_t)(t0 + r) * DDIM + c * 8;
            uint32_t off = (uint32_t)(r * ATSB + c * 16);
            cpa16(st + off, k + g);
            cpa16(st + KVT + off, v + g);
        }
        cpa_commit();
    };
    load_kv(0);
    load_kv(1);

    float O[8][4];
    #pragma unroll
    for (int i = 0; i < 8; i++)
        #pragma unroll
        for (int j = 0; j < 4; j++) O[i][j] = 0.0f;
    float m0v = -1e30f, m1v = -1e30f, l0 = 0.0f, l1 = 0.0f;

    for (int kt = 0; kt < 16; kt++) {
        if (kt < 15) cpa_wait<1>(); else cpa_wait<0>();
        __syncthreads();
        uint32_t sK = sb + (uint32_t)(kt & 1) * ATT_STAGE;
        uint32_t sV = sK + KVT;

        float S[8][4];
        #pragma unroll
        for (int i = 0; i < 8; i++)
            #pragma unroll
            for (int j = 0; j < 4; j++) S[i][j] = 0.0f;

        #pragma unroll
        for (int ks = 0; ks < 4; ks++) {
            #pragma unroll
            for (int nt = 0; nt < 8; nt++) {
                uint32_t kf[2];
                uint32_t ka = sK + (uint32_t)((nt * 8 + (lane & 7)) * ATSB + ks * 32 + ((lane >> 3) & 1) * 16);
                ldmx2(kf, ka);
                mma16816(S[nt], qf[ks], kf);
            }
        }

        #pragma unroll
        for (int nt = 0; nt < 8; nt++)
            #pragma unroll
            for (int j = 0; j < 4; j++) {
                float e = __expf(S[nt][j] * 0.005f);
                S[nt][j] = 50.0f * __fdividef(e - 1.0f, e + 1.0f);
            }

        float mx0 = -1e30f, mx1 = -1e30f;
        #pragma unroll
        for (int nt = 0; nt < 8; nt++) {
            mx0 = fmaxf(mx0, fmaxf(S[nt][0], S[nt][1]));
            mx1 = fmaxf(mx1, fmaxf(S[nt][2], S[nt][3]));
        }
        mx0 = fmaxf(mx0, __shfl_xor_sync(0xffffffffu, mx0, 1));
        mx0 = fmaxf(mx0, __shfl_xor_sync(0xffffffffu, mx0, 2));
        mx1 = fmaxf(mx1, __shfl_xor_sync(0xffffffffu, mx1, 1));
        mx1 = fmaxf(mx1, __shfl_xor_sync(0xffffffffu, mx1, 2));
        float mn0 = fmaxf(m0v, mx0), mn1 = fmaxf(m1v, mx1);
        float c0 = __expf(m0v - mn0), c1 = __expf(m1v - mn1);
        m0v = mn0; m1v = mn1;
        float s0 = 0.0f, s1 = 0.0f;
        #pragma unroll
        for (int nt = 0; nt < 8; nt++) {
            S[nt][0] = __expf(S[nt][0] - mn0);
            S[nt][1] = __expf(S[nt][1] - mn0);
            S[nt][2] = __expf(S[nt][2] - mn1);
            S[nt][3] = __expf(S[nt][3] - mn1);
            s0 += S[nt][0] + S[nt][1];
            s1 += S[nt][2] + S[nt][3];
        }
        s0 += __shfl_xor_sync(0xffffffffu, s0, 1);
        s0 += __shfl_xor_sync(0xffffffffu, s0, 2);
        s1 += __shfl_xor_sync(0xffffffffu, s1, 1);
        s1 += __shfl_xor_sync(0xffffffffu, s1, 2);
        l0 = l0 * c0 + s0;
        l1 = l1 * c1 + s1;
        #pragma unroll
        for (int dt = 0; dt < 8; dt++) {
            O[dt][0] *= c0; O[dt][1] *= c0;
            O[dt][2] *= c1; O[dt][3] *= c1;
        }

        #pragma unroll
        for (int ks2 = 0; ks2 < 4; ks2++) {
            uint32_t pf[4];
            pf[0] = pack2h(S[2 * ks2][0], S[2 * ks2][1]);
            pf[1] = pack2h(S[2 * ks2][2], S[2 * ks2][3]);
            pf[2] = pack2h(S[2 * ks2 + 1][0], S[2 * ks2 + 1][1]);
            pf[3] = pack2h(S[2 * ks2 + 1][2], S[2 * ks2 + 1][3]);
            #pragma unroll
            for (int dt = 0; dt < 8; dt++) {
                uint32_t vf[2];
                uint32_t va = sV + (uint32_t)((ks2 * 16 + (lane & 15)) * ATSB + dt * 16);
                ldmx2t(vf, va);
                mma16816(O[dt], pf, vf);
            }
        }
        __syncthreads();
        if (kt + 2 < 16) load_kv(kt + 2);
    }

    float av = svp[0] / g_sigma[2];
    float i0 = av / l0, i1 = av / l1;
    int r = lane >> 2, c2 = (lane & 3) * 2;
    #pragma unroll
    for (int dt = 0; dt < 8; dt++) {
        #pragma unroll
        for (int half = 0; half < 2; half++) {
            int tok = q0 + wm + r + half * 8;
            float inv = half ? i1 : i0;
            int d = dt * 8 + c2;
            float v0 = fmaf(O[dt][half * 2 + 0], inv, bv[h * HDIM + d]);
            float v1 = fmaf(O[dt][half * 2 + 1], inv, bv[h * HDIM + d + 1]);
            *(uint32_t*)(o + base + (size_t)tok * DDIM + d) = pack2h(v0, v1);
        }
    }
}

// ---------------- host ----------------
extern "C" void kernel_launch(void* const* d_in, const int* in_sizes, int n_in,
                              void* d_out, int out_size) {
    const float* x   = (const float*)d_in[0];
    const float* ln1 = (const float*)d_in[1];
    const float* wq  = (const float*)d_in[2];
    const float* sq  = (const float*)d_in[3];
    const float* bq  = (const float*)d_in[4];
    const float* wk  = (const float*)d_in[5];
    const float* sk  = (const float*)d_in[6];
    const float* bk  = (const float*)d_in[7];
    const float* wv  = (const float*)d_in[8];
    const float* sv  = (const float*)d_in[9];
    const float* bv  = (const float*)d_in[10];
    const float* qn  = (const float*)d_in[11];
    const float* kn  = (const float*)d_in[12];
    const float* wo  = (const float*)d_in[13];
    const float* so  = (const float*)d_in[14];
    const float* bo  = (const float*)d_in[15];
    const float* ln2 = (const float*)d_in[16];
    const float* wg  = (const float*)d_in[17];
    const float* sg  = (const float*)d_in[18];
    const float* bg  = (const float*)d_in[19];
    const float* wu  = (const float*)d_in[20];
    const float* su  = (const float*)d_in[21];
    const float* bu  = (const float*)d_in[22];
    const float* wd  = (const float*)d_in[23];
    const float* sd  = (const float*)d_in[24];
    const float* bd  = (const float*)d_in[25];
    float* out = (float*)d_out;

    float *p_x1, *p_gate;
    cudaGetSymbolAddress((void**)&p_x1, g_x1);
    cudaGetSymbolAddress((void**)&p_gate, g_gate);

    fp16 *ai, *aop, *mi, *hb, *qp, *kp, *vp;
    cudaGetSymbolAddress((void**)&ai, g_ai);
    cudaGetSymbolAddress((void**)&aop, g_aop);
    cudaGetSymbolAddress((void**)&mi, g_mi);
    cudaGetSymbolAddress((void**)&hb, g_hb);
    cudaGetSymbolAddress((void**)&qp, g_q);
    cudaGetSymbolAddress((void**)&kp, g_k);
    cudaGetSymbolAddress((void**)&vp, g_v);

    fp16 *wqT, *wkT, *wvT, *woT, *wgT, *wuT, *wdT;
    cudaGetSymbolAddress((void**)&wqT, g_wqT);
    cudaGetSymbolAddress((void**)&wkT, g_wkT);
    cudaGetSymbolAddress((void**)&wvT, g_wvT);
    cudaGetSymbolAddress((void**)&woT, g_woT);
    cudaGetSymbolAddress((void**)&wgT, g_wgT);
    cudaGetSymbolAddress((void**)&wuT, g_wuT);
    cudaGetSymbolAddress((void**)&wdT, g_wdT);

    cudaFuncSetAttribute(gemm_hmma<1>, cudaFuncAttributeMaxDynamicSharedMemorySize, GEMM_SMEM);
    cudaFuncSetAttribute(gemm_hmma<2>, cudaFuncAttributeMaxDynamicSharedMemorySize, GEMM_SMEM);
    cudaFuncSetAttribute(gemm_hmma<3>, cudaFuncAttributeMaxDynamicSharedMemorySize, GEMM_SMEM);
    cudaFuncSetAttribute(gemm_qkv, cudaFuncAttributeMaxDynamicSharedMemorySize, GEMM_SMEM);
    cudaFuncSetAttribute(attn_hmma, cudaFuncAttributeMaxDynamicSharedMemorySize, ATT_SMEM);

    static cudaStream_t s2 = nullptr, s3 = nullptr;
    static cudaEvent_t evFork = nullptr, evA = nullptr, evB = nullptr;
    if (!s2) {
        cudaStreamCreate(&s2);
        cudaStreamCreate(&s3);
        cudaEventCreateWithFlags(&evFork, cudaEventDisableTiming);
        cudaEventCreateWithFlags(&evA, cudaEventDisableTiming);
        cudaEventCreateWithFlags(&evB, cudaEventDisableTiming);
    }

    WP wp;
    wp.p[0] = wq; wp.p[1] = wk; wp.p[2] = wv; wp.p[3] = wo;
    wp.p[4] = wg; wp.p[5] = wu; wp.p[6] = wd;

    WCAll wc;
    wc.W[0] = wq; wc.O[0] = wqT;
    wc.W[1] = wk; wc.O[1] = wkT;
    wc.W[2] = wv; wc.O[2] = wvT;
    wc.W[3] = wo; wc.O[3] = woT;
    wc.W[4] = wg; wc.O[4] = wgT;
    wc.W[5] = wu; wc.O[5] = wuT;
    wc.W[6] = wd; wc.O[6] = wdT;

    cudaEventRecord(evFork, 0);
    cudaStreamWaitEvent(s2, evFork, 0);
    cudaStreamWaitEvent(s3, evFork, 0);

    // ---- chain A on s2: PI over {wq,wk,wv} ----
    pi_init<<<33, 256, 0, s2>>>(0, 3);
    for (int t = 0; t < 5; t++) {
        pi_fwd<<<384, 256, 0, s2>>>(wp, t, 0, 3072);
        pi_zero_u<<<33, 256, 0, s2>>>(0, 3);
        pi_bwd<<<96, 256, 0, s2>>>(wp, t, 0);
        pi_norm_u<<<3, 256, 0, s2>>>(t, 0);
    }
    pi_fwd<<<384, 256, 0, s2>>>(wp, 5, 0, 3072);
    pi_sigma<<<1, 32, 0, s2>>>(0, 3);
    cudaEventRecord(evA, s2);

    // ---- chain B on s3: wconv rest + PI over {wo,wg,wu,wd} ----
    wconv_sub<<<9280, dim3(32, 8), 0, s3>>>(wc, 3);
    pi_init<<<43, 256, 0, s3>>>(3, 4);
    for (int t = 0; t < 5; t++) {
        pi_fwd<<<726, 256, 0, s3>>>(wp, t, 3, 5808);
        pi_zero_u<<<43, 256, 0, s3>>>(3, 4);
        pi_bwd<<<296, 256, 0, s3>>>(wp, t, 3);
        pi_norm_u<<<4, 256, 0, s3>>>(t, 3);
    }
    pi_fwd<<<726, 256, 0, s3>>>(wp, 5, 3, 5808);
    pi_sigma<<<1, 32, 0, s3>>>(3, 4);
    cudaEventRecord(evB, s3);

    // ---- main stream ----
    wconv_sub<<<3072, dim3(32, 8)>>>(wc, 0);
    rmsnorm_h<<<NTOK, 256>>>(x, ln1, ai);

    QKVArgs qa;
    qa.b[0] = wqT; qa.c[0] = qp;
    qa.b[1] = wkT; qa.c[1] = kp;
    qa.b[2] = wvT; qa.c[2] = vp;
    gemm_qkv<<<dim3(8, 32, 3), 256, GEMM_SMEM>>>(ai, qa);

    cudaStreamWaitEvent(0, evA, 0);

    qknorm_h<<<dim3(8192, 2), 256>>>(qp, kp, qn, kn, sq, sk, bq, bk);

    attn_hmma<<<dim3(8, 64), 256, ATT_SMEM>>>(qp, kp, vp, aop, sv, bv);

    cudaStreamWaitEvent(0, evB, 0);

    dim3 g1(8, 32);
    gemm_hmma<1><<<g1, 256, GEMM_SMEM>>>(aop, woT, 1024, 1024,
                                         p_x1, nullptr, 0, so, 3, bo, x);

    rmsnorm_h<<<NTOK, 256>>>(p_x1, ln2, mi);

    dim3 g2(22, 32);
    gemm_hmma<3><<<g2, 256, GEMM_SMEM>>>(mi, wgT, 1024, 2736,
                                         p_gate, nullptr, 0, sg, 4, bg, nullptr);
    gemm_hmma<2><<<g2, 256, GEMM_SMEM>>>(mi, wuT, 1024, 2736,
                                         nullptr, hb, KPADM, su, 5, bu, p_gate);
    gemm_hmma<1><<<g1, 256, GEMM_SMEM>>>(hb, wdT, KPADM, 1024,
                                         out, nullptr, 0, sd, 6, bd, p_x1);
}